// round 6
// baseline (speedup 1.0000x reference)
#include <cuda_runtime.h>
#include <cuda_fp16.h>
#include <cstdint>

// ============================================================================
// SelfAttention: out = softmax( (xWq^T+bq)(xWk^T+bk)^T ) (xWv^T+bv)
// B=4, S=2048, H=1024 (fp32 in/out)
// All GEMMs: legacy mma.sync m16n8k16 fp16 (tcgen05 unavailable on sm_100).
// Precision: 3x-FP16 hi/lo split for q/k projections + scores; 1x for V & PV.
// Split GEMMs use PAIRED tiles (hi chunks 0-3, lo chunks 4-7 per 128B row) so
// one pipeline chunk feeds all 3 products of a K=32 slice.
// ============================================================================

#define BATCH 4
#define SEQ   2048
#define HID   1024
#define MTOT  (BATCH*SEQ)          // 8192

// ---- scratch (device globals; allocation-free per harness rules) ----
__device__ __half g_xh[(size_t)MTOT * HID];
__device__ __half g_xl[(size_t)MTOT * HID];
__device__ __half g_wh[(size_t)3 * HID * HID];
__device__ __half g_wl[(size_t)3 * HID * HID];
__device__ __half g_qh[(size_t)MTOT * HID];
__device__ __half g_ql[(size_t)MTOT * HID];
__device__ __half g_kh[(size_t)MTOT * HID];
__device__ __half g_kl[(size_t)MTOT * HID];
__device__ __half g_vh[(size_t)MTOT * HID];
__device__ float  g_s [(size_t)BATCH * SEQ * SEQ];
__device__ __half g_p [(size_t)BATCH * SEQ * SEQ];

// ----------------------------------------------------------------------------
// helpers
// ----------------------------------------------------------------------------
__device__ __forceinline__ uint32_t smem_u32(const void* p) {
    uint32_t a;
    asm("{ .reg .u64 t; cvta.to.shared.u64 t, %1; cvt.u32.u64 %0, t; }"
        : "=r"(a) : "l"(p));
    return a;
}

__device__ __forceinline__ void cpa16(uint32_t dst, const void* src) {
    asm volatile("cp.async.cg.shared.global [%0], [%1], 16;"
                 :: "r"(dst), "l"(src));
}

__device__ __forceinline__ void ldsm4(uint32_t& r0, uint32_t& r1,
                                      uint32_t& r2, uint32_t& r3, uint32_t a) {
    asm volatile("ldmatrix.sync.aligned.m8n8.x4.shared.b16 {%0,%1,%2,%3}, [%4];"
                 : "=r"(r0), "=r"(r1), "=r"(r2), "=r"(r3) : "r"(a));
}
__device__ __forceinline__ void ldsm4t(uint32_t& r0, uint32_t& r1,
                                       uint32_t& r2, uint32_t& r3, uint32_t a) {
    asm volatile("ldmatrix.sync.aligned.m8n8.x4.trans.shared.b16 {%0,%1,%2,%3}, [%4];"
                 : "=r"(r0), "=r"(r1), "=r"(r2), "=r"(r3) : "r"(a));
}

__device__ __forceinline__ void mma16816(float c[4], const uint32_t a[4],
                                         uint32_t b0, uint32_t b1) {
    asm volatile(
        "mma.sync.aligned.m16n8k16.row.col.f32.f16.f16.f32 "
        "{%0,%1,%2,%3}, {%4,%5,%6,%7}, {%8,%9}, {%0,%1,%2,%3};\n"
        : "+f"(c[0]), "+f"(c[1]), "+f"(c[2]), "+f"(c[3])
        : "r"(a[0]), "r"(a[1]), "r"(a[2]), "r"(a[3]), "r"(b0), "r"(b1));
}

// ============================================================================
// 3-product split GEMM (TN): C = Ah*Bh^T + Ah*Bl^T + Al*Bh^T (+bias)
// CTA tile 128x128. Paired stage tiles: 128 rows x 8 chunks of 16B,
// chunks 0-3 = hi halves k0..k0+31, chunks 4-7 = lo halves k0..k0+31.
// 3-stage cp.async pipeline, 32KB/stage.
//   EPI: 0 = fp32 store; 1 = bias + hi/lo half split store
// ============================================================================
template<int KVAL, int EPI>
__device__ __forceinline__ void gemm_split3(
    const __half* __restrict__ Ah, const __half* __restrict__ Al,
    const __half* __restrict__ Bh, const __half* __restrict__ Bl,
    int lda, int ldb,
    float* __restrict__ Cf, __half* __restrict__ Ch, __half* __restrict__ Cl,
    const float* __restrict__ bias, int ldc)
{
    constexpr int T = KVAL / 32;          // chunk iterations
    constexpr int STAGES = 3;
    constexpr uint32_t STAGE = 32768u;

    extern __shared__ __align__(16) char smem[];
    const uint32_t sbase = smem_u32(smem);

    const int tid  = threadIdx.x;
    const int lane = tid & 31;
    const int warp = tid >> 5;
    const int wm = warp & 3;
    const int wn = warp >> 2;
    const int tm0 = blockIdx.y * 128;
    const int tn0 = blockIdx.x * 128;

    // cp.async: 4 x 16B per thread per tile; chunk c<4 from hi, else lo
    uint32_t dA[4], dB[4];
    const __half* pA[4];
    const __half* pB[4];
    #pragma unroll
    for (int i = 0; i < 4; ++i) {
        const int slot = tid + i * 256;
        const int r = slot >> 3, c = slot & 7;
        const uint32_t d = (uint32_t)(r * 128 + ((c ^ (r & 7)) << 4));
        dA[i] = d;
        dB[i] = d;
        pA[i] = ((c < 4) ? Ah : Al) + (size_t)(tm0 + r) * lda + (c & 3) * 8;
        pB[i] = ((c < 4) ? Bh : Bl) + (size_t)(tn0 + r) * ldb + (c & 3) * 8;
    }

    // ldmatrix address precompute
    const uint32_t kcoA = (lane >> 4) & 1;
    uint32_t aoff[2], asw[2];
    {
        const int roff = (lane & 7) + (((lane >> 3) & 1) << 3);
        #pragma unroll
        for (int mi = 0; mi < 2; ++mi) {
            const int r = wm * 32 + mi * 16 + roff;
            aoff[mi] = (uint32_t)(r * 128);
            asw[mi]  = (uint32_t)(r & 7);
        }
    }
    const uint32_t kcoB = (lane >> 3) & 1;
    uint32_t boff[4], bsw[4];
    {
        const int noff = (lane & 7) + (((lane >> 4) & 1) << 3);
        #pragma unroll
        for (int p = 0; p < 4; ++p) {
            const int r = wn * 64 + p * 16 + noff;
            boff[p] = (uint32_t)(r * 128);
            bsw[p]  = (uint32_t)(r & 7);
        }
    }

    float acc[2][8][4];
    #pragma unroll
    for (int mi = 0; mi < 2; ++mi)
        #pragma unroll
        for (int ni = 0; ni < 8; ++ni)
            #pragma unroll
            for (int j = 0; j < 4; ++j) acc[mi][ni][j] = 0.f;

    auto issue = [&](int t) {
        const int k0 = t * 32;
        const uint32_t s = sbase + (uint32_t)(t % STAGES) * STAGE;
        #pragma unroll
        for (int i = 0; i < 4; ++i) {
            cpa16(s + dA[i], pA[i] + k0);
            cpa16(s + 16384u + dB[i], pB[i] + k0);
        }
    };

    #pragma unroll
    for (int s = 0; s < STAGES - 1; ++s) {
        if (s < T) issue(s);
        asm volatile("cp.async.commit_group;");
    }

    for (int t = 0; t < T; ++t) {
        asm volatile("cp.async.wait_group 1;");
        __syncthreads();
        if (t + STAGES - 1 < T) issue(t + STAGES - 1);
        asm volatile("cp.async.commit_group;");

        const uint32_t sA = sbase + (uint32_t)(t % STAGES) * STAGE;
        const uint32_t sB = sA + 16384u;
        #pragma unroll
        for (int kk = 0; kk < 2; ++kk) {
            uint32_t ah[2][4], al[2][4];
            #pragma unroll
            for (int mi = 0; mi < 2; ++mi) {
                ldsm4(ah[mi][0], ah[mi][1], ah[mi][2], ah[mi][3],
                      sA + aoff[mi] + ((((uint32_t)(2 * kk) + kcoA) ^ asw[mi]) << 4));
                ldsm4(al[mi][0], al[mi][1], al[mi][2], al[mi][3],
                      sA + aoff[mi] + ((((uint32_t)(4 + 2 * kk) + kcoA) ^ asw[mi]) << 4));
            }
            #pragma unroll
            for (int p = 0; p < 4; ++p) {
                uint32_t bh[4], bl[4];
                ldsm4(bh[0], bh[1], bh[2], bh[3],
                      sB + boff[p] + ((((uint32_t)(2 * kk) + kcoB) ^ bsw[p]) << 4));
                ldsm4(bl[0], bl[1], bl[2], bl[3],
                      sB + boff[p] + ((((uint32_t)(4 + 2 * kk) + kcoB) ^ bsw[p]) << 4));
                #pragma unroll
                for (int mi = 0; mi < 2; ++mi) {
                    mma16816(acc[mi][2 * p],     ah[mi], bh[0], bh[1]);
                    mma16816(acc[mi][2 * p + 1], ah[mi], bh[2], bh[3]);
                    mma16816(acc[mi][2 * p],     ah[mi], bl[0], bl[1]);
                    mma16816(acc[mi][2 * p + 1], ah[mi], bl[2], bl[3]);
                    mma16816(acc[mi][2 * p],     al[mi], bh[0], bh[1]);
                    mma16816(acc[mi][2 * p + 1], al[mi], bh[2], bh[3]);
                }
            }
        }
    }

    // ---- epilogue ----
    const int gid = lane >> 2, qid = lane & 3;
    #pragma unroll
    for (int mi = 0; mi < 2; ++mi) {
        #pragma unroll
        for (int ni = 0; ni < 8; ++ni) {
            const int r = tm0 + wm * 32 + mi * 16 + gid;
            const int c = tn0 + wn * 64 + ni * 8 + qid * 2;
            float v0 = acc[mi][ni][0], v1 = acc[mi][ni][1];
            float v2 = acc[mi][ni][2], v3 = acc[mi][ni][3];
            if (EPI == 1) {
                const float2 bb = *reinterpret_cast<const float2*>(bias + c);
                v0 += bb.x; v1 += bb.y; v2 += bb.x; v3 += bb.y;
            }
            if (EPI == 0) {
                *reinterpret_cast<float2*>(Cf + (size_t)r * ldc + c) =
                    make_float2(v0, v1);
                *reinterpret_cast<float2*>(Cf + (size_t)(r + 8) * ldc + c) =
                    make_float2(v2, v3);
            } else {
                const __half h0 = __float2half_rn(v0), h1 = __float2half_rn(v1);
                const __half h2 = __float2half_rn(v2), h3 = __float2half_rn(v3);
                *reinterpret_cast<__half2*>(Ch + (size_t)r * ldc + c) =
                    __halves2half2(h0, h1);
                *reinterpret_cast<__half2*>(Ch + (size_t)(r + 8) * ldc + c) =
                    __halves2half2(h2, h3);
                *reinterpret_cast<__half2*>(Cl + (size_t)r * ldc + c) =
                    __halves2half2(__float2half_rn(v0 - __half2float(h0)),
                                   __float2half_rn(v1 - __half2float(h1)));
                *reinterpret_cast<__half2*>(Cl + (size_t)(r + 8) * ldc + c) =
                    __halves2half2(__float2half_rn(v2 - __half2float(h2)),
                                   __float2half_rn(v3 - __half2float(h3)));
            }
        }
    }
}

// ============================================================================
// Single-product GEMM core (unchanged from round 5): 128x128 tile, BK=64,
// 3-stage cp.async.  BNN=false TN; BNN=true NN.
//   EPI: 0 = fp32 store; 2 = bias + half store
// ============================================================================
template<int KVAL, bool BNN, int EPI>
__device__ __forceinline__ void gemm_main(
    const __half* __restrict__ Ah, const __half* __restrict__ Bh,
    int lda, int ldb,
    float* __restrict__ Cf, __half* __restrict__ Ch,
    const float* __restrict__ bias, int ldc)
{
    constexpr int T = KVAL / 64;
    constexpr int STAGES = 3;
    constexpr uint32_t STAGE = 32768u;

    extern __shared__ __align__(16) char smem[];
    const uint32_t sbase = smem_u32(smem);

    const int tid  = threadIdx.x;
    const int lane = tid & 31;
    const int warp = tid >> 5;
    const int wm = warp & 3;
    const int wn = warp >> 2;
    const int tm0 = blockIdx.y * 128;
    const int tn0 = blockIdx.x * 128;

    uint32_t dA[4], gA[4], dB[4], gB[4];
    #pragma unroll
    for (int i = 0; i < 4; ++i) {
        const int slot = tid + i * 256;
        { const int r = slot >> 3, c = slot & 7;
          dA[i] = (uint32_t)(r * 128 + ((c ^ (r & 7)) << 4));
          gA[i] = (uint32_t)((tm0 + r) * lda + c * 8); }
        if (!BNN) {
            const int r = slot >> 3, c = slot & 7;
            dB[i] = (uint32_t)(r * 128 + ((c ^ (r & 7)) << 4));
            gB[i] = (uint32_t)((tn0 + r) * ldb + c * 8);
        } else {
            const int r = slot >> 4, c = slot & 15;
            dB[i] = (uint32_t)(r * 256 + ((c ^ (r & 7)) << 4));
            gB[i] = (uint32_t)(r * ldb + tn0 + c * 8);
        }
    }

    const uint32_t kcoA = (lane >> 4) & 1;
    uint32_t aoff[2], asw[2];
    {
        const int roff = (lane & 7) + (((lane >> 3) & 1) << 3);
        #pragma unroll
        for (int mi = 0; mi < 2; ++mi) {
            const int r = wm * 32 + mi * 16 + roff;
            aoff[mi] = (uint32_t)(r * 128);
            asw[mi]  = (uint32_t)(r & 7);
        }
    }
    const uint32_t kcoB = (lane >> 3) & 1;
    uint32_t boff[4], bsw[4];
    uint32_t bco[4], bkoff = 0;
    if (!BNN) {
        const int noff = (lane & 7) + (((lane >> 4) & 1) << 3);
        #pragma unroll
        for (int p = 0; p < 4; ++p) {
            const int r = wn * 64 + p * 16 + noff;
            boff[p] = (uint32_t)(r * 128);
            bsw[p]  = (uint32_t)(r & 7);
        }
    } else {
        const int koff = (lane & 7) + (((lane >> 3) & 1) << 3);
        bkoff = (uint32_t)(koff * 256);
        const int ncsel = (lane >> 4) & 1;
        #pragma unroll
        for (int p = 0; p < 4; ++p) {
            const int ncb = wn * 8 + p * 2 + ncsel;
            bco[p] = (uint32_t)((ncb ^ (lane & 7)) << 4);
        }
    }

    float acc[2][8][4];
    #pragma unroll
    for (int mi = 0; mi < 2; ++mi)
        #pragma unroll
        for (int ni = 0; ni < 8; ++ni)
            #pragma unroll
            for (int j = 0; j < 4; ++j) acc[mi][ni][j] = 0.f;

    auto issue = [&](int t) {
        const int k0 = t * 64;
        const uint32_t s = sbase + (uint32_t)(t % STAGES) * STAGE;
        #pragma unroll
        for (int i = 0; i < 4; ++i) {
            cpa16(s + dA[i], Ah + gA[i] + k0);
            if (!BNN) cpa16(s + 16384u + dB[i], Bh + gB[i] + k0);
            else      cpa16(s + 16384u + dB[i], Bh + gB[i] + (size_t)k0 * ldb);
        }
    };

    #pragma unroll
    for (int s = 0; s < STAGES - 1; ++s) {
        if (s < T) issue(s);
        asm volatile("cp.async.commit_group;");
    }

    for (int t = 0; t < T; ++t) {
        asm volatile("cp.async.wait_group 1;");
        __syncthreads();
        if (t + STAGES - 1 < T) issue(t + STAGES - 1);
        asm volatile("cp.async.commit_group;");

        const uint32_t sA = sbase + (uint32_t)(t % STAGES) * STAGE;
        const uint32_t sB = sA + 16384u;
        #pragma unroll
        for (int kk = 0; kk < 4; ++kk) {
            uint32_t a[2][4];
            #pragma unroll
            for (int mi = 0; mi < 2; ++mi)
                ldsm4(a[mi][0], a[mi][1], a[mi][2], a[mi][3],
                      sA + aoff[mi] + ((((uint32_t)(2 * kk) + kcoA) ^ asw[mi]) << 4));
            uint32_t b[4][4];
            #pragma unroll
            for (int p = 0; p < 4; ++p) {
                if (!BNN)
                    ldsm4(b[p][0], b[p][1], b[p][2], b[p][3],
                          sB + boff[p] + ((((uint32_t)(2 * kk) + kcoB) ^ bsw[p]) << 4));
                else
                    ldsm4t(b[p][0], b[p][1], b[p][2], b[p][3],
                           sB + (uint32_t)kk * 4096u + bkoff + bco[p]);
            }
            #pragma unroll
            for (int mi = 0; mi < 2; ++mi)
                #pragma unroll
                for (int p = 0; p < 4; ++p) {
                    mma16816(acc[mi][2 * p],     a[mi], b[p][0], b[p][1]);
                    mma16816(acc[mi][2 * p + 1], a[mi], b[p][2], b[p][3]);
                }
        }
    }

    const int gid = lane >> 2, qid = lane & 3;
    #pragma unroll
    for (int mi = 0; mi < 2; ++mi) {
        #pragma unroll
        for (int ni = 0; ni < 8; ++ni) {
            const int r = tm0 + wm * 32 + mi * 16 + gid;
            const int c = tn0 + wn * 64 + ni * 8 + qid * 2;
            float v0 = acc[mi][ni][0], v1 = acc[mi][ni][1];
            float v2 = acc[mi][ni][2], v3 = acc[mi][ni][3];
            if (EPI == 2) {
                const float2 bb = *reinterpret_cast<const float2*>(bias + c);
                v0 += bb.x; v1 += bb.y; v2 += bb.x; v3 += bb.y;
            }
            if (EPI == 0) {
                *reinterpret_cast<float2*>(Cf + (size_t)r * ldc + c) =
                    make_float2(v0, v1);
                *reinterpret_cast<float2*>(Cf + (size_t)(r + 8) * ldc + c) =
                    make_float2(v2, v3);
            } else {
                *reinterpret_cast<__half2*>(Ch + (size_t)r * ldc + c) =
                    __halves2half2(__float2half_rn(v0), __float2half_rn(v1));
                *reinterpret_cast<__half2*>(Ch + (size_t)(r + 8) * ldc + c) =
                    __halves2half2(__float2half_rn(v2), __float2half_rn(v3));
            }
        }
    }
}

// ----------------------------------------------------------------------------
// split kernels
// ----------------------------------------------------------------------------
__device__ __forceinline__ void split4(const float4 v, __half2* dh, __half2* dl) {
    const __half h0 = __float2half_rn(v.x), h1 = __float2half_rn(v.y);
    const __half h2 = __float2half_rn(v.z), h3 = __float2half_rn(v.w);
    dh[0] = __halves2half2(h0, h1);
    dh[1] = __halves2half2(h2, h3);
    dl[0] = __halves2half2(__float2half_rn(v.x - __half2float(h0)),
                           __float2half_rn(v.y - __half2float(h1)));
    dl[1] = __halves2half2(__float2half_rn(v.z - __half2float(h2)),
                           __float2half_rn(v.w - __half2float(h3)));
}

__global__ __launch_bounds__(256)
void split_x_kernel(const float* __restrict__ src)
{
    const int i = blockIdx.x * blockDim.x + threadIdx.x;
    const float4 v = reinterpret_cast<const float4*>(src)[i];
    split4(v, reinterpret_cast<__half2*>(g_xh) + 2 * i,
              reinterpret_cast<__half2*>(g_xl) + 2 * i);
}

__global__ __launch_bounds__(256)
void split_w_kernel(const float* __restrict__ Wq, const float* __restrict__ Wk,
                    const float* __restrict__ Wv)
{
    const float* src = (blockIdx.z == 0) ? Wq : (blockIdx.z == 1) ? Wk : Wv;
    const size_t off = (size_t)blockIdx.z * (HID * HID / 4);
    const int i = blockIdx.x * blockDim.x + threadIdx.x;
    const float4 v = reinterpret_cast<const float4*>(src)[i];
    split4(v, reinterpret_cast<__half2*>(g_wh) + 2 * (off + i),
              reinterpret_cast<__half2*>(g_wl) + 2 * (off + i));
}

// ----------------------------------------------------------------------------
// GEMM kernels
// ----------------------------------------------------------------------------
__global__ __launch_bounds__(256, 2)
void qkv_kernel(const float* __restrict__ bq, const float* __restrict__ bk,
                const float* __restrict__ bv)
{
    const int z = blockIdx.z;
    const __half* Wh = g_wh + (size_t)z * HID * HID;
    const __half* Wl = g_wl + (size_t)z * HID * HID;
    if (z == 0)
        gemm_split3<1024, 1>(g_xh, g_xl, Wh, Wl, HID, HID,
                             nullptr, g_qh, g_ql, bq, HID);
    else if (z == 1)
        gemm_split3<1024, 1>(g_xh, g_xl, Wh, Wl, HID, HID,
                             nullptr, g_kh, g_kl, bk, HID);
    else
        gemm_main<1024, false, 2>(g_xh, Wh, HID, HID,
                                  nullptr, g_vh, bv, HID);
}

__global__ __launch_bounds__(256, 2)
void scores_kernel()
{
    const size_t bo = (size_t)blockIdx.z * SEQ * HID;
    gemm_split3<1024, 0>(g_qh + bo, g_ql + bo, g_kh + bo, g_kl + bo,
                         HID, HID,
                         g_s + (size_t)blockIdx.z * SEQ * SEQ,
                         nullptr, nullptr, nullptr, SEQ);
}

__global__ __launch_bounds__(256, 2)
void pv_kernel(float* __restrict__ out)
{
    const size_t so = (size_t)blockIdx.z * SEQ * SEQ;
    const size_t vo = (size_t)blockIdx.z * SEQ * HID;
    gemm_main<2048, true, 0>(g_p + so, g_vh + vo, SEQ, HID,
                             out + vo, nullptr, nullptr, HID);
}

// ----------------------------------------------------------------------------
// softmax with threshold-gated exp (elements < rowmax-17 -> 0)
// ----------------------------------------------------------------------------
__global__ __launch_bounds__(256)
void softmax_kernel()
{
    const float* src = g_s + (size_t)blockIdx.x * SEQ;
    __half* dst = g_p + (size_t)blockIdx.x * SEQ;
    const int t = threadIdx.x;
    __shared__ float red[8];

    const float4* p4 = reinterpret_cast<const float4*>(src);
    float4 u0 = p4[t];
    float4 u1 = p4[t + 256];

    const float m0 = fmaxf(fmaxf(u0.x, u0.y), fmaxf(u0.z, u0.w));
    const float m1 = fmaxf(fmaxf(u1.x, u1.y), fmaxf(u1.z, u1.w));
    float m = fmaxf(m0, m1);
    #pragma unroll
    for (int off = 16; off; off >>= 1)
        m = fmaxf(m, __shfl_xor_sync(0xffffffffu, m, off));
    if ((t & 31) == 0) red[t >> 5] = m;
    __syncthreads();
    if (t < 8) {
        float mm = red[t];
        #pragma unroll
        for (int off = 4; off; off >>= 1)
            mm = fmaxf(mm, __shfl_xor_sync(0xffu, mm, off));
        if (t == 0) red[0] = mm;
    }
    __syncthreads();
    m = red[0];
    __syncthreads();

    const float thr = m - 17.0f;

    if (__any_sync(0xffffffffu, m0 > thr)) {
        u0.x = (u0.x > thr) ? __expf(u0.x - m) : 0.f;
        u0.y = (u0.y > thr) ? __expf(u0.y - m) : 0.f;
        u0.z = (u0.z > thr) ? __expf(u0.z - m) : 0.f;
        u0.w = (u0.w > thr) ? __expf(u0.w - m) : 0.f;
    } else {
        u0.x = u0.y = u0.z = u0.w = 0.f;
    }
    if (__any_sync(0xffffffffu, m1 > thr)) {
        u1.x = (u1.x > thr) ? __expf(u1.x - m) : 0.f;
        u1.y = (u1.y > thr) ? __expf(u1.y - m) : 0.f;
        u1.z = (u1.z > thr) ? __expf(u1.z - m) : 0.f;
        u1.w = (u1.w > thr) ? __expf(u1.w - m) : 0.f;
    } else {
        u1.x = u1.y = u1.z = u1.w = 0.f;
    }

    float s = (u0.x + u0.y + u0.z + u0.w) + (u1.x + u1.y + u1.z + u1.w);
    #pragma unroll
    for (int off = 16; off; off >>= 1)
        s += __shfl_xor_sync(0xffffffffu, s, off);
    if ((t & 31) == 0) red[t >> 5] = s;
    __syncthreads();
    if (t < 8) {
        float ss = red[t];
        #pragma unroll
        for (int off = 4; off; off >>= 1)
            ss += __shfl_xor_sync(0xffu, ss, off);
        if (t == 0) red[0] = ss;
    }
    __syncthreads();
    const float inv = 1.0f / red[0];

    __half2* d2 = reinterpret_cast<__half2*>(dst);
    d2[2 * t]           = __halves2half2(__float2half_rn(u0.x * inv),
                                         __float2half_rn(u0.y * inv));
    d2[2 * t + 1]       = __halves2half2(__float2half_rn(u0.z * inv),
                                         __float2half_rn(u0.w * inv));
    d2[512 + 2 * t]     = __halves2half2(__float2half_rn(u1.x * inv),
                                         __float2half_rn(u1.y * inv));
    d2[512 + 2 * t + 1] = __halves2half2(__float2half_rn(u1.z * inv),
                                         __float2half_rn(u1.w * inv));
}

// ----------------------------------------------------------------------------
// launch
// ----------------------------------------------------------------------------
#define GEMM_SMEM 98304

extern "C" void kernel_launch(void* const* d_in, const int* in_sizes, int n_in,
                              void* d_out, int out_size)
{
    (void)in_sizes; (void)n_in; (void)out_size;
    const float* x  = (const float*)d_in[0];
    const float* Wq = (const float*)d_in[1];
    const float* bq = (const float*)d_in[2];
    const float* Wk = (const float*)d_in[3];
    const float* bk = (const float*)d_in[4];
    const float* Wv = (const float*)d_in[5];
    const float* bv = (const float*)d_in[6];
    float* out = (float*)d_out;

    cudaFuncSetAttribute(qkv_kernel,
        cudaFuncAttributeMaxDynamicSharedMemorySize, GEMM_SMEM);
    cudaFuncSetAttribute(scores_kernel,
        cudaFuncAttributeMaxDynamicSharedMemorySize, GEMM_SMEM);
    cudaFuncSetAttribute(pv_kernel,
        cudaFuncAttributeMaxDynamicSharedMemorySize, GEMM_SMEM);

    // 0) hi/lo splits of x and the three weight matrices
    split_x_kernel<<<MTOT * HID / 4 / 256, 256>>>(x);
    split_w_kernel<<<dim3(HID * HID / 4 / 256, 1, 3), 256>>>(Wq, Wk, Wv);

    // 1) q/k/v projections (q,k: 3-product paired-tile; v: 1x fp16)
    qkv_kernel<<<dim3(HID / 128, MTOT / 128, 3), 256, GEMM_SMEM>>>(bq, bk, bv);
    // 2) scores = q k^T (3-product paired-tile) -> fp32
    scores_kernel<<<dim3(SEQ / 128, SEQ / 128, BATCH), 256, GEMM_SMEM>>>();
    // 3) softmax rows -> fp16 P (threshold-gated exp)
    softmax_kernel<<<BATCH * SEQ, 256>>>();
    // 4) out = P v (1x fp16)
    pv_kernel<<<dim3(HID / 128, SEQ / 128, BATCH), 256, GEMM_SMEM>>>(out);
}

// round 7
// speedup vs baseline: 1.0145x; 1.0145x over previous
#include <cuda_runtime.h>
#include <cuda_fp16.h>
#include <cstdint>

// ============================================================================
// SelfAttention: out = softmax( (xWq^T+bq)(xWk^T+bk)^T ) (xWv^T+bv)
// B=4, S=2048, H=1024 (fp32 in/out)
// All GEMMs: legacy mma.sync m16n8k16 fp16 (tcgen05 unavailable on sm_100).
// Precision: 3x-FP16 hi/lo split for q/k projections + scores; 1x for V & PV.
// Split GEMMs: PAIRED tiles (hi chunks 0-3, lo chunks 4-7 per 128B row) with
// PRODUCT-MAJOR mma ordering (acc reuse distance 16 mmas — fixes round-6's
// accumulator RAW stall).
// ============================================================================

#define BATCH 4
#define SEQ   2048
#define HID   1024
#define MTOT  (BATCH*SEQ)          // 8192

// ---- scratch (device globals; allocation-free per harness rules) ----
__device__ __half g_xh[(size_t)MTOT * HID];
__device__ __half g_xl[(size_t)MTOT * HID];
__device__ __half g_wh[(size_t)3 * HID * HID];
__device__ __half g_wl[(size_t)3 * HID * HID];
__device__ __half g_qh[(size_t)MTOT * HID];
__device__ __half g_ql[(size_t)MTOT * HID];
__device__ __half g_kh[(size_t)MTOT * HID];
__device__ __half g_kl[(size_t)MTOT * HID];
__device__ __half g_vh[(size_t)MTOT * HID];
__device__ float  g_s [(size_t)BATCH * SEQ * SEQ];
__device__ __half g_p [(size_t)BATCH * SEQ * SEQ];

// ----------------------------------------------------------------------------
// helpers
// ----------------------------------------------------------------------------
__device__ __forceinline__ uint32_t smem_u32(const void* p) {
    uint32_t a;
    asm("{ .reg .u64 t; cvta.to.shared.u64 t, %1; cvt.u32.u64 %0, t; }"
        : "=r"(a) : "l"(p));
    return a;
}

__device__ __forceinline__ void cpa16(uint32_t dst, const void* src) {
    asm volatile("cp.async.cg.shared.global [%0], [%1], 16;"
                 :: "r"(dst), "l"(src));
}

__device__ __forceinline__ void ldsm4(uint32_t& r0, uint32_t& r1,
                                      uint32_t& r2, uint32_t& r3, uint32_t a) {
    asm volatile("ldmatrix.sync.aligned.m8n8.x4.shared.b16 {%0,%1,%2,%3}, [%4];"
                 : "=r"(r0), "=r"(r1), "=r"(r2), "=r"(r3) : "r"(a));
}
__device__ __forceinline__ void ldsm4t(uint32_t& r0, uint32_t& r1,
                                       uint32_t& r2, uint32_t& r3, uint32_t a) {
    asm volatile("ldmatrix.sync.aligned.m8n8.x4.trans.shared.b16 {%0,%1,%2,%3}, [%4];"
                 : "=r"(r0), "=r"(r1), "=r"(r2), "=r"(r3) : "r"(a));
}

__device__ __forceinline__ void mma16816(float c[4], const uint32_t a[4],
                                         uint32_t b0, uint32_t b1) {
    asm volatile(
        "mma.sync.aligned.m16n8k16.row.col.f32.f16.f16.f32 "
        "{%0,%1,%2,%3}, {%4,%5,%6,%7}, {%8,%9}, {%0,%1,%2,%3};\n"
        : "+f"(c[0]), "+f"(c[1]), "+f"(c[2]), "+f"(c[3])
        : "r"(a[0]), "r"(a[1]), "r"(a[2]), "r"(a[3]), "r"(b0), "r"(b1));
}

// ============================================================================
// 3-product split GEMM (TN): C = Ah*Bh^T + Al*Bh^T + Ah*Bl^T (+bias)
// CTA tile 128x128. Paired stage tiles: 128 rows x 8 chunks of 16B,
// chunks 0-3 = hi halves k0..k0+31, chunks 4-7 = lo halves k0..k0+31.
// 3-stage cp.async pipeline, 32KB/stage. Product-major mma ordering.
//   EPI: 0 = fp32 store; 1 = bias + hi/lo half split store
// ============================================================================
template<int KVAL, int EPI>
__device__ __forceinline__ void gemm_split3(
    const __half* __restrict__ Ah, const __half* __restrict__ Al,
    const __half* __restrict__ Bh, const __half* __restrict__ Bl,
    int lda, int ldb,
    float* __restrict__ Cf, __half* __restrict__ Ch, __half* __restrict__ Cl,
    const float* __restrict__ bias, int ldc)
{
    constexpr int T = KVAL / 32;          // chunk iterations
    constexpr int STAGES = 3;
    constexpr uint32_t STAGE = 32768u;

    extern __shared__ __align__(16) char smem[];
    const uint32_t sbase = smem_u32(smem);

    const int tid  = threadIdx.x;
    const int lane = tid & 31;
    const int warp = tid >> 5;
    const int wm = warp & 3;
    const int wn = warp >> 2;
    const int tm0 = blockIdx.y * 128;
    const int tn0 = blockIdx.x * 128;

    // cp.async: 4 x 16B per thread per tile; chunk c<4 from hi, else lo
    uint32_t dA[4], dB[4];
    const __half* pA[4];
    const __half* pB[4];
    #pragma unroll
    for (int i = 0; i < 4; ++i) {
        const int slot = tid + i * 256;
        const int r = slot >> 3, c = slot & 7;
        const uint32_t d = (uint32_t)(r * 128 + ((c ^ (r & 7)) << 4));
        dA[i] = d;
        dB[i] = d;
        pA[i] = ((c < 4) ? Ah : Al) + (size_t)(tm0 + r) * lda + (c & 3) * 8;
        pB[i] = ((c < 4) ? Bh : Bl) + (size_t)(tn0 + r) * ldb + (c & 3) * 8;
    }

    // ldmatrix address precompute
    const uint32_t kcoA = (lane >> 4) & 1;
    uint32_t aoff[2], asw[2];
    {
        const int roff = (lane & 7) + (((lane >> 3) & 1) << 3);
        #pragma unroll
        for (int mi = 0; mi < 2; ++mi) {
            const int r = wm * 32 + mi * 16 + roff;
            aoff[mi] = (uint32_t)(r * 128);
            asw[mi]  = (uint32_t)(r & 7);
        }
    }
    const uint32_t kcoB = (lane >> 3) & 1;
    uint32_t boff[4], bsw[4];
    {
        const int noff = (lane & 7) + (((lane >> 4) & 1) << 3);
        #pragma unroll
        for (int p = 0; p < 4; ++p) {
            const int r = wn * 64 + p * 16 + noff;
            boff[p] = (uint32_t)(r * 128);
            bsw[p]  = (uint32_t)(r & 7);
        }
    }

    float acc[2][8][4];
    #pragma unroll
    for (int mi = 0; mi < 2; ++mi)
        #pragma unroll
        for (int ni = 0; ni < 8; ++ni)
            #pragma unroll
            for (int j = 0; j < 4; ++j) acc[mi][ni][j] = 0.f;

    auto issue = [&](int t) {
        const int k0 = t * 32;
        const uint32_t s = sbase + (uint32_t)(t % STAGES) * STAGE;
        #pragma unroll
        for (int i = 0; i < 4; ++i) {
            cpa16(s + dA[i], pA[i] + k0);
            cpa16(s + 16384u + dB[i], pB[i] + k0);
        }
    };

    #pragma unroll
    for (int s = 0; s < STAGES - 1; ++s) {
        if (s < T) issue(s);
        asm volatile("cp.async.commit_group;");
    }

    for (int t = 0; t < T; ++t) {
        asm volatile("cp.async.wait_group 1;");
        __syncthreads();
        if (t + STAGES - 1 < T) issue(t + STAGES - 1);
        asm volatile("cp.async.commit_group;");

        const uint32_t sA = sbase + (uint32_t)(t % STAGES) * STAGE;
        const uint32_t sB = sA + 16384u;
        #pragma unroll
        for (int kk = 0; kk < 2; ++kk) {
            // A fragments: hi (chunks 0-3) and lo (chunks 4-7)
            uint32_t ah[2][4], al[2][4];
            #pragma unroll
            for (int mi = 0; mi < 2; ++mi) {
                ldsm4(ah[mi][0], ah[mi][1], ah[mi][2], ah[mi][3],
                      sA + aoff[mi] + ((((uint32_t)(2 * kk) + kcoA) ^ asw[mi]) << 4));
                ldsm4(al[mi][0], al[mi][1], al[mi][2], al[mi][3],
                      sA + aoff[mi] + ((((uint32_t)(4 + 2 * kk) + kcoA) ^ asw[mi]) << 4));
            }
            // B hi fragments for ALL p (used by two product passes)
            uint32_t bh[4][4];
            #pragma unroll
            for (int p = 0; p < 4; ++p)
                ldsm4(bh[p][0], bh[p][1], bh[p][2], bh[p][3],
                      sB + boff[p] + ((((uint32_t)(2 * kk) + kcoB) ^ bsw[p]) << 4));

            // P0: Ah x Bh — 16 mmas over distinct accumulators
            #pragma unroll
            for (int mi = 0; mi < 2; ++mi)
                #pragma unroll
                for (int p = 0; p < 4; ++p) {
                    mma16816(acc[mi][2 * p],     ah[mi], bh[p][0], bh[p][1]);
                    mma16816(acc[mi][2 * p + 1], ah[mi], bh[p][2], bh[p][3]);
                }
            // P1: Al x Bh — reuses bh, acc reuse distance = 16 mmas
            #pragma unroll
            for (int mi = 0; mi < 2; ++mi)
                #pragma unroll
                for (int p = 0; p < 4; ++p) {
                    mma16816(acc[mi][2 * p],     al[mi], bh[p][0], bh[p][1]);
                    mma16816(acc[mi][2 * p + 1], al[mi], bh[p][2], bh[p][3]);
                }
            // B lo fragments (bh now dead)
            uint32_t bl[4][4];
            #pragma unroll
            for (int p = 0; p < 4; ++p)
                ldsm4(bl[p][0], bl[p][1], bl[p][2], bl[p][3],
                      sB + boff[p] + ((((uint32_t)(4 + 2 * kk) + kcoB) ^ bsw[p]) << 4));
            // P2: Ah x Bl
            #pragma unroll
            for (int mi = 0; mi < 2; ++mi)
                #pragma unroll
                for (int p = 0; p < 4; ++p) {
                    mma16816(acc[mi][2 * p],     ah[mi], bl[p][0], bl[p][1]);
                    mma16816(acc[mi][2 * p + 1], ah[mi], bl[p][2], bl[p][3]);
                }
        }
    }

    // ---- epilogue ----
    const int gid = lane >> 2, qid = lane & 3;
    #pragma unroll
    for (int mi = 0; mi < 2; ++mi) {
        #pragma unroll
        for (int ni = 0; ni < 8; ++ni) {
            const int r = tm0 + wm * 32 + mi * 16 + gid;
            const int c = tn0 + wn * 64 + ni * 8 + qid * 2;
            float v0 = acc[mi][ni][0], v1 = acc[mi][ni][1];
            float v2 = acc[mi][ni][2], v3 = acc[mi][ni][3];
            if (EPI == 1) {
                const float2 bb = *reinterpret_cast<const float2*>(bias + c);
                v0 += bb.x; v1 += bb.y; v2 += bb.x; v3 += bb.y;
            }
            if (EPI == 0) {
                *reinterpret_cast<float2*>(Cf + (size_t)r * ldc + c) =
                    make_float2(v0, v1);
                *reinterpret_cast<float2*>(Cf + (size_t)(r + 8) * ldc + c) =
                    make_float2(v2, v3);
            } else {
                const __half h0 = __float2half_rn(v0), h1 = __float2half_rn(v1);
                const __half h2 = __float2half_rn(v2), h3 = __float2half_rn(v3);
                *reinterpret_cast<__half2*>(Ch + (size_t)r * ldc + c) =
                    __halves2half2(h0, h1);
                *reinterpret_cast<__half2*>(Ch + (size_t)(r + 8) * ldc + c) =
                    __halves2half2(h2, h3);
                *reinterpret_cast<__half2*>(Cl + (size_t)r * ldc + c) =
                    __halves2half2(__float2half_rn(v0 - __half2float(h0)),
                                   __float2half_rn(v1 - __half2float(h1)));
                *reinterpret_cast<__half2*>(Cl + (size_t)(r + 8) * ldc + c) =
                    __halves2half2(__float2half_rn(v2 - __half2float(h2)),
                                   __float2half_rn(v3 - __half2float(h3)));
            }
        }
    }
}

// ============================================================================
// Single-product GEMM core: 128x128 tile, BK=64, 3-stage cp.async.
//   BNN=false TN; BNN=true NN.  EPI: 0 = fp32 store; 2 = bias + half store
// ============================================================================
template<int KVAL, bool BNN, int EPI>
__device__ __forceinline__ void gemm_main(
    const __half* __restrict__ Ah, const __half* __restrict__ Bh,
    int lda, int ldb,
    float* __restrict__ Cf, __half* __restrict__ Ch,
    const float* __restrict__ bias, int ldc)
{
    constexpr int T = KVAL / 64;
    constexpr int STAGES = 3;
    constexpr uint32_t STAGE = 32768u;

    extern __shared__ __align__(16) char smem[];
    const uint32_t sbase = smem_u32(smem);

    const int tid  = threadIdx.x;
    const int lane = tid & 31;
    const int warp = tid >> 5;
    const int wm = warp & 3;
    const int wn = warp >> 2;
    const int tm0 = blockIdx.y * 128;
    const int tn0 = blockIdx.x * 128;

    uint32_t dA[4], gA[4], dB[4], gB[4];
    #pragma unroll
    for (int i = 0; i < 4; ++i) {
        const int slot = tid + i * 256;
        { const int r = slot >> 3, c = slot & 7;
          dA[i] = (uint32_t)(r * 128 + ((c ^ (r & 7)) << 4));
          gA[i] = (uint32_t)((tm0 + r) * lda + c * 8); }
        if (!BNN) {
            const int r = slot >> 3, c = slot & 7;
            dB[i] = (uint32_t)(r * 128 + ((c ^ (r & 7)) << 4));
            gB[i] = (uint32_t)((tn0 + r) * ldb + c * 8);
        } else {
            const int r = slot >> 4, c = slot & 15;
            dB[i] = (uint32_t)(r * 256 + ((c ^ (r & 7)) << 4));
            gB[i] = (uint32_t)(r * ldb + tn0 + c * 8);
        }
    }

    const uint32_t kcoA = (lane >> 4) & 1;
    uint32_t aoff[2], asw[2];
    {
        const int roff = (lane & 7) + (((lane >> 3) & 1) << 3);
        #pragma unroll
        for (int mi = 0; mi < 2; ++mi) {
            const int r = wm * 32 + mi * 16 + roff;
            aoff[mi] = (uint32_t)(r * 128);
            asw[mi]  = (uint32_t)(r & 7);
        }
    }
    const uint32_t kcoB = (lane >> 3) & 1;
    uint32_t boff[4], bsw[4];
    uint32_t bco[4], bkoff = 0;
    if (!BNN) {
        const int noff = (lane & 7) + (((lane >> 4) & 1) << 3);
        #pragma unroll
        for (int p = 0; p < 4; ++p) {
            const int r = wn * 64 + p * 16 + noff;
            boff[p] = (uint32_t)(r * 128);
            bsw[p]  = (uint32_t)(r & 7);
        }
    } else {
        const int koff = (lane & 7) + (((lane >> 3) & 1) << 3);
        bkoff = (uint32_t)(koff * 256);
        const int ncsel = (lane >> 4) & 1;
        #pragma unroll
        for (int p = 0; p < 4; ++p) {
            const int ncb = wn * 8 + p * 2 + ncsel;
            bco[p] = (uint32_t)((ncb ^ (lane & 7)) << 4);
        }
    }

    float acc[2][8][4];
    #pragma unroll
    for (int mi = 0; mi < 2; ++mi)
        #pragma unroll
        for (int ni = 0; ni < 8; ++ni)
            #pragma unroll
            for (int j = 0; j < 4; ++j) acc[mi][ni][j] = 0.f;

    auto issue = [&](int t) {
        const int k0 = t * 64;
        const uint32_t s = sbase + (uint32_t)(t % STAGES) * STAGE;
        #pragma unroll
        for (int i = 0; i < 4; ++i) {
            cpa16(s + dA[i], Ah + gA[i] + k0);
            if (!BNN) cpa16(s + 16384u + dB[i], Bh + gB[i] + k0);
            else      cpa16(s + 16384u + dB[i], Bh + gB[i] + (size_t)k0 * ldb);
        }
    };

    #pragma unroll
    for (int s = 0; s < STAGES - 1; ++s) {
        if (s < T) issue(s);
        asm volatile("cp.async.commit_group;");
    }

    for (int t = 0; t < T; ++t) {
        asm volatile("cp.async.wait_group 1;");
        __syncthreads();
        if (t + STAGES - 1 < T) issue(t + STAGES - 1);
        asm volatile("cp.async.commit_group;");

        const uint32_t sA = sbase + (uint32_t)(t % STAGES) * STAGE;
        const uint32_t sB = sA + 16384u;
        #pragma unroll
        for (int kk = 0; kk < 4; ++kk) {
            uint32_t a[2][4];
            #pragma unroll
            for (int mi = 0; mi < 2; ++mi)
                ldsm4(a[mi][0], a[mi][1], a[mi][2], a[mi][3],
                      sA + aoff[mi] + ((((uint32_t)(2 * kk) + kcoA) ^ asw[mi]) << 4));
            uint32_t b[4][4];
            #pragma unroll
            for (int p = 0; p < 4; ++p) {
                if (!BNN)
                    ldsm4(b[p][0], b[p][1], b[p][2], b[p][3],
                          sB + boff[p] + ((((uint32_t)(2 * kk) + kcoB) ^ bsw[p]) << 4));
                else
                    ldsm4t(b[p][0], b[p][1], b[p][2], b[p][3],
                           sB + (uint32_t)kk * 4096u + bkoff + bco[p]);
            }
            #pragma unroll
            for (int mi = 0; mi < 2; ++mi)
                #pragma unroll
                for (int p = 0; p < 4; ++p) {
                    mma16816(acc[mi][2 * p],     a[mi], b[p][0], b[p][1]);
                    mma16816(acc[mi][2 * p + 1], a[mi], b[p][2], b[p][3]);
                }
        }
    }

    const int gid = lane >> 2, qid = lane & 3;
    #pragma unroll
    for (int mi = 0; mi < 2; ++mi) {
        #pragma unroll
        for (int ni = 0; ni < 8; ++ni) {
            const int r = tm0 + wm * 32 + mi * 16 + gid;
            const int c = tn0 + wn * 64 + ni * 8 + qid * 2;
            float v0 = acc[mi][ni][0], v1 = acc[mi][ni][1];
            float v2 = acc[mi][ni][2], v3 = acc[mi][ni][3];
            if (EPI == 2) {
                const float2 bb = *reinterpret_cast<const float2*>(bias + c);
                v0 += bb.x; v1 += bb.y; v2 += bb.x; v3 += bb.y;
            }
            if (EPI == 0) {
                *reinterpret_cast<float2*>(Cf + (size_t)r * ldc + c) =
                    make_float2(v0, v1);
                *reinterpret_cast<float2*>(Cf + (size_t)(r + 8) * ldc + c) =
                    make_float2(v2, v3);
            } else {
                *reinterpret_cast<__half2*>(Ch + (size_t)r * ldc + c) =
                    __halves2half2(__float2half_rn(v0), __float2half_rn(v1));
                *reinterpret_cast<__half2*>(Ch + (size_t)(r + 8) * ldc + c) =
                    __halves2half2(__float2half_rn(v2), __float2half_rn(v3));
            }
        }
    }
}

// ----------------------------------------------------------------------------
// split kernels
// ----------------------------------------------------------------------------
__device__ __forceinline__ void split4(const float4 v, __half2* dh, __half2* dl) {
    const __half h0 = __float2half_rn(v.x), h1 = __float2half_rn(v.y);
    const __half h2 = __float2half_rn(v.z), h3 = __float2half_rn(v.w);
    dh[0] = __halves2half2(h0, h1);
    dh[1] = __halves2half2(h2, h3);
    dl[0] = __halves2half2(__float2half_rn(v.x - __half2float(h0)),
                           __float2half_rn(v.y - __half2float(h1)));
    dl[1] = __halves2half2(__float2half_rn(v.z - __half2float(h2)),
                           __float2half_rn(v.w - __half2float(h3)));
}

__global__ __launch_bounds__(256)
void split_x_kernel(const float* __restrict__ src)
{
    const int i = blockIdx.x * blockDim.x + threadIdx.x;
    const float4 v = reinterpret_cast<const float4*>(src)[i];
    split4(v, reinterpret_cast<__half2*>(g_xh) + 2 * i,
              reinterpret_cast<__half2*>(g_xl) + 2 * i);
}

__global__ __launch_bounds__(256)
void split_w_kernel(const float* __restrict__ Wq, const float* __restrict__ Wk,
                    const float* __restrict__ Wv)
{
    const float* src = (blockIdx.z == 0) ? Wq : (blockIdx.z == 1) ? Wk : Wv;
    const size_t off = (size_t)blockIdx.z * (HID * HID / 4);
    const int i = blockIdx.x * blockDim.x + threadIdx.x;
    const float4 v = reinterpret_cast<const float4*>(src)[i];
    split4(v, reinterpret_cast<__half2*>(g_wh) + 2 * (off + i),
              reinterpret_cast<__half2*>(g_wl) + 2 * (off + i));
}

// ----------------------------------------------------------------------------
// GEMM kernels
// ----------------------------------------------------------------------------
__global__ __launch_bounds__(256, 2)
void qkv_kernel(const float* __restrict__ bq, const float* __restrict__ bk,
                const float* __restrict__ bv)
{
    const int z = blockIdx.z;
    const __half* Wh = g_wh + (size_t)z * HID * HID;
    const __half* Wl = g_wl + (size_t)z * HID * HID;
    if (z == 0)
        gemm_split3<1024, 1>(g_xh, g_xl, Wh, Wl, HID, HID,
                             nullptr, g_qh, g_ql, bq, HID);
    else if (z == 1)
        gemm_split3<1024, 1>(g_xh, g_xl, Wh, Wl, HID, HID,
                             nullptr, g_kh, g_kl, bk, HID);
    else
        gemm_main<1024, false, 2>(g_xh, Wh, HID, HID,
                                  nullptr, g_vh, bv, HID);
}

__global__ __launch_bounds__(256, 2)
void scores_kernel()
{
    const size_t bo = (size_t)blockIdx.z * SEQ * HID;
    gemm_split3<1024, 0>(g_qh + bo, g_ql + bo, g_kh + bo, g_kl + bo,
                         HID, HID,
                         g_s + (size_t)blockIdx.z * SEQ * SEQ,
                         nullptr, nullptr, nullptr, SEQ);
}

__global__ __launch_bounds__(256, 2)
void pv_kernel(float* __restrict__ out)
{
    const size_t so = (size_t)blockIdx.z * SEQ * SEQ;
    const size_t vo = (size_t)blockIdx.z * SEQ * HID;
    gemm_main<2048, true, 0>(g_p + so, g_vh + vo, SEQ, HID,
                             out + vo, nullptr, nullptr, HID);
}

// ----------------------------------------------------------------------------
// softmax with threshold-gated exp (elements < rowmax-17 -> 0)
// ----------------------------------------------------------------------------
__global__ __launch_bounds__(256)
void softmax_kernel()
{
    const float* src = g_s + (size_t)blockIdx.x * SEQ;
    __half* dst = g_p + (size_t)blockIdx.x * SEQ;
    const int t = threadIdx.x;
    __shared__ float red[8];

    const float4* p4 = reinterpret_cast<const float4*>(src);
    float4 u0 = p4[t];
    float4 u1 = p4[t + 256];

    const float m0 = fmaxf(fmaxf(u0.x, u0.y), fmaxf(u0.z, u0.w));
    const float m1 = fmaxf(fmaxf(u1.x, u1.y), fmaxf(u1.z, u1.w));
    float m = fmaxf(m0, m1);
    #pragma unroll
    for (int off = 16; off; off >>= 1)
        m = fmaxf(m, __shfl_xor_sync(0xffffffffu, m, off));
    if ((t & 31) == 0) red[t >> 5] = m;
    __syncthreads();
    if (t < 8) {
        float mm = red[t];
        #pragma unroll
        for (int off = 4; off; off >>= 1)
            mm = fmaxf(mm, __shfl_xor_sync(0xffu, mm, off));
        if (t == 0) red[0] = mm;
    }
    __syncthreads();
    m = red[0];
    __syncthreads();

    const float thr = m - 17.0f;

    if (__any_sync(0xffffffffu, m0 > thr)) {
        u0.x = (u0.x > thr) ? __expf(u0.x - m) : 0.f;
        u0.y = (u0.y > thr) ? __expf(u0.y - m) : 0.f;
        u0.z = (u0.z > thr) ? __expf(u0.z - m) : 0.f;
        u0.w = (u0.w > thr) ? __expf(u0.w - m) : 0.f;
    } else {
        u0.x = u0.y = u0.z = u0.w = 0.f;
    }
    if (__any_sync(0xffffffffu, m1 > thr)) {
        u1.x = (u1.x > thr) ? __expf(u1.x - m) : 0.f;
        u1.y = (u1.y > thr) ? __expf(u1.y - m) : 0.f;
        u1.z = (u1.z > thr) ? __expf(u1.z - m) : 0.f;
        u1.w = (u1.w > thr) ? __expf(u1.w - m) : 0.f;
    } else {
        u1.x = u1.y = u1.z = u1.w = 0.f;
    }

    float s = (u0.x + u0.y + u0.z + u0.w) + (u1.x + u1.y + u1.z + u1.w);
    #pragma unroll
    for (int off = 16; off; off >>= 1)
        s += __shfl_xor_sync(0xffffffffu, s, off);
    if ((t & 31) == 0) red[t >> 5] = s;
    __syncthreads();
    if (t < 8) {
        float ss = red[t];
        #pragma unroll
        for (int off = 4; off; off >>= 1)
            ss += __shfl_xor_sync(0xffu, ss, off);
        if (t == 0) red[0] = ss;
    }
    __syncthreads();
    const float inv = 1.0f / red[0];

    __half2* d2 = reinterpret_cast<__half2*>(dst);
    d2[2 * t]           = __halves2half2(__float2half_rn(u0.x * inv),
                                         __float2half_rn(u0.y * inv));
    d2[2 * t + 1]       = __halves2half2(__float2half_rn(u0.z * inv),
                                         __float2half_rn(u0.w * inv));
    d2[512 + 2 * t]     = __halves2half2(__float2half_rn(u1.x * inv),
                                         __float2half_rn(u1.y * inv));
    d2[512 + 2 * t + 1] = __halves2half2(__float2half_rn(u1.z * inv),
                                         __float2half_rn(u1.w * inv));
}

// ----------------------------------------------------------------------------
// launch
// ----------------------------------------------------------------------------
#define GEMM_SMEM 98304

extern "C" void kernel_launch(void* const* d_in, const int* in_sizes, int n_in,
                              void* d_out, int out_size)
{
    (void)in_sizes; (void)n_in; (void)out_size;
    const float* x  = (const float*)d_in[0];
    const float* Wq = (const float*)d_in[1];
    const float* bq = (const float*)d_in[2];
    const float* Wk = (const float*)d_in[3];
    const float* bk = (const float*)d_in[4];
    const float* Wv = (const float*)d_in[5];
    const float* bv = (const float*)d_in[6];
    float* out = (float*)d_out;

    cudaFuncSetAttribute(qkv_kernel,
        cudaFuncAttributeMaxDynamicSharedMemorySize, GEMM_SMEM);
    cudaFuncSetAttribute(scores_kernel,
        cudaFuncAttributeMaxDynamicSharedMemorySize, GEMM_SMEM);
    cudaFuncSetAttribute(pv_kernel,
        cudaFuncAttributeMaxDynamicSharedMemorySize, GEMM_SMEM);

    // 0) hi/lo splits of x and the three weight matrices
    split_x_kernel<<<MTOT * HID / 4 / 256, 256>>>(x);
    split_w_kernel<<<dim3(HID * HID / 4 / 256, 1, 3), 256>>>(Wq, Wk, Wv);

    // 1) q/k/v projections (q,k: 3-product paired-tile; v: 1x fp16)
    qkv_kernel<<<dim3(HID / 128, MTOT / 128, 3), 256, GEMM_SMEM>>>(bq, bk, bv);
    // 2) scores = q k^T (3-product paired-tile) -> fp32
    scores_kernel<<<dim3(SEQ / 128, SEQ / 128, BATCH), 256, GEMM_SMEM>>>();
    // 3) softmax rows -> fp16 P (threshold-gated exp)
    softmax_kernel<<<BATCH * SEQ, 256>>>();
    // 4) out = P v (1x fp16)
    pv_kernel<<<dim3(HID / 128, SEQ / 128, BATCH), 256, GEMM_SMEM>>>(out);
}

// round 9
// speedup vs baseline: 1.0325x; 1.0177x over previous
#include <cuda_runtime.h>
#include <cuda_fp16.h>
#include <cstdint>

// ============================================================================
// SelfAttention: out = softmax( (xWq^T+bq)(xWk^T+bk)^T ) (xWv^T+bv)
// B=4, S=2048, H=1024 (fp32 in/out)
// Algebraic reduction:  q_i.k_j = x_i (Wq^T Wk) x_j^T + rowconst + w_j
//   rowconst cancels in softmax; w_j = x_j.(Wk^T bq) added pre-exp (fp32).
// So: M = Wq^T Wk (split GEMM, tiny), y = x.M (split), scores = y.x^T (split),
// v = x.Wv^T + bv (1x), out = P.v (1x).  q/k projections eliminated.
// All GEMMs: mma.sync m16n8k16 fp16, 3x hi/lo split where needed (round-5 core).
// ============================================================================

#define BATCH 4
#define SEQ   2048
#define HID   1024
#define MTOT  (BATCH*SEQ)          // 8192

// ---- scratch (device globals; allocation-free per harness rules) ----
__device__ __half g_xh[(size_t)MTOT * HID];
__device__ __half g_xl[(size_t)MTOT * HID];
__device__ __half g_wqt_h[(size_t)HID * HID];   // Wq^T split
__device__ __half g_wqt_l[(size_t)HID * HID];
__device__ __half g_wk_h[(size_t)HID * HID];    // Wk split (row-major)
__device__ __half g_wk_l[(size_t)HID * HID];
__device__ __half g_wv_h[(size_t)HID * HID];    // Wv fp16
__device__ __half g_mh[(size_t)HID * HID];      // M = Wq^T Wk split
__device__ __half g_ml[(size_t)HID * HID];
__device__ __half g_yh[(size_t)MTOT * HID];     // y = x.M split
__device__ __half g_yl[(size_t)MTOT * HID];
__device__ __half g_vh[(size_t)MTOT * HID];
__device__ float  g_s [(size_t)BATCH * SEQ * SEQ];
__device__ __half g_p [(size_t)BATCH * SEQ * SEQ];
__device__ float  g_w [MTOT];                   // w_j per (batch,key)
__device__ float  g_t2[HID];                    // Wk^T bq
__device__ float  g_zero[HID];                  // static zero (bias for M,y)

// ----------------------------------------------------------------------------
// helpers
// ----------------------------------------------------------------------------
__device__ __forceinline__ uint32_t smem_u32(const void* p) {
    uint32_t a;
    asm("{ .reg .u64 t; cvta.to.shared.u64 t, %1; cvt.u32.u64 %0, t; }"
        : "=r"(a) : "l"(p));
    return a;
}

__device__ __forceinline__ void cpa16(uint32_t dst, const void* src) {
    asm volatile("cp.async.cg.shared.global [%0], [%1], 16;"
                 :: "r"(dst), "l"(src));
}

__device__ __forceinline__ void ldsm4(uint32_t& r0, uint32_t& r1,
                                      uint32_t& r2, uint32_t& r3, uint32_t a) {
    asm volatile("ldmatrix.sync.aligned.m8n8.x4.shared.b16 {%0,%1,%2,%3}, [%4];"
                 : "=r"(r0), "=r"(r1), "=r"(r2), "=r"(r3) : "r"(a));
}
__device__ __forceinline__ void ldsm4t(uint32_t& r0, uint32_t& r1,
                                       uint32_t& r2, uint32_t& r3, uint32_t a) {
    asm volatile("ldmatrix.sync.aligned.m8n8.x4.trans.shared.b16 {%0,%1,%2,%3}, [%4];"
                 : "=r"(r0), "=r"(r1), "=r"(r2), "=r"(r3) : "r"(a));
}

__device__ __forceinline__ void mma16816(float c[4], const uint32_t a[4],
                                         uint32_t b0, uint32_t b1) {
    asm volatile(
        "mma.sync.aligned.m16n8k16.row.col.f32.f16.f16.f32 "
        "{%0,%1,%2,%3}, {%4,%5,%6,%7}, {%8,%9}, {%0,%1,%2,%3};\n"
        : "+f"(c[0]), "+f"(c[1]), "+f"(c[2]), "+f"(c[3])
        : "r"(a[0]), "r"(a[1]), "r"(a[2]), "r"(a[3]), "r"(b0), "r"(b1));
}

// ============================================================================
// GEMM core (round-5, measured-best): 128x128 CTA tile, BK=64, 3-stage
// cp.async pipeline.
//   BNN=false: TN — A[M,K], B[N,K] both K-major (C = A * B^T)
//   BNN=true : NN — A[M,K] K-major, B[K,N] N-major (C = A * B)
//   NSPLIT=3 : products Ah*Bh + Ah*Bl + Al*Bh ; NSPLIT=1 : Ah*Bh
//   EPI: 0 = fp32 store; 1 = bias + hi/lo half split store; 2 = bias + half
// ============================================================================
template<int KVAL, int NSPLIT, bool BNN, int EPI>
__device__ __forceinline__ void gemm_main(
    const __half* __restrict__ Ah, const __half* __restrict__ Al,
    const __half* __restrict__ Bh, const __half* __restrict__ Bl,
    int lda, int ldb,
    float* __restrict__ Cf, __half* __restrict__ Ch, __half* __restrict__ Cl,
    const float* __restrict__ bias, int ldc)
{
    constexpr int NC = KVAL / 64;
    constexpr int T  = NSPLIT * NC;
    constexpr int STAGES = 3;
    constexpr uint32_t STAGE = 32768u;

    extern __shared__ __align__(16) char smem[];
    const uint32_t sbase = smem_u32(smem);

    const int tid  = threadIdx.x;
    const int lane = tid & 31;
    const int warp = tid >> 5;
    const int wm = warp & 3;
    const int wn = warp >> 2;
    const int tm0 = blockIdx.y * 128;
    const int tn0 = blockIdx.x * 128;

    uint32_t dA[4], gA[4], dB[4], gB[4];
    #pragma unroll
    for (int i = 0; i < 4; ++i) {
        const int slot = tid + i * 256;
        { const int r = slot >> 3, c = slot & 7;
          dA[i] = (uint32_t)(r * 128 + ((c ^ (r & 7)) << 4));
          gA[i] = (uint32_t)((tm0 + r) * lda + c * 8); }
        if (!BNN) {
            const int r = slot >> 3, c = slot & 7;
            dB[i] = (uint32_t)(r * 128 + ((c ^ (r & 7)) << 4));
            gB[i] = (uint32_t)((tn0 + r) * ldb + c * 8);
        } else {
            const int r = slot >> 4, c = slot & 15;
            dB[i] = (uint32_t)(r * 256 + ((c ^ (r & 7)) << 4));
            gB[i] = (uint32_t)(r * ldb + tn0 + c * 8);
        }
    }

    const __half* const Alist[3] = {Ah, Ah, Al};
    const __half* const Blist[3] = {Bh, Bl, Bh};

    const uint32_t kcoA = (lane >> 4) & 1;
    uint32_t aoff[2], asw[2];
    {
        const int roff = (lane & 7) + (((lane >> 3) & 1) << 3);
        #pragma unroll
        for (int mi = 0; mi < 2; ++mi) {
            const int r = wm * 32 + mi * 16 + roff;
            aoff[mi] = (uint32_t)(r * 128);
            asw[mi]  = (uint32_t)(r & 7);
        }
    }
    const uint32_t kcoB = (lane >> 3) & 1;
    uint32_t boff[4], bsw[4];
    uint32_t bco[4], bkoff = 0;
    if (!BNN) {
        const int noff = (lane & 7) + (((lane >> 4) & 1) << 3);
        #pragma unroll
        for (int p = 0; p < 4; ++p) {
            const int r = wn * 64 + p * 16 + noff;
            boff[p] = (uint32_t)(r * 128);
            bsw[p]  = (uint32_t)(r & 7);
        }
    } else {
        const int koff = (lane & 7) + (((lane >> 3) & 1) << 3);
        bkoff = (uint32_t)(koff * 256);
        const int ncsel = (lane >> 4) & 1;
        #pragma unroll
        for (int p = 0; p < 4; ++p) {
            const int ncb = wn * 8 + p * 2 + ncsel;
            bco[p] = (uint32_t)((ncb ^ (lane & 7)) << 4);
        }
    }

    float acc[2][8][4];
    #pragma unroll
    for (int mi = 0; mi < 2; ++mi)
        #pragma unroll
        for (int ni = 0; ni < 8; ++ni)
            #pragma unroll
            for (int j = 0; j < 4; ++j) acc[mi][ni][j] = 0.f;

    auto issue = [&](int t) {
        int comp, kc;
        if (NSPLIT == 1) { comp = 0; kc = t; }
        else             { comp = t / NC; kc = t - comp * NC; }
        const int k0 = kc * 64;
        const __half* Ap = Alist[comp];
        const __half* Bp = Blist[comp];
        const uint32_t s = sbase + (uint32_t)(t % STAGES) * STAGE;
        #pragma unroll
        for (int i = 0; i < 4; ++i) {
            cpa16(s + dA[i], Ap + gA[i] + k0);
            if (!BNN) cpa16(s + 16384u + dB[i], Bp + gB[i] + k0);
            else      cpa16(s + 16384u + dB[i], Bp + gB[i] + (size_t)k0 * ldb);
        }
    };

    #pragma unroll
    for (int s = 0; s < STAGES - 1; ++s) {
        if (s < T) issue(s);
        asm volatile("cp.async.commit_group;");
    }

    for (int t = 0; t < T; ++t) {
        asm volatile("cp.async.wait_group 1;");
        __syncthreads();
        if (t + STAGES - 1 < T) issue(t + STAGES - 1);
        asm volatile("cp.async.commit_group;");

        const uint32_t sA = sbase + (uint32_t)(t % STAGES) * STAGE;
        const uint32_t sB = sA + 16384u;
        #pragma unroll
        for (int kk = 0; kk < 4; ++kk) {
            uint32_t a[2][4];
            #pragma unroll
            for (int mi = 0; mi < 2; ++mi)
                ldsm4(a[mi][0], a[mi][1], a[mi][2], a[mi][3],
                      sA + aoff[mi] + ((((uint32_t)(2 * kk) + kcoA) ^ asw[mi]) << 4));
            uint32_t b[4][4];
            #pragma unroll
            for (int p = 0; p < 4; ++p) {
                if (!BNN)
                    ldsm4(b[p][0], b[p][1], b[p][2], b[p][3],
                          sB + boff[p] + ((((uint32_t)(2 * kk) + kcoB) ^ bsw[p]) << 4));
                else
                    ldsm4t(b[p][0], b[p][1], b[p][2], b[p][3],
                           sB + (uint32_t)kk * 4096u + bkoff + bco[p]);
            }
            #pragma unroll
            for (int mi = 0; mi < 2; ++mi)
                #pragma unroll
                for (int p = 0; p < 4; ++p) {
                    mma16816(acc[mi][2 * p],     a[mi], b[p][0], b[p][1]);
                    mma16816(acc[mi][2 * p + 1], a[mi], b[p][2], b[p][3]);
                }
        }
    }

    const int gid = lane >> 2, qid = lane & 3;
    #pragma unroll
    for (int mi = 0; mi < 2; ++mi) {
        #pragma unroll
        for (int ni = 0; ni < 8; ++ni) {
            const int r = tm0 + wm * 32 + mi * 16 + gid;
            const int c = tn0 + wn * 64 + ni * 8 + qid * 2;
            float v0 = acc[mi][ni][0], v1 = acc[mi][ni][1];
            float v2 = acc[mi][ni][2], v3 = acc[mi][ni][3];
            if (EPI == 1 || EPI == 2) {
                const float2 bb = *reinterpret_cast<const float2*>(bias + c);
                v0 += bb.x; v1 += bb.y; v2 += bb.x; v3 += bb.y;
            }
            if (EPI == 0) {
                *reinterpret_cast<float2*>(Cf + (size_t)r * ldc + c) =
                    make_float2(v0, v1);
                *reinterpret_cast<float2*>(Cf + (size_t)(r + 8) * ldc + c) =
                    make_float2(v2, v3);
            } else if (EPI == 2) {
                *reinterpret_cast<__half2*>(Ch + (size_t)r * ldc + c) =
                    __halves2half2(__float2half_rn(v0), __float2half_rn(v1));
                *reinterpret_cast<__half2*>(Ch + (size_t)(r + 8) * ldc + c) =
                    __halves2half2(__float2half_rn(v2), __float2half_rn(v3));
            } else {
                const __half h0 = __float2half_rn(v0), h1 = __float2half_rn(v1);
                const __half h2 = __float2half_rn(v2), h3 = __float2half_rn(v3);
                *reinterpret_cast<__half2*>(Ch + (size_t)r * ldc + c) =
                    __halves2half2(h0, h1);
                *reinterpret_cast<__half2*>(Ch + (size_t)(r + 8) * ldc + c) =
                    __halves2half2(h2, h3);
                *reinterpret_cast<__half2*>(Cl + (size_t)r * ldc + c) =
                    __halves2half2(__float2half_rn(v0 - __half2float(h0)),
                                   __float2half_rn(v1 - __half2float(h1)));
                *reinterpret_cast<__half2*>(Cl + (size_t)(r + 8) * ldc + c) =
                    __halves2half2(__float2half_rn(v2 - __half2float(h2)),
                                   __float2half_rn(v3 - __half2float(h3)));
            }
        }
    }
}

// ----------------------------------------------------------------------------
// prep kernels
// ----------------------------------------------------------------------------
__device__ __forceinline__ void split4(const float4 v, __half2* dh, __half2* dl) {
    const __half h0 = __float2half_rn(v.x), h1 = __float2half_rn(v.y);
    const __half h2 = __float2half_rn(v.z), h3 = __float2half_rn(v.w);
    dh[0] = __halves2half2(h0, h1);
    dh[1] = __halves2half2(h2, h3);
    dl[0] = __halves2half2(__float2half_rn(v.x - __half2float(h0)),
                           __float2half_rn(v.y - __half2float(h1)));
    dl[1] = __halves2half2(__float2half_rn(v.z - __half2float(h2)),
                           __float2half_rn(v.w - __half2float(h3)));
}

__global__ __launch_bounds__(256)
void split_x_kernel(const float* __restrict__ src)
{
    const int i = blockIdx.x * blockDim.x + threadIdx.x;
    const float4 v = reinterpret_cast<const float4*>(src)[i];
    split4(v, reinterpret_cast<__half2*>(g_xh) + 2 * i,
              reinterpret_cast<__half2*>(g_xl) + 2 * i);
}

__global__ __launch_bounds__(256)
void wk_split_kernel(const float* __restrict__ Wk)
{
    const int i = blockIdx.x * blockDim.x + threadIdx.x;
    const float4 v = reinterpret_cast<const float4*>(Wk)[i];
    split4(v, reinterpret_cast<__half2*>(g_wk_h) + 2 * i,
              reinterpret_cast<__half2*>(g_wk_l) + 2 * i);
}

__global__ __launch_bounds__(256)
void wv_conv_kernel(const float* __restrict__ Wv)
{
    const int i = blockIdx.x * blockDim.x + threadIdx.x;
    const float4 v = reinterpret_cast<const float4*>(Wv)[i];
    reinterpret_cast<__half2*>(g_wv_h)[2 * i] =
        __halves2half2(__float2half_rn(v.x), __float2half_rn(v.y));
    reinterpret_cast<__half2*>(g_wv_h)[2 * i + 1] =
        __halves2half2(__float2half_rn(v.z), __float2half_rn(v.w));
}

// WqT split: g_wqt[a*H+d] = split(Wq[d*H+a])
__global__ __launch_bounds__(256)
void wq_transpose_kernel(const float* __restrict__ Wq)
{
    __shared__ float s[32][33];
    const int a0 = blockIdx.x * 32, d0 = blockIdx.y * 32;
    const int tx = threadIdx.x & 31, ty = threadIdx.x >> 5;   // 32 x 8
    #pragma unroll
    for (int i = 0; i < 4; ++i) {
        const int d = d0 + ty + 8 * i;
        s[ty + 8 * i][tx] = Wq[(size_t)d * HID + a0 + tx];
    }
    __syncthreads();
    #pragma unroll
    for (int i = 0; i < 4; ++i) {
        const int a = a0 + ty + 8 * i;
        const float v = s[tx][ty + 8 * i];
        const __half h = __float2half_rn(v);
        g_wqt_h[(size_t)a * HID + d0 + tx] = h;
        g_wqt_l[(size_t)a * HID + d0 + tx] =
            __float2half_rn(v - __half2float(h));
    }
}

// t2 = Wk^T bq  (t2[a] = sum_d Wk[d,a]*bq[d]); coalesced over a
__global__ __launch_bounds__(256)
void t2_kernel(const float* __restrict__ Wk, const float* __restrict__ bq)
{
    const int a = blockIdx.x * 256 + threadIdx.x;
    float acc = 0.f;
    for (int d = 0; d < HID; ++d)
        acc += Wk[(size_t)d * HID + a] * bq[d];
    g_t2[a] = acc;
}

// w[i] = x_i . t2   (one warp per row)
__global__ __launch_bounds__(128)
void w_kernel(const float* __restrict__ x)
{
    const int warp = threadIdx.x >> 5, lane = threadIdx.x & 31;
    const int row = blockIdx.x * 4 + warp;
    const float* xr = x + (size_t)row * HID;
    float s = 0.f;
    for (int a = lane; a < HID; a += 32) s += xr[a] * g_t2[a];
    #pragma unroll
    for (int off = 16; off; off >>= 1)
        s += __shfl_xor_sync(0xffffffffu, s, off);
    if (lane == 0) g_w[row] = s;
}

// ----------------------------------------------------------------------------
// GEMM kernels
// ----------------------------------------------------------------------------
__global__ __launch_bounds__(256, 2)
void m_kernel()   // M = Wq^T Wk  (NN split3) -> split store
{
    gemm_main<1024, 3, true, 1>(g_wqt_h, g_wqt_l, g_wk_h, g_wk_l, HID, HID,
                                nullptr, g_mh, g_ml, g_zero, HID);
}

__global__ __launch_bounds__(256, 2)
void y_kernel()   // y = x M  (NN split3) -> split store
{
    gemm_main<1024, 3, true, 1>(g_xh, g_xl, g_mh, g_ml, HID, HID,
                                nullptr, g_yh, g_yl, g_zero, HID);
}

__global__ __launch_bounds__(256, 2)
void v_kernel(const float* __restrict__ bv)   // v = x Wv^T + bv (TN 1x)
{
    gemm_main<1024, 1, false, 2>(g_xh, nullptr, g_wv_h, nullptr, HID, HID,
                                 nullptr, g_vh, nullptr, bv, HID);
}

__global__ __launch_bounds__(256, 2)
void scores_kernel()   // s = y x^T (TN split3) -> fp32
{
    const size_t bo = (size_t)blockIdx.z * SEQ * HID;
    gemm_main<1024, 3, false, 0>(g_yh + bo, g_yl + bo, g_xh + bo, g_xl + bo,
                                 HID, HID,
                                 g_s + (size_t)blockIdx.z * SEQ * SEQ,
                                 nullptr, nullptr, nullptr, SEQ);
}

__global__ __launch_bounds__(256, 2)
void pv_kernel(float* __restrict__ out)   // out = P v (NN 1x)
{
    const size_t so = (size_t)blockIdx.z * SEQ * SEQ;
    const size_t vo = (size_t)blockIdx.z * SEQ * HID;
    gemm_main<2048, 1, true, 0>(g_p + so, nullptr, g_vh + vo, nullptr,
                                SEQ, HID, out + vo, nullptr, nullptr,
                                nullptr, HID);
}

// ----------------------------------------------------------------------------
// softmax over logits l_ij = s_ij + w_j  (threshold-gated exp, thr = max-17)
// ----------------------------------------------------------------------------
__global__ __launch_bounds__(256)
void softmax_kernel()
{
    const float* src = g_s + (size_t)blockIdx.x * SEQ;
    __half* dst = g_p + (size_t)blockIdx.x * SEQ;
    const int t = threadIdx.x;
    const int wbase = (blockIdx.x >> 11) << 11;   // batch * SEQ
    __shared__ float red[8];

    const float4* p4 = reinterpret_cast<const float4*>(src);
    float4 u0 = p4[t];
    float4 u1 = p4[t + 256];
    const float4 w0 = *reinterpret_cast<const float4*>(g_w + wbase + 4 * t);
    const float4 w1 = *reinterpret_cast<const float4*>(g_w + wbase + 1024 + 4 * t);
    u0.x += w0.x; u0.y += w0.y; u0.z += w0.z; u0.w += w0.w;
    u1.x += w1.x; u1.y += w1.y; u1.z += w1.z; u1.w += w1.w;

    const float m0 = fmaxf(fmaxf(u0.x, u0.y), fmaxf(u0.z, u0.w));
    const float m1 = fmaxf(fmaxf(u1.x, u1.y), fmaxf(u1.z, u1.w));
    float m = fmaxf(m0, m1);
    #pragma unroll
    for (int off = 16; off; off >>= 1)
        m = fmaxf(m, __shfl_xor_sync(0xffffffffu, m, off));
    if ((t & 31) == 0) red[t >> 5] = m;
    __syncthreads();
    if (t < 8) {
        float mm = red[t];
        #pragma unroll
        for (int off = 4; off; off >>= 1)
            mm = fmaxf(mm, __shfl_xor_sync(0xffu, mm, off));
        if (t == 0) red[0] = mm;
    }
    __syncthreads();
    m = red[0];
    __syncthreads();

    const float thr = m - 17.0f;

    if (__any_sync(0xffffffffu, m0 > thr)) {
        u0.x = (u0.x > thr) ? __expf(u0.x - m) : 0.f;
        u0.y = (u0.y > thr) ? __expf(u0.y - m) : 0.f;
        u0.z = (u0.z > thr) ? __expf(u0.z - m) : 0.f;
        u0.w = (u0.w > thr) ? __expf(u0.w - m) : 0.f;
    } else {
        u0.x = u0.y = u0.z = u0.w = 0.f;
    }
    if (__any_sync(0xffffffffu, m1 > thr)) {
        u1.x = (u1.x > thr) ? __expf(u1.x - m) : 0.f;
        u1.y = (u1.y > thr) ? __expf(u1.y - m) : 0.f;
        u1.z = (u1.z > thr) ? __expf(u1.z - m) : 0.f;
        u1.w = (u1.w > thr) ? __expf(u1.w - m) : 0.f;
    } else {
        u1.x = u1.y = u1.z = u1.w = 0.f;
    }

    float s = (u0.x + u0.y + u0.z + u0.w) + (u1.x + u1.y + u1.z + u1.w);
    #pragma unroll
    for (int off = 16; off; off >>= 1)
        s += __shfl_xor_sync(0xffffffffu, s, off);
    if ((t & 31) == 0) red[t >> 5] = s;
    __syncthreads();
    if (t < 8) {
        float ss = red[t];
        #pragma unroll
        for (int off = 4; off; off >>= 1)
            ss += __shfl_xor_sync(0xffu, ss, off);
        if (t == 0) red[0] = ss;
    }
    __syncthreads();
    const float inv = 1.0f / red[0];

    __half2* d2 = reinterpret_cast<__half2*>(dst);
    d2[2 * t]           = __halves2half2(__float2half_rn(u0.x * inv),
                                         __float2half_rn(u0.y * inv));
    d2[2 * t + 1]       = __halves2half2(__float2half_rn(u0.z * inv),
                                         __float2half_rn(u0.w * inv));
    d2[512 + 2 * t]     = __halves2half2(__float2half_rn(u1.x * inv),
                                         __float2half_rn(u1.y * inv));
    d2[512 + 2 * t + 1] = __halves2half2(__float2half_rn(u1.z * inv),
                                         __float2half_rn(u1.w * inv));
}

// ----------------------------------------------------------------------------
// launch
// ----------------------------------------------------------------------------
#define GEMM_SMEM 98304

extern "C" void kernel_launch(void* const* d_in, const int* in_sizes, int n_in,
                              void* d_out, int out_size)
{
    (void)in_sizes; (void)n_in; (void)out_size;
    const float* x  = (const float*)d_in[0];
    const float* Wq = (const float*)d_in[1];
    const float* bq = (const float*)d_in[2];
    const float* Wk = (const float*)d_in[3];
    const float* Wv = (const float*)d_in[5];
    const float* bv = (const float*)d_in[6];
    float* out = (float*)d_out;

    cudaFuncSetAttribute(m_kernel,
        cudaFuncAttributeMaxDynamicSharedMemorySize, GEMM_SMEM);
    cudaFuncSetAttribute(y_kernel,
        cudaFuncAttributeMaxDynamicSharedMemorySize, GEMM_SMEM);
    cudaFuncSetAttribute(v_kernel,
        cudaFuncAttributeMaxDynamicSharedMemorySize, GEMM_SMEM);
    cudaFuncSetAttribute(scores_kernel,
        cudaFuncAttributeMaxDynamicSharedMemorySize, GEMM_SMEM);
    cudaFuncSetAttribute(pv_kernel,
        cudaFuncAttributeMaxDynamicSharedMemorySize, GEMM_SMEM);

    // 0) prep: splits / transpose / rank-1 vectors
    split_x_kernel<<<MTOT * HID / 4 / 256, 256>>>(x);
    wq_transpose_kernel<<<dim3(HID / 32, HID / 32), 256>>>(Wq);
    wk_split_kernel<<<HID * HID / 4 / 256, 256>>>(Wk);
    wv_conv_kernel<<<HID * HID / 4 / 256, 256>>>(Wv);
    t2_kernel<<<HID / 256, 256>>>(Wk, bq);
    w_kernel<<<MTOT / 4, 128>>>(x);

    // 1) M = Wq^T Wk (split3)
    m_kernel<<<dim3(HID / 128, HID / 128), 256, GEMM_SMEM>>>();
    // 2) y = x M (split3), v = x Wv^T + bv (1x)
    y_kernel<<<dim3(HID / 128, MTOT / 128), 256, GEMM_SMEM>>>();
    v_kernel<<<dim3(HID / 128, MTOT / 128), 256, GEMM_SMEM>>>(bv);
    // 3) scores = y x^T (split3) -> fp32
    scores_kernel<<<dim3(SEQ / 128, SEQ / 128, BATCH), 256, GEMM_SMEM>>>();
    // 4) softmax(s + w_j) -> fp16 P
    softmax_kernel<<<BATCH * SEQ, 256>>>();
    // 5) out = P v (1x)
    pv_kernel<<<dim3(HID / 128, SEQ / 128, BATCH), 256, GEMM_SMEM>>>(out);
}

// round 10
// speedup vs baseline: 1.0828x; 1.0487x over previous
#include <cuda_runtime.h>
#include <cuda_fp16.h>
#include <cstdint>

// ============================================================================
// SelfAttention: out = softmax( (xWq^T+bq)(xWk^T+bk)^T ) (xWv^T+bv)
// B=4, S=2048, H=1024 (fp32 in/out)
// Algebraic reduction:  q_i.k_j = x_i (Wq^T Wk) x_j^T + rowconst + w_j
//   rowconst cancels in softmax; w_j = x_j.(Wk^T bq) added pre-exp (fp32).
// M = Wq^T Wk and v = x.Wv^T+bv computed in ONE merged launch (fills the
// 64-CTA occupancy hole m_kernel had); then y = x.M, scores = y.x^T,
// softmax(+w), out = P.v.
// All GEMMs: mma.sync m16n8k16 fp16, 3x hi/lo split where needed.
// ============================================================================

#define BATCH 4
#define SEQ   2048
#define HID   1024
#define MTOT  (BATCH*SEQ)          // 8192

// ---- scratch (device globals; allocation-free per harness rules) ----
__device__ __half g_xh[(size_t)MTOT * HID];
__device__ __half g_xl[(size_t)MTOT * HID];
__device__ __half g_wqt_h[(size_t)HID * HID];   // Wq^T split
__device__ __half g_wqt_l[(size_t)HID * HID];
__device__ __half g_wk_h[(size_t)HID * HID];    // Wk split (row-major)
__device__ __half g_wk_l[(size_t)HID * HID];
__device__ __half g_wv_h[(size_t)HID * HID];    // Wv fp16
__device__ __half g_mh[(size_t)HID * HID];      // M = Wq^T Wk split
__device__ __half g_ml[(size_t)HID * HID];
__device__ __half g_yh[(size_t)MTOT * HID];     // y = x.M split
__device__ __half g_yl[(size_t)MTOT * HID];
__device__ __half g_vh[(size_t)MTOT * HID];
__device__ float  g_s [(size_t)BATCH * SEQ * SEQ];
__device__ __half g_p [(size_t)BATCH * SEQ * SEQ];
__device__ float  g_w [MTOT];                   // w_j per (batch,key)
__device__ float  g_t2[HID];                    // Wk^T bq
__device__ float  g_zero[HID];                  // static zero (bias for M,y)

// ----------------------------------------------------------------------------
// helpers
// ----------------------------------------------------------------------------
__device__ __forceinline__ uint32_t smem_u32(const void* p) {
    uint32_t a;
    asm("{ .reg .u64 t; cvta.to.shared.u64 t, %1; cvt.u32.u64 %0, t; }"
        : "=r"(a) : "l"(p));
    return a;
}

__device__ __forceinline__ void cpa16(uint32_t dst, const void* src) {
    asm volatile("cp.async.cg.shared.global [%0], [%1], 16;"
                 :: "r"(dst), "l"(src));
}

__device__ __forceinline__ void ldsm4(uint32_t& r0, uint32_t& r1,
                                      uint32_t& r2, uint32_t& r3, uint32_t a) {
    asm volatile("ldmatrix.sync.aligned.m8n8.x4.shared.b16 {%0,%1,%2,%3}, [%4];"
                 : "=r"(r0), "=r"(r1), "=r"(r2), "=r"(r3) : "r"(a));
}
__device__ __forceinline__ void ldsm4t(uint32_t& r0, uint32_t& r1,
                                       uint32_t& r2, uint32_t& r3, uint32_t a) {
    asm volatile("ldmatrix.sync.aligned.m8n8.x4.trans.shared.b16 {%0,%1,%2,%3}, [%4];"
                 : "=r"(r0), "=r"(r1), "=r"(r2), "=r"(r3) : "r"(a));
}

__device__ __forceinline__ void mma16816(float c[4], const uint32_t a[4],
                                         uint32_t b0, uint32_t b1) {
    asm volatile(
        "mma.sync.aligned.m16n8k16.row.col.f32.f16.f16.f32 "
        "{%0,%1,%2,%3}, {%4,%5,%6,%7}, {%8,%9}, {%0,%1,%2,%3};\n"
        : "+f"(c[0]), "+f"(c[1]), "+f"(c[2]), "+f"(c[3])
        : "r"(a[0]), "r"(a[1]), "r"(a[2]), "r"(a[3]), "r"(b0), "r"(b1));
}

// ============================================================================
// GEMM core: 128x128 CTA tile at (tm0, tn0), BK=64, 3-stage cp.async pipeline.
//   BNN=false: TN — A[M,K], B[N,K] both K-major (C = A * B^T)
//   BNN=true : NN — A[M,K] K-major, B[K,N] N-major (C = A * B)
//   NSPLIT=3 : products Ah*Bh + Ah*Bl + Al*Bh ; NSPLIT=1 : Ah*Bh
//   EPI: 0 = fp32 store; 1 = bias + hi/lo half split store; 2 = bias + half
// ============================================================================
template<int KVAL, int NSPLIT, bool BNN, int EPI>
__device__ __forceinline__ void gemm_main(
    const __half* __restrict__ Ah, const __half* __restrict__ Al,
    const __half* __restrict__ Bh, const __half* __restrict__ Bl,
    int lda, int ldb,
    float* __restrict__ Cf, __half* __restrict__ Ch, __half* __restrict__ Cl,
    const float* __restrict__ bias, int ldc,
    int tm0, int tn0)
{
    constexpr int NC = KVAL / 64;
    constexpr int T  = NSPLIT * NC;
    constexpr int STAGES = 3;
    constexpr uint32_t STAGE = 32768u;

    extern __shared__ __align__(16) char smem[];
    const uint32_t sbase = smem_u32(smem);

    const int tid  = threadIdx.x;
    const int lane = tid & 31;
    const int warp = tid >> 5;
    const int wm = warp & 3;
    const int wn = warp >> 2;

    uint32_t dA[4], gA[4], dB[4], gB[4];
    #pragma unroll
    for (int i = 0; i < 4; ++i) {
        const int slot = tid + i * 256;
        { const int r = slot >> 3, c = slot & 7;
          dA[i] = (uint32_t)(r * 128 + ((c ^ (r & 7)) << 4));
          gA[i] = (uint32_t)((tm0 + r) * lda + c * 8); }
        if (!BNN) {
            const int r = slot >> 3, c = slot & 7;
            dB[i] = (uint32_t)(r * 128 + ((c ^ (r & 7)) << 4));
            gB[i] = (uint32_t)((tn0 + r) * ldb + c * 8);
        } else {
            const int r = slot >> 4, c = slot & 15;
            dB[i] = (uint32_t)(r * 256 + ((c ^ (r & 7)) << 4));
            gB[i] = (uint32_t)(r * ldb + tn0 + c * 8);
        }
    }

    const __half* const Alist[3] = {Ah, Ah, Al};
    const __half* const Blist[3] = {Bh, Bl, Bh};

    const uint32_t kcoA = (lane >> 4) & 1;
    uint32_t aoff[2], asw[2];
    {
        const int roff = (lane & 7) + (((lane >> 3) & 1) << 3);
        #pragma unroll
        for (int mi = 0; mi < 2; ++mi) {
            const int r = wm * 32 + mi * 16 + roff;
            aoff[mi] = (uint32_t)(r * 128);
            asw[mi]  = (uint32_t)(r & 7);
        }
    }
    const uint32_t kcoB = (lane >> 3) & 1;
    uint32_t boff[4], bsw[4];
    uint32_t bco[4], bkoff = 0;
    if (!BNN) {
        const int noff = (lane & 7) + (((lane >> 4) & 1) << 3);
        #pragma unroll
        for (int p = 0; p < 4; ++p) {
            const int r = wn * 64 + p * 16 + noff;
            boff[p] = (uint32_t)(r * 128);
            bsw[p]  = (uint32_t)(r & 7);
        }
    } else {
        const int koff = (lane & 7) + (((lane >> 3) & 1) << 3);
        bkoff = (uint32_t)(koff * 256);
        const int ncsel = (lane >> 4) & 1;
        #pragma unroll
        for (int p = 0; p < 4; ++p) {
            const int ncb = wn * 8 + p * 2 + ncsel;
            bco[p] = (uint32_t)((ncb ^ (lane & 7)) << 4);
        }
    }

    float acc[2][8][4];
    #pragma unroll
    for (int mi = 0; mi < 2; ++mi)
        #pragma unroll
        for (int ni = 0; ni < 8; ++ni)
            #pragma unroll
            for (int j = 0; j < 4; ++j) acc[mi][ni][j] = 0.f;

    auto issue = [&](int t) {
        int comp, kc;
        if (NSPLIT == 1) { comp = 0; kc = t; }
        else             { comp = t / NC; kc = t - comp * NC; }
        const int k0 = kc * 64;
        const __half* Ap = Alist[comp];
        const __half* Bp = Blist[comp];
        const uint32_t s = sbase + (uint32_t)(t % STAGES) * STAGE;
        #pragma unroll
        for (int i = 0; i < 4; ++i) {
            cpa16(s + dA[i], Ap + gA[i] + k0);
            if (!BNN) cpa16(s + 16384u + dB[i], Bp + gB[i] + k0);
            else      cpa16(s + 16384u + dB[i], Bp + gB[i] + (size_t)k0 * ldb);
        }
    };

    #pragma unroll
    for (int s = 0; s < STAGES - 1; ++s) {
        if (s < T) issue(s);
        asm volatile("cp.async.commit_group;");
    }

    for (int t = 0; t < T; ++t) {
        asm volatile("cp.async.wait_group 1;");
        __syncthreads();
        if (t + STAGES - 1 < T) issue(t + STAGES - 1);
        asm volatile("cp.async.commit_group;");

        const uint32_t sA = sbase + (uint32_t)(t % STAGES) * STAGE;
        const uint32_t sB = sA + 16384u;
        #pragma unroll
        for (int kk = 0; kk < 4; ++kk) {
            uint32_t a[2][4];
            #pragma unroll
            for (int mi = 0; mi < 2; ++mi)
                ldsm4(a[mi][0], a[mi][1], a[mi][2], a[mi][3],
                      sA + aoff[mi] + ((((uint32_t)(2 * kk) + kcoA) ^ asw[mi]) << 4));
            uint32_t b[4][4];
            #pragma unroll
            for (int p = 0; p < 4; ++p) {
                if (!BNN)
                    ldsm4(b[p][0], b[p][1], b[p][2], b[p][3],
                          sB + boff[p] + ((((uint32_t)(2 * kk) + kcoB) ^ bsw[p]) << 4));
                else
                    ldsm4t(b[p][0], b[p][1], b[p][2], b[p][3],
                           sB + (uint32_t)kk * 4096u + bkoff + bco[p]);
            }
            #pragma unroll
            for (int mi = 0; mi < 2; ++mi)
                #pragma unroll
                for (int p = 0; p < 4; ++p) {
                    mma16816(acc[mi][2 * p],     a[mi], b[p][0], b[p][1]);
                    mma16816(acc[mi][2 * p + 1], a[mi], b[p][2], b[p][3]);
                }
        }
    }

    const int gid = lane >> 2, qid = lane & 3;
    #pragma unroll
    for (int mi = 0; mi < 2; ++mi) {
        #pragma unroll
        for (int ni = 0; ni < 8; ++ni) {
            const int r = tm0 + wm * 32 + mi * 16 + gid;
            const int c = tn0 + wn * 64 + ni * 8 + qid * 2;
            float v0 = acc[mi][ni][0], v1 = acc[mi][ni][1];
            float v2 = acc[mi][ni][2], v3 = acc[mi][ni][3];
            if (EPI == 1 || EPI == 2) {
                const float2 bb = *reinterpret_cast<const float2*>(bias + c);
                v0 += bb.x; v1 += bb.y; v2 += bb.x; v3 += bb.y;
            }
            if (EPI == 0) {
                *reinterpret_cast<float2*>(Cf + (size_t)r * ldc + c) =
                    make_float2(v0, v1);
                *reinterpret_cast<float2*>(Cf + (size_t)(r + 8) * ldc + c) =
                    make_float2(v2, v3);
            } else if (EPI == 2) {
                *reinterpret_cast<__half2*>(Ch + (size_t)r * ldc + c) =
                    __halves2half2(__float2half_rn(v0), __float2half_rn(v1));
                *reinterpret_cast<__half2*>(Ch + (size_t)(r + 8) * ldc + c) =
                    __halves2half2(__float2half_rn(v2), __float2half_rn(v3));
            } else {
                const __half h0 = __float2half_rn(v0), h1 = __float2half_rn(v1);
                const __half h2 = __float2half_rn(v2), h3 = __float2half_rn(v3);
                *reinterpret_cast<__half2*>(Ch + (size_t)r * ldc + c) =
                    __halves2half2(h0, h1);
                *reinterpret_cast<__half2*>(Ch + (size_t)(r + 8) * ldc + c) =
                    __halves2half2(h2, h3);
                *reinterpret_cast<__half2*>(Cl + (size_t)r * ldc + c) =
                    __halves2half2(__float2half_rn(v0 - __half2float(h0)),
                                   __float2half_rn(v1 - __half2float(h1)));
                *reinterpret_cast<__half2*>(Cl + (size_t)(r + 8) * ldc + c) =
                    __halves2half2(__float2half_rn(v2 - __half2float(h2)),
                                   __float2half_rn(v3 - __half2float(h3)));
            }
        }
    }
}

// ----------------------------------------------------------------------------
// prep kernels
// ----------------------------------------------------------------------------
__device__ __forceinline__ void split4(const float4 v, __half2* dh, __half2* dl) {
    const __half h0 = __float2half_rn(v.x), h1 = __float2half_rn(v.y);
    const __half h2 = __float2half_rn(v.z), h3 = __float2half_rn(v.w);
    dh[0] = __halves2half2(h0, h1);
    dh[1] = __halves2half2(h2, h3);
    dl[0] = __halves2half2(__float2half_rn(v.x - __half2float(h0)),
                           __float2half_rn(v.y - __half2float(h1)));
    dl[1] = __halves2half2(__float2half_rn(v.z - __half2float(h2)),
                           __float2half_rn(v.w - __half2float(h3)));
}

__global__ __launch_bounds__(256)
void split_x_kernel(const float* __restrict__ src)
{
    const int i = blockIdx.x * blockDim.x + threadIdx.x;
    const float4 v = reinterpret_cast<const float4*>(src)[i];
    split4(v, reinterpret_cast<__half2*>(g_xh) + 2 * i,
              reinterpret_cast<__half2*>(g_xl) + 2 * i);
}

__global__ __launch_bounds__(256)
void wk_split_kernel(const float* __restrict__ Wk)
{
    const int i = blockIdx.x * blockDim.x + threadIdx.x;
    const float4 v = reinterpret_cast<const float4*>(Wk)[i];
    split4(v, reinterpret_cast<__half2*>(g_wk_h) + 2 * i,
              reinterpret_cast<__half2*>(g_wk_l) + 2 * i);
}

__global__ __launch_bounds__(256)
void wv_conv_kernel(const float* __restrict__ Wv)
{
    const int i = blockIdx.x * blockDim.x + threadIdx.x;
    const float4 v = reinterpret_cast<const float4*>(Wv)[i];
    reinterpret_cast<__half2*>(g_wv_h)[2 * i] =
        __halves2half2(__float2half_rn(v.x), __float2half_rn(v.y));
    reinterpret_cast<__half2*>(g_wv_h)[2 * i + 1] =
        __halves2half2(__float2half_rn(v.z), __float2half_rn(v.w));
}

// WqT split: g_wqt[a*H+d] = split(Wq[d*H+a])
__global__ __launch_bounds__(256)
void wq_transpose_kernel(const float* __restrict__ Wq)
{
    __shared__ float s[32][33];
    const int a0 = blockIdx.x * 32, d0 = blockIdx.y * 32;
    const int tx = threadIdx.x & 31, ty = threadIdx.x >> 5;   // 32 x 8
    #pragma unroll
    for (int i = 0; i < 4; ++i) {
        const int d = d0 + ty + 8 * i;
        s[ty + 8 * i][tx] = Wq[(size_t)d * HID + a0 + tx];
    }
    __syncthreads();
    #pragma unroll
    for (int i = 0; i < 4; ++i) {
        const int a = a0 + ty + 8 * i;
        const float v = s[tx][ty + 8 * i];
        const __half h = __float2half_rn(v);
        g_wqt_h[(size_t)a * HID + d0 + tx] = h;
        g_wqt_l[(size_t)a * HID + d0 + tx] =
            __float2half_rn(v - __half2float(h));
    }
}

// t2 = Wk^T bq  (t2[a] = sum_d Wk[d,a]*bq[d]); coalesced over a
__global__ __launch_bounds__(256)
void t2_kernel(const float* __restrict__ Wk, const float* __restrict__ bq)
{
    const int a = blockIdx.x * 256 + threadIdx.x;
    float acc = 0.f;
    #pragma unroll 8
    for (int d = 0; d < HID; ++d)
        acc += Wk[(size_t)d * HID + a] * bq[d];
    g_t2[a] = acc;
}

// w[i] = x_i . t2   (one warp per row)
__global__ __launch_bounds__(128)
void w_kernel(const float* __restrict__ x)
{
    const int warp = threadIdx.x >> 5, lane = threadIdx.x & 31;
    const int row = blockIdx.x * 4 + warp;
    const float* xr = x + (size_t)row * HID;
    float s = 0.f;
    for (int a = lane; a < HID; a += 32) s += xr[a] * g_t2[a];
    #pragma unroll
    for (int off = 16; off; off >>= 1)
        s += __shfl_xor_sync(0xffffffffu, s, off);
    if (lane == 0) g_w[row] = s;
}

// ----------------------------------------------------------------------------
// GEMM kernels
// ----------------------------------------------------------------------------
// Merged M + V launch: grid (8, 72).  y<8 -> M tile, y>=8 -> V tile.
__global__ __launch_bounds__(256, 2)
void mv_kernel(const float* __restrict__ bv)
{
    if (blockIdx.y < 8)
        gemm_main<1024, 3, true, 1>(g_wqt_h, g_wqt_l, g_wk_h, g_wk_l, HID, HID,
                                    nullptr, g_mh, g_ml, g_zero, HID,
                                    blockIdx.y * 128, blockIdx.x * 128);
    else
        gemm_main<1024, 1, false, 2>(g_xh, nullptr, g_wv_h, nullptr, HID, HID,
                                     nullptr, g_vh, nullptr, bv, HID,
                                     (blockIdx.y - 8) * 128, blockIdx.x * 128);
}

__global__ __launch_bounds__(256, 2)
void y_kernel()   // y = x M  (NN split3) -> split store
{
    gemm_main<1024, 3, true, 1>(g_xh, g_xl, g_mh, g_ml, HID, HID,
                                nullptr, g_yh, g_yl, g_zero, HID,
                                blockIdx.y * 128, blockIdx.x * 128);
}

__global__ __launch_bounds__(256, 2)
void scores_kernel()   // s = y x^T (TN split3) -> fp32
{
    const size_t bo = (size_t)blockIdx.z * SEQ * HID;
    gemm_main<1024, 3, false, 0>(g_yh + bo, g_yl + bo, g_xh + bo, g_xl + bo,
                                 HID, HID,
                                 g_s + (size_t)blockIdx.z * SEQ * SEQ,
                                 nullptr, nullptr, nullptr, SEQ,
                                 blockIdx.y * 128, blockIdx.x * 128);
}

__global__ __launch_bounds__(256, 2)
void pv_kernel(float* __restrict__ out)   // out = P v (NN 1x)
{
    const size_t so = (size_t)blockIdx.z * SEQ * SEQ;
    const size_t vo = (size_t)blockIdx.z * SEQ * HID;
    gemm_main<2048, 1, true, 0>(g_p + so, nullptr, g_vh + vo, nullptr,
                                SEQ, HID, out + vo, nullptr, nullptr,
                                nullptr, HID,
                                blockIdx.y * 128, blockIdx.x * 128);
}

// ----------------------------------------------------------------------------
// softmax over logits l_ij = s_ij + w_j  (threshold-gated exp, thr = max-17)
// ----------------------------------------------------------------------------
__global__ __launch_bounds__(256)
void softmax_kernel()
{
    const float* src = g_s + (size_t)blockIdx.x * SEQ;
    __half* dst = g_p + (size_t)blockIdx.x * SEQ;
    const int t = threadIdx.x;
    const int wbase = (blockIdx.x >> 11) << 11;   // batch * SEQ
    __shared__ float red[8];

    const float4* p4 = reinterpret_cast<const float4*>(src);
    float4 u0 = p4[t];
    float4 u1 = p4[t + 256];
    const float4 w0 = *reinterpret_cast<const float4*>(g_w + wbase + 4 * t);
    const float4 w1 = *reinterpret_cast<const float4*>(g_w + wbase + 1024 + 4 * t);
    u0.x += w0.x; u0.y += w0.y; u0.z += w0.z; u0.w += w0.w;
    u1.x += w1.x; u1.y += w1.y; u1.z += w1.z; u1.w += w1.w;

    const float m0 = fmaxf(fmaxf(u0.x, u0.y), fmaxf(u0.z, u0.w));
    const float m1 = fmaxf(fmaxf(u1.x, u1.y), fmaxf(u1.z, u1.w));
    float m = fmaxf(m0, m1);
    #pragma unroll
    for (int off = 16; off; off >>= 1)
        m = fmaxf(m, __shfl_xor_sync(0xffffffffu, m, off));
    if ((t & 31) == 0) red[t >> 5] = m;
    __syncthreads();
    if (t < 8) {
        float mm = red[t];
        #pragma unroll
        for (int off = 4; off; off >>= 1)
            mm = fmaxf(mm, __shfl_xor_sync(0xffu, mm, off));
        if (t == 0) red[0] = mm;
    }
    __syncthreads();
    m = red[0];
    __syncthreads();

    const float thr = m - 17.0f;

    if (__any_sync(0xffffffffu, m0 > thr)) {
        u0.x = (u0.x > thr) ? __expf(u0.x - m) : 0.f;
        u0.y = (u0.y > thr) ? __expf(u0.y - m) : 0.f;
        u0.z = (u0.z > thr) ? __expf(u0.z - m) : 0.f;
        u0.w = (u0.w > thr) ? __expf(u0.w - m) : 0.f;
    } else {
        u0.x = u0.y = u0.z = u0.w = 0.f;
    }
    if (__any_sync(0xffffffffu, m1 > thr)) {
        u1.x = (u1.x > thr) ? __expf(u1.x - m) : 0.f;
        u1.y = (u1.y > thr) ? __expf(u1.y - m) : 0.f;
        u1.z = (u1.z > thr) ? __expf(u1.z - m) : 0.f;
        u1.w = (u1.w > thr) ? __expf(u1.w - m) : 0.f;
    } else {
        u1.x = u1.y = u1.z = u1.w = 0.f;
    }

    float s = (u0.x + u0.y + u0.z + u0.w) + (u1.x + u1.y + u1.z + u1.w);
    #pragma unroll
    for (int off = 16; off; off >>= 1)
        s += __shfl_xor_sync(0xffffffffu, s, off);
    if ((t & 31) == 0) red[t >> 5] = s;
    __syncthreads();
    if (t < 8) {
        float ss = red[t];
        #pragma unroll
        for (int off = 4; off; off >>= 1)
            ss += __shfl_xor_sync(0xffu, ss, off);
        if (t == 0) red[0] = ss;
    }
    __syncthreads();
    const float inv = 1.0f / red[0];

    __half2* d2 = reinterpret_cast<__half2*>(dst);
    d2[2 * t]           = __halves2half2(__float2half_rn(u0.x * inv),
                                         __float2half_rn(u0.y * inv));
    d2[2 * t + 1]       = __halves2half2(__float2half_rn(u0.z * inv),
                                         __float2half_rn(u0.w * inv));
    d2[512 + 2 * t]     = __halves2half2(__float2half_rn(u1.x * inv),
                                         __float2half_rn(u1.y * inv));
    d2[512 + 2 * t + 1] = __halves2half2(__float2half_rn(u1.z * inv),
                                         __float2half_rn(u1.w * inv));
}

// ----------------------------------------------------------------------------
// launch
// ----------------------------------------------------------------------------
#define GEMM_SMEM 98304

extern "C" void kernel_launch(void* const* d_in, const int* in_sizes, int n_in,
                              void* d_out, int out_size)
{
    (void)in_sizes; (void)n_in; (void)out_size;
    const float* x  = (const float*)d_in[0];
    const float* Wq = (const float*)d_in[1];
    const float* bq = (const float*)d_in[2];
    const float* Wk = (const float*)d_in[3];
    const float* Wv = (const float*)d_in[5];
    const float* bv = (const float*)d_in[6];
    float* out = (float*)d_out;

    cudaFuncSetAttribute(mv_kernel,
        cudaFuncAttributeMaxDynamicSharedMemorySize, GEMM_SMEM);
    cudaFuncSetAttribute(y_kernel,
        cudaFuncAttributeMaxDynamicSharedMemorySize, GEMM_SMEM);
    cudaFuncSetAttribute(scores_kernel,
        cudaFuncAttributeMaxDynamicSharedMemorySize, GEMM_SMEM);
    cudaFuncSetAttribute(pv_kernel,
        cudaFuncAttributeMaxDynamicSharedMemorySize, GEMM_SMEM);

    // 0) prep: splits / transpose / rank-1 vectors
    split_x_kernel<<<MTOT * HID / 4 / 256, 256>>>(x);
    wq_transpose_kernel<<<dim3(HID / 32, HID / 32), 256>>>(Wq);
    wk_split_kernel<<<HID * HID / 4 / 256, 256>>>(Wk);
    wv_conv_kernel<<<HID * HID / 4 / 256, 256>>>(Wv);
    t2_kernel<<<HID / 256, 256>>>(Wk, bq);
    w_kernel<<<MTOT / 4, 128>>>(x);

    // 1) merged: M = Wq^T Wk (split3, y<8) + v = x Wv^T + bv (1x, y>=8)
    mv_kernel<<<dim3(HID / 128, 8 + MTOT / 128), 256, GEMM_SMEM>>>(bv);
    // 2) y = x M (split3)
    y_kernel<<<dim3(HID / 128, MTOT / 128), 256, GEMM_SMEM>>>();
    // 3) scores = y x^T (split3) -> fp32
    scores_kernel<<<dim3(SEQ / 128, SEQ / 128, BATCH), 256, GEMM_SMEM>>>();
    // 4) softmax(s + w_j) -> fp16 P
    softmax_kernel<<<BATCH * SEQ, 256>>>();
    // 5) out = P v (1x)
    pv_kernel<<<dim3(HID / 128, SEQ / 128, BATCH), 256, GEMM_SMEM>>>(out);
}

// round 11
// speedup vs baseline: 1.2439x; 1.1488x over previous
#include <cuda_runtime.h>
#include <cuda_fp16.h>
#include <cstdint>

// ============================================================================
// SelfAttention: out = softmax( (xWq^T+bq)(xWk^T+bk)^T ) (xWv^T+bv)
// B=4, S=2048, H=1024 (fp32 in/out)
// Algebraic reduction:  q_i.k_j = x_i (Wq^T Wk) x_j^T + rowconst + w_j
//   rowconst cancels in softmax; w_j = x_j.(Wk^T bq) added pre-exp (fp32).
// M = Wq^T Wk and v = x.Wv^T+bv in ONE merged launch; y = x.M; scores = y.x^T.
// Softmax is threshold-gated (max-17): surviving probabilities (~2/row) are
// compacted deterministically and P.v is computed as a GATHER fused into the
// softmax kernel — the dense pv GEMM is eliminated.
// GEMMs: mma.sync m16n8k16 fp16, 3x hi/lo split where needed.
// ============================================================================

#define BATCH 4
#define SEQ   2048
#define HID   1024
#define MTOT  (BATCH*SEQ)          // 8192

// ---- scratch (device globals; allocation-free per harness rules) ----
__device__ __half g_xh[(size_t)MTOT * HID];
__device__ __half g_xl[(size_t)MTOT * HID];
__device__ __half g_wqt_h[(size_t)HID * HID];   // Wq^T split
__device__ __half g_wqt_l[(size_t)HID * HID];
__device__ __half g_wk_h[(size_t)HID * HID];    // Wk split (row-major)
__device__ __half g_wk_l[(size_t)HID * HID];
__device__ __half g_wv_h[(size_t)HID * HID];    // Wv fp16
__device__ __half g_mh[(size_t)HID * HID];      // M = Wq^T Wk split
__device__ __half g_ml[(size_t)HID * HID];
__device__ __half g_yh[(size_t)MTOT * HID];     // y = x.M split
__device__ __half g_yl[(size_t)MTOT * HID];
__device__ __half g_vh[(size_t)MTOT * HID];
__device__ float  g_s [(size_t)BATCH * SEQ * SEQ];
__device__ float  g_w [MTOT];                   // w_j per (batch,key)
__device__ float  g_t2[HID];                    // Wk^T bq
__device__ float  g_zero[HID];                  // static zero (bias for M,y)

// ----------------------------------------------------------------------------
// helpers
// ----------------------------------------------------------------------------
__device__ __forceinline__ uint32_t smem_u32(const void* p) {
    uint32_t a;
    asm("{ .reg .u64 t; cvta.to.shared.u64 t, %1; cvt.u32.u64 %0, t; }"
        : "=r"(a) : "l"(p));
    return a;
}

__device__ __forceinline__ void cpa16(uint32_t dst, const void* src) {
    asm volatile("cp.async.cg.shared.global [%0], [%1], 16;"
                 :: "r"(dst), "l"(src));
}

__device__ __forceinline__ void ldsm4(uint32_t& r0, uint32_t& r1,
                                      uint32_t& r2, uint32_t& r3, uint32_t a) {
    asm volatile("ldmatrix.sync.aligned.m8n8.x4.shared.b16 {%0,%1,%2,%3}, [%4];"
                 : "=r"(r0), "=r"(r1), "=r"(r2), "=r"(r3) : "r"(a));
}
__device__ __forceinline__ void ldsm4t(uint32_t& r0, uint32_t& r1,
                                       uint32_t& r2, uint32_t& r3, uint32_t a) {
    asm volatile("ldmatrix.sync.aligned.m8n8.x4.trans.shared.b16 {%0,%1,%2,%3}, [%4];"
                 : "=r"(r0), "=r"(r1), "=r"(r2), "=r"(r3) : "r"(a));
}

__device__ __forceinline__ void mma16816(float c[4], const uint32_t a[4],
                                         uint32_t b0, uint32_t b1) {
    asm volatile(
        "mma.sync.aligned.m16n8k16.row.col.f32.f16.f16.f32 "
        "{%0,%1,%2,%3}, {%4,%5,%6,%7}, {%8,%9}, {%0,%1,%2,%3};\n"
        : "+f"(c[0]), "+f"(c[1]), "+f"(c[2]), "+f"(c[3])
        : "r"(a[0]), "r"(a[1]), "r"(a[2]), "r"(a[3]), "r"(b0), "r"(b1));
}

// ============================================================================
// GEMM core: 128x128 CTA tile at (tm0, tn0), BK=64, 3-stage cp.async pipeline.
//   BNN=false: TN — A[M,K], B[N,K] both K-major (C = A * B^T)
//   BNN=true : NN — A[M,K] K-major, B[K,N] N-major (C = A * B)
//   NSPLIT=3 : products Ah*Bh + Ah*Bl + Al*Bh ; NSPLIT=1 : Ah*Bh
//   EPI: 0 = fp32 store; 1 = bias + hi/lo half split store; 2 = bias + half
// ============================================================================
template<int KVAL, int NSPLIT, bool BNN, int EPI>
__device__ __forceinline__ void gemm_main(
    const __half* __restrict__ Ah, const __half* __restrict__ Al,
    const __half* __restrict__ Bh, const __half* __restrict__ Bl,
    int lda, int ldb,
    float* __restrict__ Cf, __half* __restrict__ Ch, __half* __restrict__ Cl,
    const float* __restrict__ bias, int ldc,
    int tm0, int tn0)
{
    constexpr int NC = KVAL / 64;
    constexpr int T  = NSPLIT * NC;
    constexpr int STAGES = 3;
    constexpr uint32_t STAGE = 32768u;

    extern __shared__ __align__(16) char smem[];
    const uint32_t sbase = smem_u32(smem);

    const int tid  = threadIdx.x;
    const int lane = tid & 31;
    const int warp = tid >> 5;
    const int wm = warp & 3;
    const int wn = warp >> 2;

    uint32_t dA[4], gA[4], dB[4], gB[4];
    #pragma unroll
    for (int i = 0; i < 4; ++i) {
        const int slot = tid + i * 256;
        { const int r = slot >> 3, c = slot & 7;
          dA[i] = (uint32_t)(r * 128 + ((c ^ (r & 7)) << 4));
          gA[i] = (uint32_t)((tm0 + r) * lda + c * 8); }
        if (!BNN) {
            const int r = slot >> 3, c = slot & 7;
            dB[i] = (uint32_t)(r * 128 + ((c ^ (r & 7)) << 4));
            gB[i] = (uint32_t)((tn0 + r) * ldb + c * 8);
        } else {
            const int r = slot >> 4, c = slot & 15;
            dB[i] = (uint32_t)(r * 256 + ((c ^ (r & 7)) << 4));
            gB[i] = (uint32_t)(r * ldb + tn0 + c * 8);
        }
    }

    const __half* const Alist[3] = {Ah, Ah, Al};
    const __half* const Blist[3] = {Bh, Bl, Bh};

    const uint32_t kcoA = (lane >> 4) & 1;
    uint32_t aoff[2], asw[2];
    {
        const int roff = (lane & 7) + (((lane >> 3) & 1) << 3);
        #pragma unroll
        for (int mi = 0; mi < 2; ++mi) {
            const int r = wm * 32 + mi * 16 + roff;
            aoff[mi] = (uint32_t)(r * 128);
            asw[mi]  = (uint32_t)(r & 7);
        }
    }
    const uint32_t kcoB = (lane >> 3) & 1;
    uint32_t boff[4], bsw[4];
    uint32_t bco[4], bkoff = 0;
    if (!BNN) {
        const int noff = (lane & 7) + (((lane >> 4) & 1) << 3);
        #pragma unroll
        for (int p = 0; p < 4; ++p) {
            const int r = wn * 64 + p * 16 + noff;
            boff[p] = (uint32_t)(r * 128);
            bsw[p]  = (uint32_t)(r & 7);
        }
    } else {
        const int koff = (lane & 7) + (((lane >> 3) & 1) << 3);
        bkoff = (uint32_t)(koff * 256);
        const int ncsel = (lane >> 4) & 1;
        #pragma unroll
        for (int p = 0; p < 4; ++p) {
            const int ncb = wn * 8 + p * 2 + ncsel;
            bco[p] = (uint32_t)((ncb ^ (lane & 7)) << 4);
        }
    }

    float acc[2][8][4];
    #pragma unroll
    for (int mi = 0; mi < 2; ++mi)
        #pragma unroll
        for (int ni = 0; ni < 8; ++ni)
            #pragma unroll
            for (int j = 0; j < 4; ++j) acc[mi][ni][j] = 0.f;

    auto issue = [&](int t) {
        int comp, kc;
        if (NSPLIT == 1) { comp = 0; kc = t; }
        else             { comp = t / NC; kc = t - comp * NC; }
        const int k0 = kc * 64;
        const __half* Ap = Alist[comp];
        const __half* Bp = Blist[comp];
        const uint32_t s = sbase + (uint32_t)(t % STAGES) * STAGE;
        #pragma unroll
        for (int i = 0; i < 4; ++i) {
            cpa16(s + dA[i], Ap + gA[i] + k0);
            if (!BNN) cpa16(s + 16384u + dB[i], Bp + gB[i] + k0);
            else      cpa16(s + 16384u + dB[i], Bp + gB[i] + (size_t)k0 * ldb);
        }
    };

    #pragma unroll
    for (int s = 0; s < STAGES - 1; ++s) {
        if (s < T) issue(s);
        asm volatile("cp.async.commit_group;");
    }

    for (int t = 0; t < T; ++t) {
        asm volatile("cp.async.wait_group 1;");
        __syncthreads();
        if (t + STAGES - 1 < T) issue(t + STAGES - 1);
        asm volatile("cp.async.commit_group;");

        const uint32_t sA = sbase + (uint32_t)(t % STAGES) * STAGE;
        const uint32_t sB = sA + 16384u;
        #pragma unroll
        for (int kk = 0; kk < 4; ++kk) {
            uint32_t a[2][4];
            #pragma unroll
            for (int mi = 0; mi < 2; ++mi)
                ldsm4(a[mi][0], a[mi][1], a[mi][2], a[mi][3],
                      sA + aoff[mi] + ((((uint32_t)(2 * kk) + kcoA) ^ asw[mi]) << 4));
            uint32_t b[4][4];
            #pragma unroll
            for (int p = 0; p < 4; ++p) {
                if (!BNN)
                    ldsm4(b[p][0], b[p][1], b[p][2], b[p][3],
                          sB + boff[p] + ((((uint32_t)(2 * kk) + kcoB) ^ bsw[p]) << 4));
                else
                    ldsm4t(b[p][0], b[p][1], b[p][2], b[p][3],
                           sB + (uint32_t)kk * 4096u + bkoff + bco[p]);
            }
            #pragma unroll
            for (int mi = 0; mi < 2; ++mi)
                #pragma unroll
                for (int p = 0; p < 4; ++p) {
                    mma16816(acc[mi][2 * p],     a[mi], b[p][0], b[p][1]);
                    mma16816(acc[mi][2 * p + 1], a[mi], b[p][2], b[p][3]);
                }
        }
    }

    const int gid = lane >> 2, qid = lane & 3;
    #pragma unroll
    for (int mi = 0; mi < 2; ++mi) {
        #pragma unroll
        for (int ni = 0; ni < 8; ++ni) {
            const int r = tm0 + wm * 32 + mi * 16 + gid;
            const int c = tn0 + wn * 64 + ni * 8 + qid * 2;
            float v0 = acc[mi][ni][0], v1 = acc[mi][ni][1];
            float v2 = acc[mi][ni][2], v3 = acc[mi][ni][3];
            if (EPI == 1 || EPI == 2) {
                const float2 bb = *reinterpret_cast<const float2*>(bias + c);
                v0 += bb.x; v1 += bb.y; v2 += bb.x; v3 += bb.y;
            }
            if (EPI == 0) {
                *reinterpret_cast<float2*>(Cf + (size_t)r * ldc + c) =
                    make_float2(v0, v1);
                *reinterpret_cast<float2*>(Cf + (size_t)(r + 8) * ldc + c) =
                    make_float2(v2, v3);
            } else if (EPI == 2) {
                *reinterpret_cast<__half2*>(Ch + (size_t)r * ldc + c) =
                    __halves2half2(__float2half_rn(v0), __float2half_rn(v1));
                *reinterpret_cast<__half2*>(Ch + (size_t)(r + 8) * ldc + c) =
                    __halves2half2(__float2half_rn(v2), __float2half_rn(v3));
            } else {
                const __half h0 = __float2half_rn(v0), h1 = __float2half_rn(v1);
                const __half h2 = __float2half_rn(v2), h3 = __float2half_rn(v3);
                *reinterpret_cast<__half2*>(Ch + (size_t)r * ldc + c) =
                    __halves2half2(h0, h1);
                *reinterpret_cast<__half2*>(Ch + (size_t)(r + 8) * ldc + c) =
                    __halves2half2(h2, h3);
                *reinterpret_cast<__half2*>(Cl + (size_t)r * ldc + c) =
                    __halves2half2(__float2half_rn(v0 - __half2float(h0)),
                                   __float2half_rn(v1 - __half2float(h1)));
                *reinterpret_cast<__half2*>(Cl + (size_t)(r + 8) * ldc + c) =
                    __halves2half2(__float2half_rn(v2 - __half2float(h2)),
                                   __float2half_rn(v3 - __half2float(h3)));
            }
        }
    }
}

// ----------------------------------------------------------------------------
// prep kernels
// ----------------------------------------------------------------------------
__device__ __forceinline__ void split4(const float4 v, __half2* dh, __half2* dl) {
    const __half h0 = __float2half_rn(v.x), h1 = __float2half_rn(v.y);
    const __half h2 = __float2half_rn(v.z), h3 = __float2half_rn(v.w);
    dh[0] = __halves2half2(h0, h1);
    dh[1] = __halves2half2(h2, h3);
    dl[0] = __halves2half2(__float2half_rn(v.x - __half2float(h0)),
                           __float2half_rn(v.y - __half2float(h1)));
    dl[1] = __halves2half2(__float2half_rn(v.z - __half2float(h2)),
                           __float2half_rn(v.w - __half2float(h3)));
}

__global__ __launch_bounds__(256)
void split_x_kernel(const float* __restrict__ src)
{
    const int i = blockIdx.x * blockDim.x + threadIdx.x;
    const float4 v = reinterpret_cast<const float4*>(src)[i];
    split4(v, reinterpret_cast<__half2*>(g_xh) + 2 * i,
              reinterpret_cast<__half2*>(g_xl) + 2 * i);
}

__global__ __launch_bounds__(256)
void wk_split_kernel(const float* __restrict__ Wk)
{
    const int i = blockIdx.x * blockDim.x + threadIdx.x;
    const float4 v = reinterpret_cast<const float4*>(Wk)[i];
    split4(v, reinterpret_cast<__half2*>(g_wk_h) + 2 * i,
              reinterpret_cast<__half2*>(g_wk_l) + 2 * i);
}

__global__ __launch_bounds__(256)
void wv_conv_kernel(const float* __restrict__ Wv)
{
    const int i = blockIdx.x * blockDim.x + threadIdx.x;
    const float4 v = reinterpret_cast<const float4*>(Wv)[i];
    reinterpret_cast<__half2*>(g_wv_h)[2 * i] =
        __halves2half2(__float2half_rn(v.x), __float2half_rn(v.y));
    reinterpret_cast<__half2*>(g_wv_h)[2 * i + 1] =
        __halves2half2(__float2half_rn(v.z), __float2half_rn(v.w));
}

// WqT split: g_wqt[a*H+d] = split(Wq[d*H+a])
__global__ __launch_bounds__(256)
void wq_transpose_kernel(const float* __restrict__ Wq)
{
    __shared__ float s[32][33];
    const int a0 = blockIdx.x * 32, d0 = blockIdx.y * 32;
    const int tx = threadIdx.x & 31, ty = threadIdx.x >> 5;   // 32 x 8
    #pragma unroll
    for (int i = 0; i < 4; ++i) {
        const int d = d0 + ty + 8 * i;
        s[ty + 8 * i][tx] = Wq[(size_t)d * HID + a0 + tx];
    }
    __syncthreads();
    #pragma unroll
    for (int i = 0; i < 4; ++i) {
        const int a = a0 + ty + 8 * i;
        const float v = s[tx][ty + 8 * i];
        const __half h = __float2half_rn(v);
        g_wqt_h[(size_t)a * HID + d0 + tx] = h;
        g_wqt_l[(size_t)a * HID + d0 + tx] =
            __float2half_rn(v - __half2float(h));
    }
}

// t2 = Wk^T bq  (t2[a] = sum_d Wk[d,a]*bq[d]); coalesced over a
__global__ __launch_bounds__(256)
void t2_kernel(const float* __restrict__ Wk, const float* __restrict__ bq)
{
    const int a = blockIdx.x * 256 + threadIdx.x;
    float acc = 0.f;
    #pragma unroll 8
    for (int d = 0; d < HID; ++d)
        acc += Wk[(size_t)d * HID + a] * bq[d];
    g_t2[a] = acc;
}

// w[i] = x_i . t2   (one warp per row)
__global__ __launch_bounds__(128)
void w_kernel(const float* __restrict__ x)
{
    const int warp = threadIdx.x >> 5, lane = threadIdx.x & 31;
    const int row = blockIdx.x * 4 + warp;
    const float* xr = x + (size_t)row * HID;
    float s = 0.f;
    for (int a = lane; a < HID; a += 32) s += xr[a] * g_t2[a];
    #pragma unroll
    for (int off = 16; off; off >>= 1)
        s += __shfl_xor_sync(0xffffffffu, s, off);
    if (lane == 0) g_w[row] = s;
}

// ----------------------------------------------------------------------------
// GEMM kernels
// ----------------------------------------------------------------------------
// Merged M + V launch: grid (8, 72).  y<8 -> M tile, y>=8 -> V tile.
__global__ __launch_bounds__(256, 2)
void mv_kernel(const float* __restrict__ bv)
{
    if (blockIdx.y < 8)
        gemm_main<1024, 3, true, 1>(g_wqt_h, g_wqt_l, g_wk_h, g_wk_l, HID, HID,
                                    nullptr, g_mh, g_ml, g_zero, HID,
                                    blockIdx.y * 128, blockIdx.x * 128);
    else
        gemm_main<1024, 1, false, 2>(g_xh, nullptr, g_wv_h, nullptr, HID, HID,
                                     nullptr, g_vh, nullptr, bv, HID,
                                     (blockIdx.y - 8) * 128, blockIdx.x * 128);
}

__global__ __launch_bounds__(256, 2)
void y_kernel()   // y = x M  (NN split3) -> split store
{
    gemm_main<1024, 3, true, 1>(g_xh, g_xl, g_mh, g_ml, HID, HID,
                                nullptr, g_yh, g_yl, g_zero, HID,
                                blockIdx.y * 128, blockIdx.x * 128);
}

__global__ __launch_bounds__(256, 2)
void scores_kernel()   // s = y x^T (TN split3) -> fp32
{
    const size_t bo = (size_t)blockIdx.z * SEQ * HID;
    gemm_main<1024, 3, false, 0>(g_yh + bo, g_yl + bo, g_xh + bo, g_xl + bo,
                                 HID, HID,
                                 g_s + (size_t)blockIdx.z * SEQ * SEQ,
                                 nullptr, nullptr, nullptr, SEQ,
                                 blockIdx.y * 128, blockIdx.x * 128);
}

// ----------------------------------------------------------------------------
// Fused softmax + P.v gather.
// Logits l_j = s_j + w_j; threshold thr = rowmax - 17 (below: contributes
// < 4.2e-8 each -> exact zero, same as all prior passing rounds).
// Surviving (col, prob) pairs (~2 per row) are compacted DETERMINISTICALLY
// (shfl scan + cross-warp smem scan, no atomics) into smem, then the block
// computes out[row,:] = sum_k prob_k * v[col_k,:] directly.
// ----------------------------------------------------------------------------
__global__ __launch_bounds__(256)
void softmax_pv_kernel(float* __restrict__ out)
{
    const int row = blockIdx.x;
    const float* src = g_s + (size_t)row * SEQ;
    const int t = threadIdx.x;
    const int lane = t & 31, wid = t >> 5;
    const int wbase = (row >> 11) << 11;          // batch * SEQ

    __shared__ float red[8];
    __shared__ int   s_wtot[8];
    __shared__ int   s_wbase[8];
    __shared__ int   s_nnz;
    __shared__ float s_val[SEQ];
    __shared__ int   s_idx[SEQ];

    const float4* p4 = reinterpret_cast<const float4*>(src);
    float4 u0 = p4[t];
    float4 u1 = p4[t + 256];
    const float4 w0 = *reinterpret_cast<const float4*>(g_w + wbase + 4 * t);
    const float4 w1 = *reinterpret_cast<const float4*>(g_w + wbase + 1024 + 4 * t);
    u0.x += w0.x; u0.y += w0.y; u0.z += w0.z; u0.w += w0.w;
    u1.x += w1.x; u1.y += w1.y; u1.z += w1.z; u1.w += w1.w;

    const float m0 = fmaxf(fmaxf(u0.x, u0.y), fmaxf(u0.z, u0.w));
    const float m1 = fmaxf(fmaxf(u1.x, u1.y), fmaxf(u1.z, u1.w));
    float m = fmaxf(m0, m1);
    #pragma unroll
    for (int off = 16; off; off >>= 1)
        m = fmaxf(m, __shfl_xor_sync(0xffffffffu, m, off));
    if (lane == 0) red[wid] = m;
    __syncthreads();
    if (t < 8) {
        float mm = red[t];
        #pragma unroll
        for (int off = 4; off; off >>= 1)
            mm = fmaxf(mm, __shfl_xor_sync(0xffu, mm, off));
        if (t == 0) red[0] = mm;
    }
    __syncthreads();
    m = red[0];
    __syncthreads();

    const float thr = m - 17.0f;

    if (__any_sync(0xffffffffu, m0 > thr)) {
        u0.x = (u0.x > thr) ? __expf(u0.x - m) : 0.f;
        u0.y = (u0.y > thr) ? __expf(u0.y - m) : 0.f;
        u0.z = (u0.z > thr) ? __expf(u0.z - m) : 0.f;
        u0.w = (u0.w > thr) ? __expf(u0.w - m) : 0.f;
    } else {
        u0.x = u0.y = u0.z = u0.w = 0.f;
    }
    if (__any_sync(0xffffffffu, m1 > thr)) {
        u1.x = (u1.x > thr) ? __expf(u1.x - m) : 0.f;
        u1.y = (u1.y > thr) ? __expf(u1.y - m) : 0.f;
        u1.z = (u1.z > thr) ? __expf(u1.z - m) : 0.f;
        u1.w = (u1.w > thr) ? __expf(u1.w - m) : 0.f;
    } else {
        u1.x = u1.y = u1.z = u1.w = 0.f;
    }

    float s = (u0.x + u0.y + u0.z + u0.w) + (u1.x + u1.y + u1.z + u1.w);
    #pragma unroll
    for (int off = 16; off; off >>= 1)
        s += __shfl_xor_sync(0xffffffffu, s, off);
    if (lane == 0) red[wid] = s;
    __syncthreads();
    if (t < 8) {
        float ss = red[t];
        #pragma unroll
        for (int off = 4; off; off >>= 1)
            ss += __shfl_xor_sync(0xffu, ss, off);
        if (t == 0) red[0] = ss;
    }
    __syncthreads();
    const float inv = 1.0f / red[0];

    // ---- deterministic compaction of nonzero probabilities ----
    float vals[8];
    vals[0] = u0.x * inv; vals[1] = u0.y * inv;
    vals[2] = u0.z * inv; vals[3] = u0.w * inv;
    vals[4] = u1.x * inv; vals[5] = u1.y * inv;
    vals[6] = u1.z * inv; vals[7] = u1.w * inv;
    int cols[8];
    cols[0] = 4 * t;       cols[1] = 4 * t + 1;
    cols[2] = 4 * t + 2;   cols[3] = 4 * t + 3;
    cols[4] = 1024 + 4 * t;     cols[5] = 1024 + 4 * t + 1;
    cols[6] = 1024 + 4 * t + 2; cols[7] = 1024 + 4 * t + 3;

    int cnt = 0;
    #pragma unroll
    for (int j = 0; j < 8; ++j)
        if (vals[j] > 0.f) cnt++;

    int inc = cnt;
    #pragma unroll
    for (int off = 1; off < 32; off <<= 1) {
        int n = __shfl_up_sync(0xffffffffu, inc, off);
        if (lane >= off) inc += n;
    }
    if (lane == 31) s_wtot[wid] = inc;
    __syncthreads();
    if (t == 0) {
        int run = 0;
        #pragma unroll
        for (int wI = 0; wI < 8; ++wI) {
            s_wbase[wI] = run;
            run += s_wtot[wI];
        }
        s_nnz = run;
    }
    __syncthreads();
    int ofs = s_wbase[wid] + (inc - cnt);
    #pragma unroll
    for (int j = 0; j < 8; ++j) {
        if (vals[j] > 0.f) {
            s_val[ofs] = vals[j];
            s_idx[ofs] = cols[j];
            ofs++;
        }
    }
    __syncthreads();

    // ---- gather: out[row,:] = sum_k s_val[k] * v[s_idx[k], :] ----
    const __half* vbase = g_vh + (size_t)(row >> 11) * SEQ * HID;
    const int nnz = s_nnz;
    float acc0 = 0.f, acc1 = 0.f, acc2 = 0.f, acc3 = 0.f;
    for (int k = 0; k < nnz; ++k) {
        const float pv = s_val[k];
        const __half2* vr = reinterpret_cast<const __half2*>(
            vbase + (size_t)s_idx[k] * HID) + 2 * t;
        const float2 f0 = __half22float2(vr[0]);
        const float2 f1 = __half22float2(vr[1]);
        acc0 += pv * f0.x; acc1 += pv * f0.y;
        acc2 += pv * f1.x; acc3 += pv * f1.y;
    }
    float4 o;
    o.x = acc0; o.y = acc1; o.z = acc2; o.w = acc3;
    *reinterpret_cast<float4*>(out + (size_t)row * HID + 4 * t) = o;
}

// ----------------------------------------------------------------------------
// launch
// ----------------------------------------------------------------------------
#define GEMM_SMEM 98304

extern "C" void kernel_launch(void* const* d_in, const int* in_sizes, int n_in,
                              void* d_out, int out_size)
{
    (void)in_sizes; (void)n_in; (void)out_size;
    const float* x  = (const float*)d_in[0];
    const float* Wq = (const float*)d_in[1];
    const float* bq = (const float*)d_in[2];
    const float* Wk = (const float*)d_in[3];
    const float* Wv = (const float*)d_in[5];
    const float* bv = (const float*)d_in[6];
    float* out = (float*)d_out;

    cudaFuncSetAttribute(mv_kernel,
        cudaFuncAttributeMaxDynamicSharedMemorySize, GEMM_SMEM);
    cudaFuncSetAttribute(y_kernel,
        cudaFuncAttributeMaxDynamicSharedMemorySize, GEMM_SMEM);
    cudaFuncSetAttribute(scores_kernel,
        cudaFuncAttributeMaxDynamicSharedMemorySize, GEMM_SMEM);

    // 0) prep: splits / transpose / rank-1 vectors
    split_x_kernel<<<MTOT * HID / 4 / 256, 256>>>(x);
    wq_transpose_kernel<<<dim3(HID / 32, HID / 32), 256>>>(Wq);
    wk_split_kernel<<<HID * HID / 4 / 256, 256>>>(Wk);
    wv_conv_kernel<<<HID * HID / 4 / 256, 256>>>(Wv);
    t2_kernel<<<HID / 256, 256>>>(Wk, bq);
    w_kernel<<<MTOT / 4, 128>>>(x);

    // 1) merged: M = Wq^T Wk (split3, y<8) + v = x Wv^T + bv (1x, y>=8)
    mv_kernel<<<dim3(HID / 128, 8 + MTOT / 128), 256, GEMM_SMEM>>>(bv);
    // 2) y = x M (split3)
    y_kernel<<<dim3(HID / 128, MTOT / 128), 256, GEMM_SMEM>>>();
    // 3) scores = y x^T (split3) -> fp32
    scores_kernel<<<dim3(SEQ / 128, SEQ / 128, BATCH), 256, GEMM_SMEM>>>();
    // 4) fused softmax(s + w_j) + sparse P.v gather -> out
    softmax_pv_kernel<<<BATCH * SEQ, 256>>>(out);
}

// round 13
// speedup vs baseline: 1.5665x; 1.2594x over previous
#include <cuda_runtime.h>
#include <cuda_fp16.h>
#include <cstdint>

// ============================================================================
// SelfAttention: out = softmax( (xWq^T+bq)(xWk^T+bk)^T ) (xWv^T+bv)
// B=4, S=2048, H=1024 (fp32 in/out)
// q_i.k_j = x_i (Wq^T Wk) x_j^T + rowconst + w_j ; rowconst cancels.
// M = Wq^T Wk + v = x.Wv^T+bv (merged launch); y = x.M (split3).
// Scores: APPROX 1x-fp16 GEMM (yh.xh^T, fp16 store) used only to GATE the
// softmax (threshold approxmax-17.5, margin >> approx error). Surviving
// candidates (~3/row) are RESCORED exactly in fp32 from (yh+yl).(xh+xl),
// then exp/normalize/gather-v — all in one fused kernel. Dense split3 scores
// and dense pv are both eliminated.
// ============================================================================

#define BATCH 4
#define SEQ   2048
#define HID   1024
#define MTOT  (BATCH*SEQ)          // 8192

// ---- scratch (device globals; allocation-free per harness rules) ----
__device__ __half g_xh[(size_t)MTOT * HID];
__device__ __half g_xl[(size_t)MTOT * HID];
__device__ __half g_wqt_h[(size_t)HID * HID];   // Wq^T split
__device__ __half g_wqt_l[(size_t)HID * HID];
__device__ __half g_wk_h[(size_t)HID * HID];    // Wk split (row-major)
__device__ __half g_wk_l[(size_t)HID * HID];
__device__ __half g_wv_h[(size_t)HID * HID];    // Wv fp16
__device__ __half g_mh[(size_t)HID * HID];      // M = Wq^T Wk split
__device__ __half g_ml[(size_t)HID * HID];
__device__ __half g_yh[(size_t)MTOT * HID];     // y = x.M split
__device__ __half g_yl[(size_t)MTOT * HID];
__device__ __half g_vh[(size_t)MTOT * HID];
__device__ __half g_s [(size_t)BATCH * SEQ * SEQ];   // approx scores (fp16)
__device__ float  g_w [MTOT];                   // w_j per (batch,key)
__device__ float  g_t2[HID];                    // Wk^T bq
__device__ float  g_zero[HID];                  // static zero (bias for M,y)

// ----------------------------------------------------------------------------
// helpers
// ----------------------------------------------------------------------------
__device__ __forceinline__ uint32_t smem_u32(const void* p) {
    uint32_t a;
    asm("{ .reg .u64 t; cvta.to.shared.u64 t, %1; cvt.u32.u64 %0, t; }"
        : "=r"(a) : "l"(p));
    return a;
}

__device__ __forceinline__ void cpa16(uint32_t dst, const void* src) {
    asm volatile("cp.async.cg.shared.global [%0], [%1], 16;"
                 :: "r"(dst), "l"(src));
}

__device__ __forceinline__ void ldsm4(uint32_t& r0, uint32_t& r1,
                                      uint32_t& r2, uint32_t& r3, uint32_t a) {
    asm volatile("ldmatrix.sync.aligned.m8n8.x4.shared.b16 {%0,%1,%2,%3}, [%4];"
                 : "=r"(r0), "=r"(r1), "=r"(r2), "=r"(r3) : "r"(a));
}
__device__ __forceinline__ void ldsm4t(uint32_t& r0, uint32_t& r1,
                                       uint32_t& r2, uint32_t& r3, uint32_t a) {
    asm volatile("ldmatrix.sync.aligned.m8n8.x4.trans.shared.b16 {%0,%1,%2,%3}, [%4];"
                 : "=r"(r0), "=r"(r1), "=r"(r2), "=r"(r3) : "r"(a));
}

__device__ __forceinline__ void mma16816(float c[4], const uint32_t a[4],
                                         uint32_t b0, uint32_t b1) {
    asm volatile(
        "mma.sync.aligned.m16n8k16.row.col.f32.f16.f16.f32 "
        "{%0,%1,%2,%3}, {%4,%5,%6,%7}, {%8,%9}, {%0,%1,%2,%3};\n"
        : "+f"(c[0]), "+f"(c[1]), "+f"(c[2]), "+f"(c[3])
        : "r"(a[0]), "r"(a[1]), "r"(a[2]), "r"(a[3]), "r"(b0), "r"(b1));
}

// ============================================================================
// GEMM core: 128x128 CTA tile at (tm0, tn0), BK=64, 3-stage cp.async pipeline.
//   BNN=false: TN — A[M,K], B[N,K] both K-major (C = A * B^T)
//   BNN=true : NN — A[M,K] K-major, B[K,N] N-major (C = A * B)
//   NSPLIT=3 : products Ah*Bh + Ah*Bl + Al*Bh ; NSPLIT=1 : Ah*Bh
//   EPI: 0 fp32 | 1 bias + hi/lo split half | 2 bias + half | 3 plain half
// ============================================================================
template<int KVAL, int NSPLIT, bool BNN, int EPI>
__device__ __forceinline__ void gemm_main(
    const __half* __restrict__ Ah, const __half* __restrict__ Al,
    const __half* __restrict__ Bh, const __half* __restrict__ Bl,
    int lda, int ldb,
    float* __restrict__ Cf, __half* __restrict__ Ch, __half* __restrict__ Cl,
    const float* __restrict__ bias, int ldc,
    int tm0, int tn0)
{
    constexpr int NC = KVAL / 64;
    constexpr int T  = NSPLIT * NC;
    constexpr int STAGES = 3;
    constexpr uint32_t STAGE = 32768u;

    extern __shared__ __align__(16) char smem[];
    const uint32_t sbase = smem_u32(smem);

    const int tid  = threadIdx.x;
    const int lane = tid & 31;
    const int warp = tid >> 5;
    const int wm = warp & 3;
    const int wn = warp >> 2;

    uint32_t dA[4], gA[4], dB[4], gB[4];
    #pragma unroll
    for (int i = 0; i < 4; ++i) {
        const int slot = tid + i * 256;
        { const int r = slot >> 3, c = slot & 7;
          dA[i] = (uint32_t)(r * 128 + ((c ^ (r & 7)) << 4));
          gA[i] = (uint32_t)((tm0 + r) * lda + c * 8); }
        if (!BNN) {
            const int r = slot >> 3, c = slot & 7;
            dB[i] = (uint32_t)(r * 128 + ((c ^ (r & 7)) << 4));
            gB[i] = (uint32_t)((tn0 + r) * ldb + c * 8);
        } else {
            const int r = slot >> 4, c = slot & 15;
            dB[i] = (uint32_t)(r * 256 + ((c ^ (r & 7)) << 4));
            gB[i] = (uint32_t)(r * ldb + tn0 + c * 8);
        }
    }

    const __half* const Alist[3] = {Ah, Ah, Al};
    const __half* const Blist[3] = {Bh, Bl, Bh};

    const uint32_t kcoA = (lane >> 4) & 1;
    uint32_t aoff[2], asw[2];
    {
        const int roff = (lane & 7) + (((lane >> 3) & 1) << 3);
        #pragma unroll
        for (int mi = 0; mi < 2; ++mi) {
            const int r = wm * 32 + mi * 16 + roff;
            aoff[mi] = (uint32_t)(r * 128);
            asw[mi]  = (uint32_t)(r & 7);
        }
    }
    const uint32_t kcoB = (lane >> 3) & 1;
    uint32_t boff[4], bsw[4];
    uint32_t bco[4], bkoff = 0;
    if (!BNN) {
        const int noff = (lane & 7) + (((lane >> 4) & 1) << 3);
        #pragma unroll
        for (int p = 0; p < 4; ++p) {
            const int r = wn * 64 + p * 16 + noff;
            boff[p] = (uint32_t)(r * 128);
            bsw[p]  = (uint32_t)(r & 7);
        }
    } else {
        const int koff = (lane & 7) + (((lane >> 3) & 1) << 3);
        bkoff = (uint32_t)(koff * 256);
        const int ncsel = (lane >> 4) & 1;
        #pragma unroll
        for (int p = 0; p < 4; ++p) {
            const int ncb = wn * 8 + p * 2 + ncsel;
            bco[p] = (uint32_t)((ncb ^ (lane & 7)) << 4);
        }
    }

    float acc[2][8][4];
    #pragma unroll
    for (int mi = 0; mi < 2; ++mi)
        #pragma unroll
        for (int ni = 0; ni < 8; ++ni)
            #pragma unroll
            for (int j = 0; j < 4; ++j) acc[mi][ni][j] = 0.f;

    auto issue = [&](int t) {
        int comp, kc;
        if (NSPLIT == 1) { comp = 0; kc = t; }
        else             { comp = t / NC; kc = t - comp * NC; }
        const int k0 = kc * 64;
        const __half* Ap = Alist[comp];
        const __half* Bp = Blist[comp];
        const uint32_t s = sbase + (uint32_t)(t % STAGES) * STAGE;
        #pragma unroll
        for (int i = 0; i < 4; ++i) {
            cpa16(s + dA[i], Ap + gA[i] + k0);
            if (!BNN) cpa16(s + 16384u + dB[i], Bp + gB[i] + k0);
            else      cpa16(s + 16384u + dB[i], Bp + gB[i] + (size_t)k0 * ldb);
        }
    };

    #pragma unroll
    for (int s = 0; s < STAGES - 1; ++s) {
        if (s < T) issue(s);
        asm volatile("cp.async.commit_group;");
    }

    for (int t = 0; t < T; ++t) {
        asm volatile("cp.async.wait_group 1;");
        __syncthreads();
        if (t + STAGES - 1 < T) issue(t + STAGES - 1);
        asm volatile("cp.async.commit_group;");

        const uint32_t sA = sbase + (uint32_t)(t % STAGES) * STAGE;
        const uint32_t sB = sA + 16384u;
        #pragma unroll
        for (int kk = 0; kk < 4; ++kk) {
            uint32_t a[2][4];
            #pragma unroll
            for (int mi = 0; mi < 2; ++mi)
                ldsm4(a[mi][0], a[mi][1], a[mi][2], a[mi][3],
                      sA + aoff[mi] + ((((uint32_t)(2 * kk) + kcoA) ^ asw[mi]) << 4));
            uint32_t b[4][4];
            #pragma unroll
            for (int p = 0; p < 4; ++p) {
                if (!BNN)
                    ldsm4(b[p][0], b[p][1], b[p][2], b[p][3],
                          sB + boff[p] + ((((uint32_t)(2 * kk) + kcoB) ^ bsw[p]) << 4));
                else
                    ldsm4t(b[p][0], b[p][1], b[p][2], b[p][3],
                           sB + (uint32_t)kk * 4096u + bkoff + bco[p]);
            }
            #pragma unroll
            for (int mi = 0; mi < 2; ++mi)
                #pragma unroll
                for (int p = 0; p < 4; ++p) {
                    mma16816(acc[mi][2 * p],     a[mi], b[p][0], b[p][1]);
                    mma16816(acc[mi][2 * p + 1], a[mi], b[p][2], b[p][3]);
                }
        }
    }

    const int gid = lane >> 2, qid = lane & 3;
    #pragma unroll
    for (int mi = 0; mi < 2; ++mi) {
        #pragma unroll
        for (int ni = 0; ni < 8; ++ni) {
            const int r = tm0 + wm * 32 + mi * 16 + gid;
            const int c = tn0 + wn * 64 + ni * 8 + qid * 2;
            float v0 = acc[mi][ni][0], v1 = acc[mi][ni][1];
            float v2 = acc[mi][ni][2], v3 = acc[mi][ni][3];
            if (EPI == 1 || EPI == 2) {
                const float2 bb = *reinterpret_cast<const float2*>(bias + c);
                v0 += bb.x; v1 += bb.y; v2 += bb.x; v3 += bb.y;
            }
            if (EPI == 0) {
                *reinterpret_cast<float2*>(Cf + (size_t)r * ldc + c) =
                    make_float2(v0, v1);
                *reinterpret_cast<float2*>(Cf + (size_t)(r + 8) * ldc + c) =
                    make_float2(v2, v3);
            } else if (EPI == 2 || EPI == 3) {
                *reinterpret_cast<__half2*>(Ch + (size_t)r * ldc + c) =
                    __halves2half2(__float2half_rn(v0), __float2half_rn(v1));
                *reinterpret_cast<__half2*>(Ch + (size_t)(r + 8) * ldc + c) =
                    __halves2half2(__float2half_rn(v2), __float2half_rn(v3));
            } else {
                const __half h0 = __float2half_rn(v0), h1 = __float2half_rn(v1);
                const __half h2 = __float2half_rn(v2), h3 = __float2half_rn(v3);
                *reinterpret_cast<__half2*>(Ch + (size_t)r * ldc + c) =
                    __halves2half2(h0, h1);
                *reinterpret_cast<__half2*>(Ch + (size_t)(r + 8) * ldc + c) =
                    __halves2half2(h2, h3);
                *reinterpret_cast<__half2*>(Cl + (size_t)r * ldc + c) =
                    __halves2half2(__float2half_rn(v0 - __half2float(h0)),
                                   __float2half_rn(v1 - __half2float(h1)));
                *reinterpret_cast<__half2*>(Cl + (size_t)(r + 8) * ldc + c) =
                    __halves2half2(__float2half_rn(v2 - __half2float(h2)),
                                   __float2half_rn(v3 - __half2float(h3)));
            }
        }
    }
}

// ----------------------------------------------------------------------------
// prep kernels
// ----------------------------------------------------------------------------
__device__ __forceinline__ void split4(const float4 v, __half2* dh, __half2* dl) {
    const __half h0 = __float2half_rn(v.x), h1 = __float2half_rn(v.y);
    const __half h2 = __float2half_rn(v.z), h3 = __float2half_rn(v.w);
    dh[0] = __halves2half2(h0, h1);
    dh[1] = __halves2half2(h2, h3);
    dl[0] = __halves2half2(__float2half_rn(v.x - __half2float(h0)),
                           __float2half_rn(v.y - __half2float(h1)));
    dl[1] = __halves2half2(__float2half_rn(v.z - __half2float(h2)),
                           __float2half_rn(v.w - __half2float(h3)));
}

__global__ __launch_bounds__(256)
void split_x_kernel(const float* __restrict__ src)
{
    const int i = blockIdx.x * blockDim.x + threadIdx.x;
    const float4 v = reinterpret_cast<const float4*>(src)[i];
    split4(v, reinterpret_cast<__half2*>(g_xh) + 2 * i,
              reinterpret_cast<__half2*>(g_xl) + 2 * i);
}

__global__ __launch_bounds__(256)
void wk_split_kernel(const float* __restrict__ Wk)
{
    const int i = blockIdx.x * blockDim.x + threadIdx.x;
    const float4 v = reinterpret_cast<const float4*>(Wk)[i];
    split4(v, reinterpret_cast<__half2*>(g_wk_h) + 2 * i,
              reinterpret_cast<__half2*>(g_wk_l) + 2 * i);
}

__global__ __launch_bounds__(256)
void wv_conv_kernel(const float* __restrict__ Wv)
{
    const int i = blockIdx.x * blockDim.x + threadIdx.x;
    const float4 v = reinterpret_cast<const float4*>(Wv)[i];
    reinterpret_cast<__half2*>(g_wv_h)[2 * i] =
        __halves2half2(__float2half_rn(v.x), __float2half_rn(v.y));
    reinterpret_cast<__half2*>(g_wv_h)[2 * i + 1] =
        __halves2half2(__float2half_rn(v.z), __float2half_rn(v.w));
}

// WqT split: g_wqt[a*H+d] = split(Wq[d*H+a])
__global__ __launch_bounds__(256)
void wq_transpose_kernel(const float* __restrict__ Wq)
{
    __shared__ float s[32][33];
    const int a0 = blockIdx.x * 32, d0 = blockIdx.y * 32;
    const int tx = threadIdx.x & 31, ty = threadIdx.x >> 5;   // 32 x 8
    #pragma unroll
    for (int i = 0; i < 4; ++i) {
        const int d = d0 + ty + 8 * i;
        s[ty + 8 * i][tx] = Wq[(size_t)d * HID + a0 + tx];
    }
    __syncthreads();
    #pragma unroll
    for (int i = 0; i < 4; ++i) {
        const int a = a0 + ty + 8 * i;
        const float v = s[tx][ty + 8 * i];
        const __half h = __float2half_rn(v);
        g_wqt_h[(size_t)a * HID + d0 + tx] = h;
        g_wqt_l[(size_t)a * HID + d0 + tx] =
            __float2half_rn(v - __half2float(h));
    }
}

// t2 = Wk^T bq
__global__ __launch_bounds__(256)
void t2_kernel(const float* __restrict__ Wk, const float* __restrict__ bq)
{
    const int a = blockIdx.x * 256 + threadIdx.x;
    float acc = 0.f;
    #pragma unroll 8
    for (int d = 0; d < HID; ++d)
        acc += Wk[(size_t)d * HID + a] * bq[d];
    g_t2[a] = acc;
}

// w[i] = x_i . t2
__global__ __launch_bounds__(128)
void w_kernel(const float* __restrict__ x)
{
    const int warp = threadIdx.x >> 5, lane = threadIdx.x & 31;
    const int row = blockIdx.x * 4 + warp;
    const float* xr = x + (size_t)row * HID;
    float s = 0.f;
    for (int a = lane; a < HID; a += 32) s += xr[a] * g_t2[a];
    #pragma unroll
    for (int off = 16; off; off >>= 1)
        s += __shfl_xor_sync(0xffffffffu, s, off);
    if (lane == 0) g_w[row] = s;
}

// ----------------------------------------------------------------------------
// GEMM kernels
// ----------------------------------------------------------------------------
// Merged M + V launch: grid (8, 72).  y<8 -> M tile, y>=8 -> V tile.
__global__ __launch_bounds__(256, 2)
void mv_kernel(const float* __restrict__ bv)
{
    if (blockIdx.y < 8)
        gemm_main<1024, 3, true, 1>(g_wqt_h, g_wqt_l, g_wk_h, g_wk_l, HID, HID,
                                    nullptr, g_mh, g_ml, g_zero, HID,
                                    blockIdx.y * 128, blockIdx.x * 128);
    else
        gemm_main<1024, 1, false, 2>(g_xh, nullptr, g_wv_h, nullptr, HID, HID,
                                     nullptr, g_vh, nullptr, bv, HID,
                                     (blockIdx.y - 8) * 128, blockIdx.x * 128);
}

__global__ __launch_bounds__(256, 2)
void y_kernel()   // y = x M  (NN split3) -> split store
{
    gemm_main<1024, 3, true, 1>(g_xh, g_xl, g_mh, g_ml, HID, HID,
                                nullptr, g_yh, g_yl, g_zero, HID,
                                blockIdx.y * 128, blockIdx.x * 128);
}

__global__ __launch_bounds__(256, 2)
void scores_kernel()   // approx s = yh xh^T (TN 1x) -> fp16
{
    const size_t bo = (size_t)blockIdx.z * SEQ * HID;
    gemm_main<1024, 1, false, 3>(g_yh + bo, nullptr, g_xh + bo, nullptr,
                                 HID, HID,
                                 nullptr,
                                 g_s + (size_t)blockIdx.z * SEQ * SEQ, nullptr,
                                 nullptr, SEQ,
                                 blockIdx.y * 128, blockIdx.x * 128);
}

// ----------------------------------------------------------------------------
// Fused gate + exact rescore + softmax + P.v gather.
// Approx logits a_j = s16_j + w_j (err < 0.15 abs).  Candidates: a_j >
// approxmax - 17.5 (margin covers approx error with huge slack).  Candidates
// are rescored EXACTLY in fp32: l_j = (yh+yl).(xh+xl)_j + w_j, then the
// exact gate (l > exactmax - 17), exp, normalize, gather v rows.
// Deterministic compaction (shfl + smem scan), no atomics.
// ----------------------------------------------------------------------------
__global__ __launch_bounds__(256)
void softmax_rescore_pv_kernel(float* __restrict__ out)
{
    const int row = blockIdx.x;
    const int batch = row >> 11;
    const int wbase = batch << 11;
    const __half* srow = g_s + (size_t)row * SEQ;
    const int t = threadIdx.x, lane = t & 31, wid = t >> 5;

    __shared__ float red[8];
    __shared__ int   s_wtot[8];
    __shared__ int   s_wbase[8];
    __shared__ int   s_ncand;
    __shared__ int   s_idx[SEQ];
    __shared__ float s_logit[SEQ];
    __shared__ float s_y[HID];

    // ---- y row -> smem fp32 (yh + yl) ----
    {
        const __half2* yh2 = reinterpret_cast<const __half2*>(g_yh + (size_t)row * HID);
        const __half2* yl2 = reinterpret_cast<const __half2*>(g_yl + (size_t)row * HID);
        #pragma unroll
        for (int i = 0; i < 2; ++i) {
            const int k = t + i * 256;
            const float2 h = __half22float2(yh2[k]);
            const float2 l = __half22float2(yl2[k]);
            s_y[2 * k]     = h.x + l.x;
            s_y[2 * k + 1] = h.y + l.y;
        }
    }

    // ---- approx logits (8 per thread) ----
    float av[8];
    {
        const float4 w0 = *reinterpret_cast<const float4*>(g_w + wbase + 4 * t);
        const float4 w1 = *reinterpret_cast<const float4*>(g_w + wbase + 1024 + 4 * t);
        const __half2* s2 = reinterpret_cast<const __half2*>(srow);
        const float2 a0 = __half22float2(s2[2 * t]);
        const float2 a1 = __half22float2(s2[2 * t + 1]);
        const float2 a2 = __half22float2(s2[512 + 2 * t]);
        const float2 a3 = __half22float2(s2[512 + 2 * t + 1]);
        av[0] = a0.x + w0.x; av[1] = a0.y + w0.y;
        av[2] = a1.x + w0.z; av[3] = a1.y + w0.w;
        av[4] = a2.x + w1.x; av[5] = a2.y + w1.y;
        av[6] = a3.x + w1.z; av[7] = a3.y + w1.w;
    }
    int cols[8];
    cols[0] = 4 * t;           cols[1] = 4 * t + 1;
    cols[2] = 4 * t + 2;       cols[3] = 4 * t + 3;
    cols[4] = 1024 + 4 * t;    cols[5] = 1024 + 4 * t + 1;
    cols[6] = 1024 + 4 * t + 2; cols[7] = 1024 + 4 * t + 3;

    // ---- approx row max ----
    float m = av[0];
    #pragma unroll
    for (int j = 1; j < 8; ++j) m = fmaxf(m, av[j]);
    #pragma unroll
    for (int off = 16; off; off >>= 1)
        m = fmaxf(m, __shfl_xor_sync(0xffffffffu, m, off));
    if (lane == 0) red[wid] = m;
    __syncthreads();
    if (t < 8) {
        float mm = red[t];
        #pragma unroll
        for (int off = 4; off; off >>= 1)
            mm = fmaxf(mm, __shfl_xor_sync(0xffu, mm, off));
        if (t == 0) red[0] = mm;
    }
    __syncthreads();
    m = red[0];
    __syncthreads();

    const float thr = m - 17.5f;    // margin 0.5 >> approx error (<0.15)

    // ---- deterministic candidate compaction ----
    int cnt = 0;
    #pragma unroll
    for (int j = 0; j < 8; ++j)
        if (av[j] > thr) cnt++;
    int inc = cnt;
    #pragma unroll
    for (int off = 1; off < 32; off <<= 1) {
        int n = __shfl_up_sync(0xffffffffu, inc, off);
        if (lane >= off) inc += n;
    }
    if (lane == 31) s_wtot[wid] = inc;
    __syncthreads();
    if (t == 0) {
        int run = 0;
        #pragma unroll
        for (int wI = 0; wI < 8; ++wI) {
            s_wbase[wI] = run;
            run += s_wtot[wI];
        }
        s_ncand = run;
    }
    __syncthreads();
    int ofs = s_wbase[wid] + (inc - cnt);
    #pragma unroll
    for (int j = 0; j < 8; ++j) {
        if (av[j] > thr) {
            s_idx[ofs] = cols[j];
            ofs++;
        }
    }
    __syncthreads();
    const int ncand = s_ncand;   // >= 1 always (max element passes)

    // ---- exact rescore: one warp per candidate ----
    for (int k = wid; k < ncand; k += 8) {
        const int j = s_idx[k];
        const __half2* xh2 = reinterpret_cast<const __half2*>(
            g_xh + (size_t)(wbase + j) * HID);
        const __half2* xl2 = reinterpret_cast<const __half2*>(
            g_xl + (size_t)(wbase + j) * HID);
        float part = 0.f;
        for (int d = lane; d < 512; d += 32) {
            const float2 h = __half22float2(xh2[d]);
            const float2 l = __half22float2(xl2[d]);
            part += s_y[2 * d] * (h.x + l.x) + s_y[2 * d + 1] * (h.y + l.y);
        }
        #pragma unroll
        for (int off = 16; off; off >>= 1)
            part += __shfl_xor_sync(0xffffffffu, part, off);
        if (lane == 0) s_logit[k] = part + g_w[wbase + j];
    }
    __syncthreads();

    // ---- exact max over candidates ----
    float m2 = -3.4e38f;
    for (int k = t; k < ncand; k += 256) m2 = fmaxf(m2, s_logit[k]);
    #pragma unroll
    for (int off = 16; off; off >>= 1)
        m2 = fmaxf(m2, __shfl_xor_sync(0xffffffffu, m2, off));
    if (lane == 0) red[wid] = m2;
    __syncthreads();
    if (t < 8) {
        float mm = red[t];
        #pragma unroll
        for (int off = 4; off; off >>= 1)
            mm = fmaxf(mm, __shfl_xor_sync(0xffu, mm, off));
        if (t == 0) red[0] = mm;
    }
    __syncthreads();
    m2 = red[0];
    __syncthreads();

    // ---- exact gate + exp + sum ----
    const float thr2 = m2 - 17.0f;
    float ssum = 0.f;
    for (int k = t; k < ncand; k += 256) {
        const float l = s_logit[k];
        const float e = (l > thr2) ? __expf(l - m2) : 0.f;
        s_logit[k] = e;
        ssum += e;
    }
    #pragma unroll
    for (int off = 16; off; off >>= 1)
        ssum += __shfl_xor_sync(0xffffffffu, ssum, off);
    if (lane == 0) red[wid] = ssum;
    __syncthreads();
    if (t < 8) {
        float ss = red[t];
        #pragma unroll
        for (int off = 4; off; off >>= 1)
            ss += __shfl_xor_sync(0xffu, ss, off);
        if (t == 0) red[0] = ss;
    }
    __syncthreads();
    const float inv = 1.0f / red[0];
    __syncthreads();

    // ---- gather: out[row,:] = sum_k p_k * v[idx_k,:] ----
    const __half* vbase = g_vh + (size_t)batch * SEQ * HID;
    float acc0 = 0.f, acc1 = 0.f, acc2 = 0.f, acc3 = 0.f;
    for (int k = 0; k < ncand; ++k) {
        const float pv = s_logit[k] * inv;
        if (pv != 0.f) {
            const __half2* vr = reinterpret_cast<const __half2*>(
                vbase + (size_t)s_idx[k] * HID) + 2 * t;
            const float2 f0 = __half22float2(vr[0]);
            const float2 f1 = __half22float2(vr[1]);
            acc0 += pv * f0.x; acc1 += pv * f0.y;
            acc2 += pv * f1.x; acc3 += pv * f1.y;
        }
    }
    float4 o;
    o.x = acc0; o.y = acc1; o.z = acc2; o.w = acc3;
    *reinterpret_cast<float4*>(out + (size_t)row * HID + 4 * t) = o;
}

// ----------------------------------------------------------------------------
// launch
// ----------------------------------------------------------------------------
#define GEMM_SMEM 98304

extern "C" void kernel_launch(void* const* d_in, const int* in_sizes, int n_in,
                              void* d_out, int out_size)
{
    (void)in_sizes; (void)n_in; (void)out_size;
    const float* x  = (const float*)d_in[0];
    const float* Wq = (const float*)d_in[1];
    const float* bq = (const float*)d_in[2];
    const float* Wk = (const float*)d_in[3];
    const float* Wv = (const float*)d_in[5];
    const float* bv = (const float*)d_in[6];
    float* out = (float*)d_out;

    cudaFuncSetAttribute(mv_kernel,
        cudaFuncAttributeMaxDynamicSharedMemorySize, GEMM_SMEM);
    cudaFuncSetAttribute(y_kernel,
        cudaFuncAttributeMaxDynamicSharedMemorySize, GEMM_SMEM);
    cudaFuncSetAttribute(scores_kernel,
        cudaFuncAttributeMaxDynamicSharedMemorySize, GEMM_SMEM);

    // 0) prep: splits / transpose / rank-1 vectors
    split_x_kernel<<<MTOT * HID / 4 / 256, 256>>>(x);
    wq_transpose_kernel<<<dim3(HID / 32, HID / 32), 256>>>(Wq);
    wk_split_kernel<<<HID * HID / 4 / 256, 256>>>(Wk);
    wv_conv_kernel<<<HID * HID / 4 / 256, 256>>>(Wv);
    t2_kernel<<<HID / 256, 256>>>(Wk, bq);
    w_kernel<<<MTOT / 4, 128>>>(x);

    // 1) merged: M = Wq^T Wk (split3, y<8) + v = x Wv^T + bv (1x, y>=8)
    mv_kernel<<<dim3(HID / 128, 8 + MTOT / 128), 256, GEMM_SMEM>>>(bv);
    // 2) y = x M (split3)
    y_kernel<<<dim3(HID / 128, MTOT / 128), 256, GEMM_SMEM>>>();
    // 3) approx scores = yh xh^T (1x fp16) -> fp16
    scores_kernel<<<dim3(SEQ / 128, SEQ / 128, BATCH), 256, GEMM_SMEM>>>();
    // 4) fused gate + exact rescore + softmax + sparse P.v gather -> out
    softmax_rescore_pv_kernel<<<BATCH * SEQ, 256>>>(out);
}

// round 14
// speedup vs baseline: 1.5970x; 1.0195x over previous
#include <cuda_runtime.h>
#include <cuda_fp16.h>
#include <cstdint>

// ============================================================================
// SelfAttention: out = softmax( (xWq^T+bq)(xWk^T+bk)^T ) (xWv^T+bv)
// B=4, S=2048, H=1024 (fp32 in/out)
// q_i.k_j = x_i (Wq^T Wk) x_j^T + rowconst + w_j ; rowconst cancels.
// M = Wq^T Wk + v = x.Wv^T+bv (merged); y = x.M (split3, also emits int8 yq).
// Scores: APPROX INT8 GEMM (yq.xq^T, m16n8k32.s8, fp16 store) used only to
// GATE the softmax (threshold approxmax-22.5; int8 dot err rms ~0.8, margin
// covers 15+ sigma).  Candidates (~4/row) are RESCORED exactly in fp32 from
// (yh+yl).(xh+xl), then exp/normalize/gather-v in one fused kernel.
// ============================================================================

#define BATCH 4
#define SEQ   2048
#define HID   1024
#define MTOT  (BATCH*SEQ)          // 8192

#define QINV   (127.0f/8.0f)       // quantize: q = round(x * QINV)
#define SSCALE ((8.0f/127.0f)*(8.0f/127.0f))   // descale for int32 dot

// ---- scratch (device globals; allocation-free per harness rules) ----
__device__ __half g_xh[(size_t)MTOT * HID];
__device__ __half g_xl[(size_t)MTOT * HID];
__device__ int8_t g_xq[(size_t)MTOT * HID];
__device__ __half g_wqt_h[(size_t)HID * HID];
__device__ __half g_wqt_l[(size_t)HID * HID];
__device__ __half g_wk_h[(size_t)HID * HID];
__device__ __half g_wk_l[(size_t)HID * HID];
__device__ __half g_wv_h[(size_t)HID * HID];
__device__ __half g_mh[(size_t)HID * HID];
__device__ __half g_ml[(size_t)HID * HID];
__device__ __half g_yh[(size_t)MTOT * HID];
__device__ __half g_yl[(size_t)MTOT * HID];
__device__ int8_t g_yq[(size_t)MTOT * HID];
__device__ __half g_vh[(size_t)MTOT * HID];
__device__ __half g_s [(size_t)BATCH * SEQ * SEQ];   // approx scores (fp16)
__device__ float  g_w [MTOT];
__device__ float  g_t2[HID];
__device__ float  g_zero[HID];

// ----------------------------------------------------------------------------
// helpers
// ----------------------------------------------------------------------------
__device__ __forceinline__ uint32_t smem_u32(const void* p) {
    uint32_t a;
    asm("{ .reg .u64 t; cvta.to.shared.u64 t, %1; cvt.u32.u64 %0, t; }"
        : "=r"(a) : "l"(p));
    return a;
}

__device__ __forceinline__ void cpa16(uint32_t dst, const void* src) {
    asm volatile("cp.async.cg.shared.global [%0], [%1], 16;"
                 :: "r"(dst), "l"(src));
}

__device__ __forceinline__ void ldsm4(uint32_t& r0, uint32_t& r1,
                                      uint32_t& r2, uint32_t& r3, uint32_t a) {
    asm volatile("ldmatrix.sync.aligned.m8n8.x4.shared.b16 {%0,%1,%2,%3}, [%4];"
                 : "=r"(r0), "=r"(r1), "=r"(r2), "=r"(r3) : "r"(a));
}
__device__ __forceinline__ void ldsm4t(uint32_t& r0, uint32_t& r1,
                                       uint32_t& r2, uint32_t& r3, uint32_t a) {
    asm volatile("ldmatrix.sync.aligned.m8n8.x4.trans.shared.b16 {%0,%1,%2,%3}, [%4];"
                 : "=r"(r0), "=r"(r1), "=r"(r2), "=r"(r3) : "r"(a));
}

__device__ __forceinline__ void mma16816(float c[4], const uint32_t a[4],
                                         uint32_t b0, uint32_t b1) {
    asm volatile(
        "mma.sync.aligned.m16n8k16.row.col.f32.f16.f16.f32 "
        "{%0,%1,%2,%3}, {%4,%5,%6,%7}, {%8,%9}, {%0,%1,%2,%3};\n"
        : "+f"(c[0]), "+f"(c[1]), "+f"(c[2]), "+f"(c[3])
        : "r"(a[0]), "r"(a[1]), "r"(a[2]), "r"(a[3]), "r"(b0), "r"(b1));
}

__device__ __forceinline__ void mma_s8(int c[4], const uint32_t a[4],
                                       uint32_t b0, uint32_t b1) {
    asm volatile(
        "mma.sync.aligned.m16n8k32.row.col.s32.s8.s8.s32 "
        "{%0,%1,%2,%3}, {%4,%5,%6,%7}, {%8,%9}, {%0,%1,%2,%3};\n"
        : "+r"(c[0]), "+r"(c[1]), "+r"(c[2]), "+r"(c[3])
        : "r"(a[0]), "r"(a[1]), "r"(a[2]), "r"(a[3]), "r"(b0), "r"(b1));
}

__device__ __forceinline__ int8_t quant8(float x) {
    const float q = fminf(fmaxf(x * QINV, -127.f), 127.f);
    return (int8_t)__float2int_rn(q);
}

// ============================================================================
// FP16 GEMM core (unchanged): 128x128 tile, BK=64, 3-stage cp.async.
//   EPI: 0 fp32 | 1 bias + split half | 2 bias + half | 4 split half + int8
// ============================================================================
template<int KVAL, int NSPLIT, bool BNN, int EPI>
__device__ __forceinline__ void gemm_main(
    const __half* __restrict__ Ah, const __half* __restrict__ Al,
    const __half* __restrict__ Bh, const __half* __restrict__ Bl,
    int lda, int ldb,
    float* __restrict__ Cf, __half* __restrict__ Ch, __half* __restrict__ Cl,
    const float* __restrict__ bias, int ldc,
    int tm0, int tn0)
{
    constexpr int NC = KVAL / 64;
    constexpr int T  = NSPLIT * NC;
    constexpr int STAGES = 3;
    constexpr uint32_t STAGE = 32768u;

    extern __shared__ __align__(16) char smem[];
    const uint32_t sbase = smem_u32(smem);

    const int tid  = threadIdx.x;
    const int lane = tid & 31;
    const int warp = tid >> 5;
    const int wm = warp & 3;
    const int wn = warp >> 2;

    uint32_t dA[4], gA[4], dB[4], gB[4];
    #pragma unroll
    for (int i = 0; i < 4; ++i) {
        const int slot = tid + i * 256;
        { const int r = slot >> 3, c = slot & 7;
          dA[i] = (uint32_t)(r * 128 + ((c ^ (r & 7)) << 4));
          gA[i] = (uint32_t)((tm0 + r) * lda + c * 8); }
        if (!BNN) {
            const int r = slot >> 3, c = slot & 7;
            dB[i] = (uint32_t)(r * 128 + ((c ^ (r & 7)) << 4));
            gB[i] = (uint32_t)((tn0 + r) * ldb + c * 8);
        } else {
            const int r = slot >> 4, c = slot & 15;
            dB[i] = (uint32_t)(r * 256 + ((c ^ (r & 7)) << 4));
            gB[i] = (uint32_t)(r * ldb + tn0 + c * 8);
        }
    }

    const __half* const Alist[3] = {Ah, Ah, Al};
    const __half* const Blist[3] = {Bh, Bl, Bh};

    const uint32_t kcoA = (lane >> 4) & 1;
    uint32_t aoff[2], asw[2];
    {
        const int roff = (lane & 7) + (((lane >> 3) & 1) << 3);
        #pragma unroll
        for (int mi = 0; mi < 2; ++mi) {
            const int r = wm * 32 + mi * 16 + roff;
            aoff[mi] = (uint32_t)(r * 128);
            asw[mi]  = (uint32_t)(r & 7);
        }
    }
    const uint32_t kcoB = (lane >> 3) & 1;
    uint32_t boff[4], bsw[4];
    uint32_t bco[4], bkoff = 0;
    if (!BNN) {
        const int noff = (lane & 7) + (((lane >> 4) & 1) << 3);
        #pragma unroll
        for (int p = 0; p < 4; ++p) {
            const int r = wn * 64 + p * 16 + noff;
            boff[p] = (uint32_t)(r * 128);
            bsw[p]  = (uint32_t)(r & 7);
        }
    } else {
        const int koff = (lane & 7) + (((lane >> 3) & 1) << 3);
        bkoff = (uint32_t)(koff * 256);
        const int ncsel = (lane >> 4) & 1;
        #pragma unroll
        for (int p = 0; p < 4; ++p) {
            const int ncb = wn * 8 + p * 2 + ncsel;
            bco[p] = (uint32_t)((ncb ^ (lane & 7)) << 4);
        }
    }

    float acc[2][8][4];
    #pragma unroll
    for (int mi = 0; mi < 2; ++mi)
        #pragma unroll
        for (int ni = 0; ni < 8; ++ni)
            #pragma unroll
            for (int j = 0; j < 4; ++j) acc[mi][ni][j] = 0.f;

    auto issue = [&](int t) {
        int comp, kc;
        if (NSPLIT == 1) { comp = 0; kc = t; }
        else             { comp = t / NC; kc = t - comp * NC; }
        const int k0 = kc * 64;
        const __half* Ap = Alist[comp];
        const __half* Bp = Blist[comp];
        const uint32_t s = sbase + (uint32_t)(t % STAGES) * STAGE;
        #pragma unroll
        for (int i = 0; i < 4; ++i) {
            cpa16(s + dA[i], Ap + gA[i] + k0);
            if (!BNN) cpa16(s + 16384u + dB[i], Bp + gB[i] + k0);
            else      cpa16(s + 16384u + dB[i], Bp + gB[i] + (size_t)k0 * ldb);
        }
    };

    #pragma unroll
    for (int s = 0; s < STAGES - 1; ++s) {
        if (s < T) issue(s);
        asm volatile("cp.async.commit_group;");
    }

    for (int t = 0; t < T; ++t) {
        asm volatile("cp.async.wait_group 1;");
        __syncthreads();
        if (t + STAGES - 1 < T) issue(t + STAGES - 1);
        asm volatile("cp.async.commit_group;");

        const uint32_t sA = sbase + (uint32_t)(t % STAGES) * STAGE;
        const uint32_t sB = sA + 16384u;
        #pragma unroll
        for (int kk = 0; kk < 4; ++kk) {
            uint32_t a[2][4];
            #pragma unroll
            for (int mi = 0; mi < 2; ++mi)
                ldsm4(a[mi][0], a[mi][1], a[mi][2], a[mi][3],
                      sA + aoff[mi] + ((((uint32_t)(2 * kk) + kcoA) ^ asw[mi]) << 4));
            uint32_t b[4][4];
            #pragma unroll
            for (int p = 0; p < 4; ++p) {
                if (!BNN)
                    ldsm4(b[p][0], b[p][1], b[p][2], b[p][3],
                          sB + boff[p] + ((((uint32_t)(2 * kk) + kcoB) ^ bsw[p]) << 4));
                else
                    ldsm4t(b[p][0], b[p][1], b[p][2], b[p][3],
                           sB + (uint32_t)kk * 4096u + bkoff + bco[p]);
            }
            #pragma unroll
            for (int mi = 0; mi < 2; ++mi)
                #pragma unroll
                for (int p = 0; p < 4; ++p) {
                    mma16816(acc[mi][2 * p],     a[mi], b[p][0], b[p][1]);
                    mma16816(acc[mi][2 * p + 1], a[mi], b[p][2], b[p][3]);
                }
        }
    }

    const int gid = lane >> 2, qid = lane & 3;
    #pragma unroll
    for (int mi = 0; mi < 2; ++mi) {
        #pragma unroll
        for (int ni = 0; ni < 8; ++ni) {
            const int r = tm0 + wm * 32 + mi * 16 + gid;
            const int c = tn0 + wn * 64 + ni * 8 + qid * 2;
            float v0 = acc[mi][ni][0], v1 = acc[mi][ni][1];
            float v2 = acc[mi][ni][2], v3 = acc[mi][ni][3];
            if (EPI == 1 || EPI == 2) {
                const float2 bb = *reinterpret_cast<const float2*>(bias + c);
                v0 += bb.x; v1 += bb.y; v2 += bb.x; v3 += bb.y;
            }
            if (EPI == 0) {
                *reinterpret_cast<float2*>(Cf + (size_t)r * ldc + c) =
                    make_float2(v0, v1);
                *reinterpret_cast<float2*>(Cf + (size_t)(r + 8) * ldc + c) =
                    make_float2(v2, v3);
            } else if (EPI == 2) {
                *reinterpret_cast<__half2*>(Ch + (size_t)r * ldc + c) =
                    __halves2half2(__float2half_rn(v0), __float2half_rn(v1));
                *reinterpret_cast<__half2*>(Ch + (size_t)(r + 8) * ldc + c) =
                    __halves2half2(__float2half_rn(v2), __float2half_rn(v3));
            } else {
                const __half h0 = __float2half_rn(v0), h1 = __float2half_rn(v1);
                const __half h2 = __float2half_rn(v2), h3 = __float2half_rn(v3);
                *reinterpret_cast<__half2*>(Ch + (size_t)r * ldc + c) =
                    __halves2half2(h0, h1);
                *reinterpret_cast<__half2*>(Ch + (size_t)(r + 8) * ldc + c) =
                    __halves2half2(h2, h3);
                *reinterpret_cast<__half2*>(Cl + (size_t)r * ldc + c) =
                    __halves2half2(__float2half_rn(v0 - __half2float(h0)),
                                   __float2half_rn(v1 - __half2float(h1)));
                *reinterpret_cast<__half2*>(Cl + (size_t)(r + 8) * ldc + c) =
                    __halves2half2(__float2half_rn(v2 - __half2float(h2)),
                                   __float2half_rn(v3 - __half2float(h3)));
                if (EPI == 4) {
                    char2 q01; q01.x = quant8(v0); q01.y = quant8(v1);
                    char2 q23; q23.x = quant8(v2); q23.y = quant8(v3);
                    *reinterpret_cast<char2*>(g_yq + (size_t)r * ldc + c) = q01;
                    *reinterpret_cast<char2*>(g_yq + (size_t)(r + 8) * ldc + c) = q23;
                }
            }
        }
    }
}

// ============================================================================
// INT8 GEMM core (TN): C[128x128 tile] = A[M,K] * B[N,K]^T, s8 inputs,
// s32 accum, fp16 store with SSCALE.  Rows of 128 bytes = K=128 per chunk.
// Fragment byte layout of m16n8k32.s8 == m16n8k16.f16 -> same ldsm addressing.
// ============================================================================
template<int KVAL>
__device__ __forceinline__ void gemm_s8(
    const int8_t* __restrict__ A, const int8_t* __restrict__ B,
    int lda, int ldb, __half* __restrict__ C, int ldc,
    int tm0, int tn0)
{
    constexpr int T = KVAL / 128;     // 8
    constexpr int STAGES = 3;
    constexpr uint32_t STAGE = 32768u;

    extern __shared__ __align__(16) char smem[];
    const uint32_t sbase = smem_u32(smem);

    const int tid  = threadIdx.x;
    const int lane = tid & 31;
    const int warp = tid >> 5;
    const int wm = warp & 3;
    const int wn = warp >> 2;

    uint32_t dA[4], gA[4], gB[4];
    #pragma unroll
    for (int i = 0; i < 4; ++i) {
        const int slot = tid + i * 256;
        const int r = slot >> 3, c = slot & 7;
        dA[i] = (uint32_t)(r * 128 + ((c ^ (r & 7)) << 4));
        gA[i] = (uint32_t)((tm0 + r) * lda + c * 16);
        gB[i] = (uint32_t)((tn0 + r) * ldb + c * 16);
    }

    const uint32_t kcoA = (lane >> 4) & 1;
    uint32_t aoff[2], asw[2];
    {
        const int roff = (lane & 7) + (((lane >> 3) & 1) << 3);
        #pragma unroll
        for (int mi = 0; mi < 2; ++mi) {
            const int r = wm * 32 + mi * 16 + roff;
            aoff[mi] = (uint32_t)(r * 128);
            asw[mi]  = (uint32_t)(r & 7);
        }
    }
    const uint32_t kcoB = (lane >> 3) & 1;
    uint32_t boff[4], bsw[4];
    {
        const int noff = (lane & 7) + (((lane >> 4) & 1) << 3);
        #pragma unroll
        for (int p = 0; p < 4; ++p) {
            const int r = wn * 64 + p * 16 + noff;
            boff[p] = (uint32_t)(r * 128);
            bsw[p]  = (uint32_t)(r & 7);
        }
    }

    int acc[2][8][4];
    #pragma unroll
    for (int mi = 0; mi < 2; ++mi)
        #pragma unroll
        for (int ni = 0; ni < 8; ++ni)
            #pragma unroll
            for (int j = 0; j < 4; ++j) acc[mi][ni][j] = 0;

    auto issue = [&](int t) {
        const int k0 = t * 128;
        const uint32_t s = sbase + (uint32_t)(t % STAGES) * STAGE;
        #pragma unroll
        for (int i = 0; i < 4; ++i) {
            cpa16(s + dA[i], A + gA[i] + k0);
            cpa16(s + 16384u + dA[i], B + gB[i] + k0);
        }
    };

    #pragma unroll
    for (int s = 0; s < STAGES - 1; ++s) {
        if (s < T) issue(s);
        asm volatile("cp.async.commit_group;");
    }

    for (int t = 0; t < T; ++t) {
        asm volatile("cp.async.wait_group 1;");
        __syncthreads();
        if (t + STAGES - 1 < T) issue(t + STAGES - 1);
        asm volatile("cp.async.commit_group;");

        const uint32_t sA = sbase + (uint32_t)(t % STAGES) * STAGE;
        const uint32_t sB = sA + 16384u;
        #pragma unroll
        for (int kk = 0; kk < 4; ++kk) {   // 4 k-steps of K=32 bytes
            uint32_t a[2][4];
            #pragma unroll
            for (int mi = 0; mi < 2; ++mi)
                ldsm4(a[mi][0], a[mi][1], a[mi][2], a[mi][3],
                      sA + aoff[mi] + ((((uint32_t)(2 * kk) + kcoA) ^ asw[mi]) << 4));
            uint32_t b[4][4];
            #pragma unroll
            for (int p = 0; p < 4; ++p)
                ldsm4(b[p][0], b[p][1], b[p][2], b[p][3],
                      sB + boff[p] + ((((uint32_t)(2 * kk) + kcoB) ^ bsw[p]) << 4));
            #pragma unroll
            for (int mi = 0; mi < 2; ++mi)
                #pragma unroll
                for (int p = 0; p < 4; ++p) {
                    mma_s8(acc[mi][2 * p],     a[mi], b[p][0], b[p][1]);
                    mma_s8(acc[mi][2 * p + 1], a[mi], b[p][2], b[p][3]);
                }
        }
    }

    const int gid = lane >> 2, qid = lane & 3;
    #pragma unroll
    for (int mi = 0; mi < 2; ++mi) {
        #pragma unroll
        for (int ni = 0; ni < 8; ++ni) {
            const int r = tm0 + wm * 32 + mi * 16 + gid;
            const int c = tn0 + wn * 64 + ni * 8 + qid * 2;
            const float v0 = (float)acc[mi][ni][0] * SSCALE;
            const float v1 = (float)acc[mi][ni][1] * SSCALE;
            const float v2 = (float)acc[mi][ni][2] * SSCALE;
            const float v3 = (float)acc[mi][ni][3] * SSCALE;
            *reinterpret_cast<__half2*>(C + (size_t)r * ldc + c) =
                __halves2half2(__float2half_rn(v0), __float2half_rn(v1));
            *reinterpret_cast<__half2*>(C + (size_t)(r + 8) * ldc + c) =
                __halves2half2(__float2half_rn(v2), __float2half_rn(v3));
        }
    }
}

// ----------------------------------------------------------------------------
// prep kernels
// ----------------------------------------------------------------------------
__device__ __forceinline__ void split4(const float4 v, __half2* dh, __half2* dl) {
    const __half h0 = __float2half_rn(v.x), h1 = __float2half_rn(v.y);
    const __half h2 = __float2half_rn(v.z), h3 = __float2half_rn(v.w);
    dh[0] = __halves2half2(h0, h1);
    dh[1] = __halves2half2(h2, h3);
    dl[0] = __halves2half2(__float2half_rn(v.x - __half2float(h0)),
                           __float2half_rn(v.y - __half2float(h1)));
    dl[1] = __halves2half2(__float2half_rn(v.z - __half2float(h2)),
                           __float2half_rn(v.w - __half2float(h3)));
}

__global__ __launch_bounds__(256)
void split_x_kernel(const float* __restrict__ src)
{
    const int i = blockIdx.x * blockDim.x + threadIdx.x;
    const float4 v = reinterpret_cast<const float4*>(src)[i];
    split4(v, reinterpret_cast<__half2*>(g_xh) + 2 * i,
              reinterpret_cast<__half2*>(g_xl) + 2 * i);
    char4 q;
    q.x = quant8(v.x); q.y = quant8(v.y);
    q.z = quant8(v.z); q.w = quant8(v.w);
    reinterpret_cast<char4*>(g_xq)[i] = q;
}

// z=0: Wk split ; z=1: Wv fp16 convert
__global__ __launch_bounds__(256)
void wkv_prep_kernel(const float* __restrict__ Wk, const float* __restrict__ Wv)
{
    const int i = blockIdx.x * blockDim.x + threadIdx.x;
    if (blockIdx.z == 0) {
        const float4 v = reinterpret_cast<const float4*>(Wk)[i];
        split4(v, reinterpret_cast<__half2*>(g_wk_h) + 2 * i,
                  reinterpret_cast<__half2*>(g_wk_l) + 2 * i);
    } else {
        const float4 v = reinterpret_cast<const float4*>(Wv)[i];
        reinterpret_cast<__half2*>(g_wv_h)[2 * i] =
            __halves2half2(__float2half_rn(v.x), __float2half_rn(v.y));
        reinterpret_cast<__half2*>(g_wv_h)[2 * i + 1] =
            __halves2half2(__float2half_rn(v.z), __float2half_rn(v.w));
    }
}

__global__ __launch_bounds__(256)
void wq_transpose_kernel(const float* __restrict__ Wq)
{
    __shared__ float s[32][33];
    const int a0 = blockIdx.x * 32, d0 = blockIdx.y * 32;
    const int tx = threadIdx.x & 31, ty = threadIdx.x >> 5;
    #pragma unroll
    for (int i = 0; i < 4; ++i) {
        const int d = d0 + ty + 8 * i;
        s[ty + 8 * i][tx] = Wq[(size_t)d * HID + a0 + tx];
    }
    __syncthreads();
    #pragma unroll
    for (int i = 0; i < 4; ++i) {
        const int a = a0 + ty + 8 * i;
        const float v = s[tx][ty + 8 * i];
        const __half h = __float2half_rn(v);
        g_wqt_h[(size_t)a * HID + d0 + tx] = h;
        g_wqt_l[(size_t)a * HID + d0 + tx] =
            __float2half_rn(v - __half2float(h));
    }
}

__global__ __launch_bounds__(256)
void t2_kernel(const float* __restrict__ Wk, const float* __restrict__ bq)
{
    const int a = blockIdx.x * 256 + threadIdx.x;
    float acc = 0.f;
    #pragma unroll 8
    for (int d = 0; d < HID; ++d)
        acc += Wk[(size_t)d * HID + a] * bq[d];
    g_t2[a] = acc;
}

__global__ __launch_bounds__(128)
void w_kernel(const float* __restrict__ x)
{
    const int warp = threadIdx.x >> 5, lane = threadIdx.x & 31;
    const int row = blockIdx.x * 4 + warp;
    const float* xr = x + (size_t)row * HID;
    float s = 0.f;
    for (int a = lane; a < HID; a += 32) s += xr[a] * g_t2[a];
    #pragma unroll
    for (int off = 16; off; off >>= 1)
        s += __shfl_xor_sync(0xffffffffu, s, off);
    if (lane == 0) g_w[row] = s;
}

// ----------------------------------------------------------------------------
// GEMM kernels
// ----------------------------------------------------------------------------
__global__ __launch_bounds__(256, 2)
void mv_kernel(const float* __restrict__ bv)
{
    if (blockIdx.y < 8)
        gemm_main<1024, 3, true, 1>(g_wqt_h, g_wqt_l, g_wk_h, g_wk_l, HID, HID,
                                    nullptr, g_mh, g_ml, g_zero, HID,
                                    blockIdx.y * 128, blockIdx.x * 128);
    else
        gemm_main<1024, 1, false, 2>(g_xh, nullptr, g_wv_h, nullptr, HID, HID,
                                     nullptr, g_vh, nullptr, bv, HID,
                                     (blockIdx.y - 8) * 128, blockIdx.x * 128);
}

__global__ __launch_bounds__(256, 2)
void y_kernel()   // y = x M  (split3) -> yh/yl + int8 yq
{
    gemm_main<1024, 3, true, 4>(g_xh, g_xl, g_mh, g_ml, HID, HID,
                                nullptr, g_yh, g_yl, g_zero, HID,
                                blockIdx.y * 128, blockIdx.x * 128);
}

__global__ __launch_bounds__(256, 2)
void scores_kernel()   // approx s = yq xq^T (int8 TN) -> fp16
{
    const size_t bo = (size_t)blockIdx.z * SEQ * HID;
    gemm_s8<1024>(g_yq + bo, g_xq + bo, HID, HID,
                  g_s + (size_t)blockIdx.z * SEQ * SEQ, SEQ,
                  blockIdx.y * 128, blockIdx.x * 128);
}

// ----------------------------------------------------------------------------
// Fused gate + exact rescore + softmax + P.v gather.
// int8 approx err rms ~0.8 -> margin 22.5 (15+ sigma safety for any
// candidate that matters).  Exact rescore in fp32, exact gate max-17.
// ----------------------------------------------------------------------------
__global__ __launch_bounds__(256)
void softmax_rescore_pv_kernel(float* __restrict__ out)
{
    const int row = blockIdx.x;
    const int batch = row >> 11;
    const int wbase = batch << 11;
    const __half* srow = g_s + (size_t)row * SEQ;
    const int t = threadIdx.x, lane = t & 31, wid = t >> 5;

    __shared__ float red[8];
    __shared__ int   s_wtot[8];
    __shared__ int   s_wbase[8];
    __shared__ int   s_ncand;
    __shared__ int   s_idx[SEQ];
    __shared__ float s_logit[SEQ];
    __shared__ float s_y[HID];

    {
        const __half2* yh2 = reinterpret_cast<const __half2*>(g_yh + (size_t)row * HID);
        const __half2* yl2 = reinterpret_cast<const __half2*>(g_yl + (size_t)row * HID);
        #pragma unroll
        for (int i = 0; i < 2; ++i) {
            const int k = t + i * 256;
            const float2 h = __half22float2(yh2[k]);
            const float2 l = __half22float2(yl2[k]);
            s_y[2 * k]     = h.x + l.x;
            s_y[2 * k + 1] = h.y + l.y;
        }
    }

    float av[8];
    {
        const float4 w0 = *reinterpret_cast<const float4*>(g_w + wbase + 4 * t);
        const float4 w1 = *reinterpret_cast<const float4*>(g_w + wbase + 1024 + 4 * t);
        const __half2* s2 = reinterpret_cast<const __half2*>(srow);
        const float2 a0 = __half22float2(s2[2 * t]);
        const float2 a1 = __half22float2(s2[2 * t + 1]);
        const float2 a2 = __half22float2(s2[512 + 2 * t]);
        const float2 a3 = __half22float2(s2[512 + 2 * t + 1]);
        av[0] = a0.x + w0.x; av[1] = a0.y + w0.y;
        av[2] = a1.x + w0.z; av[3] = a1.y + w0.w;
        av[4] = a2.x + w1.x; av[5] = a2.y + w1.y;
        av[6] = a3.x + w1.z; av[7] = a3.y + w1.w;
    }
    int cols[8];
    cols[0] = 4 * t;           cols[1] = 4 * t + 1;
    cols[2] = 4 * t + 2;       cols[3] = 4 * t + 3;
    cols[4] = 1024 + 4 * t;    cols[5] = 1024 + 4 * t + 1;
    cols[6] = 1024 + 4 * t + 2; cols[7] = 1024 + 4 * t + 3;

    float m = av[0];
    #pragma unroll
    for (int j = 1; j < 8; ++j) m = fmaxf(m, av[j]);
    #pragma unroll
    for (int off = 16; off; off >>= 1)
        m = fmaxf(m, __shfl_xor_sync(0xffffffffu, m, off));
    if (lane == 0) red[wid] = m;
    __syncthreads();
    if (t < 8) {
        float mm = red[t];
        #pragma unroll
        for (int off = 4; off; off >>= 1)
            mm = fmaxf(mm, __shfl_xor_sync(0xffu, mm, off));
        if (t == 0) red[0] = mm;
    }
    __syncthreads();
    m = red[0];
    __syncthreads();

    const float thr = m - 22.5f;    // margin covers int8 approx error tail

    int cnt = 0;
    #pragma unroll
    for (int j = 0; j < 8; ++j)
        if (av[j] > thr) cnt++;
    int inc = cnt;
    #pragma unroll
    for (int off = 1; off < 32; off <<= 1) {
        int n = __shfl_up_sync(0xffffffffu, inc, off);
        if (lane >= off) inc += n;
    }
    if (lane == 31) s_wtot[wid] = inc;
    __syncthreads();
    if (t == 0) {
        int run = 0;
        #pragma unroll
        for (int wI = 0; wI < 8; ++wI) {
            s_wbase[wI] = run;
            run += s_wtot[wI];
        }
        s_ncand = run;
    }
    __syncthreads();
    int ofs = s_wbase[wid] + (inc - cnt);
    #pragma unroll
    for (int j = 0; j < 8; ++j) {
        if (av[j] > thr) {
            s_idx[ofs] = cols[j];
            ofs++;
        }
    }
    __syncthreads();
    const int ncand = s_ncand;

    for (int k = wid; k < ncand; k += 8) {
        const int j = s_idx[k];
        const __half2* xh2 = reinterpret_cast<const __half2*>(
            g_xh + (size_t)(wbase + j) * HID);
        const __half2* xl2 = reinterpret_cast<const __half2*>(
            g_xl + (size_t)(wbase + j) * HID);
        float part = 0.f;
        for (int d = lane; d < 512; d += 32) {
            const float2 h = __half22float2(xh2[d]);
            const float2 l = __half22float2(xl2[d]);
            part += s_y[2 * d] * (h.x + l.x) + s_y[2 * d + 1] * (h.y + l.y);
        }
        #pragma unroll
        for (int off = 16; off; off >>= 1)
            part += __shfl_xor_sync(0xffffffffu, part, off);
        if (lane == 0) s_logit[k] = part + g_w[wbase + j];
    }
    __syncthreads();

    float m2 = -3.4e38f;
    for (int k = t; k < ncand; k += 256) m2 = fmaxf(m2, s_logit[k]);
    #pragma unroll
    for (int off = 16; off; off >>= 1)
        m2 = fmaxf(m2, __shfl_xor_sync(0xffffffffu, m2, off));
    if (lane == 0) red[wid] = m2;
    __syncthreads();
    if (t < 8) {
        float mm = red[t];
        #pragma unroll
        for (int off = 4; off; off >>= 1)
            mm = fmaxf(mm, __shfl_xor_sync(0xffu, mm, off));
        if (t == 0) red[0] = mm;
    }
    __syncthreads();
    m2 = red[0];
    __syncthreads();

    const float thr2 = m2 - 17.0f;
    float ssum = 0.f;
    for (int k = t; k < ncand; k += 256) {
        const float l = s_logit[k];
        const float e = (l > thr2) ? __expf(l - m2) : 0.f;
        s_logit[k] = e;
        ssum += e;
    }
    #pragma unroll
    for (int off = 16; off; off >>= 1)
        ssum += __shfl_xor_sync(0xffffffffu, ssum, off);
    if (lane == 0) red[wid] = ssum;
    __syncthreads();
    if (t < 8) {
        float ss = red[t];
        #pragma unroll
        for (int off = 4; off; off >>= 1)
            ss += __shfl_xor_sync(0xffu, ss, off);
        if (t == 0) red[0] = ss;
    }
    __syncthreads();
    const float inv = 1.0f / red[0];
    __syncthreads();

    const __half* vbase = g_vh + (size_t)batch * SEQ * HID;
    float acc0 = 0.f, acc1 = 0.f, acc2 = 0.f, acc3 = 0.f;
    for (int k = 0; k < ncand; ++k) {
        const float pv = s_logit[k] * inv;
        if (pv != 0.f) {
            const __half2* vr = reinterpret_cast<const __half2*>(
                vbase + (size_t)s_idx[k] * HID) + 2 * t;
            const float2 f0 = __half22float2(vr[0]);
            const float2 f1 = __half22float2(vr[1]);
            acc0 += pv * f0.x; acc1 += pv * f0.y;
            acc2 += pv * f1.x; acc3 += pv * f1.y;
        }
    }
    float4 o;
    o.x = acc0; o.y = acc1; o.z = acc2; o.w = acc3;
    *reinterpret_cast<float4*>(out + (size_t)row * HID + 4 * t) = o;
}

// ----------------------------------------------------------------------------
// launch
// ----------------------------------------------------------------------------
#define GEMM_SMEM 98304

extern "C" void kernel_launch(void* const* d_in, const int* in_sizes, int n_in,
                              void* d_out, int out_size)
{
    (void)in_sizes; (void)n_in; (void)out_size;
    const float* x  = (const float*)d_in[0];
    const float* Wq = (const float*)d_in[1];
    const float* bq = (const float*)d_in[2];
    const float* Wk = (const float*)d_in[3];
    const float* Wv = (const float*)d_in[5];
    const float* bv = (const float*)d_in[6];
    float* out = (float*)d_out;

    cudaFuncSetAttribute(mv_kernel,
        cudaFuncAttributeMaxDynamicSharedMemorySize, GEMM_SMEM);
    cudaFuncSetAttribute(y_kernel,
        cudaFuncAttributeMaxDynamicSharedMemorySize, GEMM_SMEM);
    cudaFuncSetAttribute(scores_kernel,
        cudaFuncAttributeMaxDynamicSharedMemorySize, GEMM_SMEM);

    // 0) prep
    split_x_kernel<<<MTOT * HID / 4 / 256, 256>>>(x);
    wq_transpose_kernel<<<dim3(HID / 32, HID / 32), 256>>>(Wq);
    wkv_prep_kernel<<<dim3(HID * HID / 4 / 256, 1, 2), 256>>>(Wk, Wv);
    t2_kernel<<<HID / 256, 256>>>(Wk, bq);
    w_kernel<<<MTOT / 4, 128>>>(x);

    // 1) merged: M = Wq^T Wk (split3) + v = x Wv^T + bv (1x)
    mv_kernel<<<dim3(HID / 128, 8 + MTOT / 128), 256, GEMM_SMEM>>>(bv);
    // 2) y = x M (split3) -> yh/yl + yq
    y_kernel<<<dim3(HID / 128, MTOT / 128), 256, GEMM_SMEM>>>();
    // 3) approx scores = yq xq^T (int8) -> fp16
    scores_kernel<<<dim3(SEQ / 128, SEQ / 128, BATCH), 256, GEMM_SMEM>>>();
    // 4) fused gate + exact rescore + softmax + sparse P.v gather -> out
    softmax_rescore_pv_kernel<<<BATCH * SEQ, 256>>>(out);
}

// round 15
// speedup vs baseline: 1.7703x; 1.1085x over previous
#include <cuda_runtime.h>
#include <cuda_fp16.h>
#include <cstdint>

// ============================================================================
// SelfAttention: out = softmax( (xWq^T+bq)(xWk^T+bk)^T ) (xWv^T+bv)
// B=4, S=2048, H=1024 (fp32 in/out)
// q_i.k_j = x_i (Wq^T Wk) x_j^T + rowconst + w_j ; rowconst cancels.
// M = Wq^T Wk + v = x.Wv^T+bv (merged); y = x.M (split3, also emits int8 yq).
// Scores: APPROX INT8 GEMM gate (margin 22.5); candidates rescored exactly in
// fp32 then exp/normalize/gather-v in one fused kernel.
// This round: t2 = Wk^T bq parallelized (2-stage deterministic reduction;
// was an 82us 4-CTA latency hole).
// ============================================================================

#define BATCH 4
#define SEQ   2048
#define HID   1024
#define MTOT  (BATCH*SEQ)          // 8192

#define QINV   (127.0f/8.0f)
#define SSCALE ((8.0f/127.0f)*(8.0f/127.0f))

// ---- scratch (device globals; allocation-free per harness rules) ----
__device__ __half g_xh[(size_t)MTOT * HID];
__device__ __half g_xl[(size_t)MTOT * HID];
__device__ int8_t g_xq[(size_t)MTOT * HID];
__device__ __half g_wqt_h[(size_t)HID * HID];
__device__ __half g_wqt_l[(size_t)HID * HID];
__device__ __half g_wk_h[(size_t)HID * HID];
__device__ __half g_wk_l[(size_t)HID * HID];
__device__ __half g_wv_h[(size_t)HID * HID];
__device__ __half g_mh[(size_t)HID * HID];
__device__ __half g_ml[(size_t)HID * HID];
__device__ __half g_yh[(size_t)MTOT * HID];
__device__ __half g_yl[(size_t)MTOT * HID];
__device__ int8_t g_yq[(size_t)MTOT * HID];
__device__ __half g_vh[(size_t)MTOT * HID];
__device__ __half g_s [(size_t)BATCH * SEQ * SEQ];
__device__ float  g_w [MTOT];
__device__ float  g_t2[HID];
__device__ float  g_t2p[32][HID];
__device__ float  g_zero[HID];

// ----------------------------------------------------------------------------
// helpers
// ----------------------------------------------------------------------------
__device__ __forceinline__ uint32_t smem_u32(const void* p) {
    uint32_t a;
    asm("{ .reg .u64 t; cvta.to.shared.u64 t, %1; cvt.u32.u64 %0, t; }"
        : "=r"(a) : "l"(p));
    return a;
}

__device__ __forceinline__ void cpa16(uint32_t dst, const void* src) {
    asm volatile("cp.async.cg.shared.global [%0], [%1], 16;"
                 :: "r"(dst), "l"(src));
}

__device__ __forceinline__ void ldsm4(uint32_t& r0, uint32_t& r1,
                                      uint32_t& r2, uint32_t& r3, uint32_t a) {
    asm volatile("ldmatrix.sync.aligned.m8n8.x4.shared.b16 {%0,%1,%2,%3}, [%4];"
                 : "=r"(r0), "=r"(r1), "=r"(r2), "=r"(r3) : "r"(a));
}
__device__ __forceinline__ void ldsm4t(uint32_t& r0, uint32_t& r1,
                                       uint32_t& r2, uint32_t& r3, uint32_t a) {
    asm volatile("ldmatrix.sync.aligned.m8n8.x4.trans.shared.b16 {%0,%1,%2,%3}, [%4];"
                 : "=r"(r0), "=r"(r1), "=r"(r2), "=r"(r3) : "r"(a));
}

__device__ __forceinline__ void mma16816(float c[4], const uint32_t a[4],
                                         uint32_t b0, uint32_t b1) {
    asm volatile(
        "mma.sync.aligned.m16n8k16.row.col.f32.f16.f16.f32 "
        "{%0,%1,%2,%3}, {%4,%5,%6,%7}, {%8,%9}, {%0,%1,%2,%3};\n"
        : "+f"(c[0]), "+f"(c[1]), "+f"(c[2]), "+f"(c[3])
        : "r"(a[0]), "r"(a[1]), "r"(a[2]), "r"(a[3]), "r"(b0), "r"(b1));
}

__device__ __forceinline__ void mma_s8(int c[4], const uint32_t a[4],
                                       uint32_t b0, uint32_t b1) {
    asm volatile(
        "mma.sync.aligned.m16n8k32.row.col.s32.s8.s8.s32 "
        "{%0,%1,%2,%3}, {%4,%5,%6,%7}, {%8,%9}, {%0,%1,%2,%3};\n"
        : "+r"(c[0]), "+r"(c[1]), "+r"(c[2]), "+r"(c[3])
        : "r"(a[0]), "r"(a[1]), "r"(a[2]), "r"(a[3]), "r"(b0), "r"(b1));
}

__device__ __forceinline__ int8_t quant8(float x) {
    const float q = fminf(fmaxf(x * QINV, -127.f), 127.f);
    return (int8_t)__float2int_rn(q);
}

// ============================================================================
// FP16 GEMM core: 128x128 tile, BK=64, 3-stage cp.async.
//   EPI: 0 fp32 | 1 bias + split half | 2 bias + half | 4 split half + int8
// ============================================================================
template<int KVAL, int NSPLIT, bool BNN, int EPI>
__device__ __forceinline__ void gemm_main(
    const __half* __restrict__ Ah, const __half* __restrict__ Al,
    const __half* __restrict__ Bh, const __half* __restrict__ Bl,
    int lda, int ldb,
    float* __restrict__ Cf, __half* __restrict__ Ch, __half* __restrict__ Cl,
    const float* __restrict__ bias, int ldc,
    int tm0, int tn0)
{
    constexpr int NC = KVAL / 64;
    constexpr int T  = NSPLIT * NC;
    constexpr int STAGES = 3;
    constexpr uint32_t STAGE = 32768u;

    extern __shared__ __align__(16) char smem[];
    const uint32_t sbase = smem_u32(smem);

    const int tid  = threadIdx.x;
    const int lane = tid & 31;
    const int warp = tid >> 5;
    const int wm = warp & 3;
    const int wn = warp >> 2;

    uint32_t dA[4], gA[4], dB[4], gB[4];
    #pragma unroll
    for (int i = 0; i < 4; ++i) {
        const int slot = tid + i * 256;
        { const int r = slot >> 3, c = slot & 7;
          dA[i] = (uint32_t)(r * 128 + ((c ^ (r & 7)) << 4));
          gA[i] = (uint32_t)((tm0 + r) * lda + c * 8); }
        if (!BNN) {
            const int r = slot >> 3, c = slot & 7;
            dB[i] = (uint32_t)(r * 128 + ((c ^ (r & 7)) << 4));
            gB[i] = (uint32_t)((tn0 + r) * ldb + c * 8);
        } else {
            const int r = slot >> 4, c = slot & 15;
            dB[i] = (uint32_t)(r * 256 + ((c ^ (r & 7)) << 4));
            gB[i] = (uint32_t)(r * ldb + tn0 + c * 8);
        }
    }

    const __half* const Alist[3] = {Ah, Ah, Al};
    const __half* const Blist[3] = {Bh, Bl, Bh};

    const uint32_t kcoA = (lane >> 4) & 1;
    uint32_t aoff[2], asw[2];
    {
        const int roff = (lane & 7) + (((lane >> 3) & 1) << 3);
        #pragma unroll
        for (int mi = 0; mi < 2; ++mi) {
            const int r = wm * 32 + mi * 16 + roff;
            aoff[mi] = (uint32_t)(r * 128);
            asw[mi]  = (uint32_t)(r & 7);
        }
    }
    const uint32_t kcoB = (lane >> 3) & 1;
    uint32_t boff[4], bsw[4];
    uint32_t bco[4], bkoff = 0;
    if (!BNN) {
        const int noff = (lane & 7) + (((lane >> 4) & 1) << 3);
        #pragma unroll
        for (int p = 0; p < 4; ++p) {
            const int r = wn * 64 + p * 16 + noff;
            boff[p] = (uint32_t)(r * 128);
            bsw[p]  = (uint32_t)(r & 7);
        }
    } else {
        const int koff = (lane & 7) + (((lane >> 3) & 1) << 3);
        bkoff = (uint32_t)(koff * 256);
        const int ncsel = (lane >> 4) & 1;
        #pragma unroll
        for (int p = 0; p < 4; ++p) {
            const int ncb = wn * 8 + p * 2 + ncsel;
            bco[p] = (uint32_t)((ncb ^ (lane & 7)) << 4);
        }
    }

    float acc[2][8][4];
    #pragma unroll
    for (int mi = 0; mi < 2; ++mi)
        #pragma unroll
        for (int ni = 0; ni < 8; ++ni)
            #pragma unroll
            for (int j = 0; j < 4; ++j) acc[mi][ni][j] = 0.f;

    auto issue = [&](int t) {
        int comp, kc;
        if (NSPLIT == 1) { comp = 0; kc = t; }
        else             { comp = t / NC; kc = t - comp * NC; }
        const int k0 = kc * 64;
        const __half* Ap = Alist[comp];
        const __half* Bp = Blist[comp];
        const uint32_t s = sbase + (uint32_t)(t % STAGES) * STAGE;
        #pragma unroll
        for (int i = 0; i < 4; ++i) {
            cpa16(s + dA[i], Ap + gA[i] + k0);
            if (!BNN) cpa16(s + 16384u + dB[i], Bp + gB[i] + k0);
            else      cpa16(s + 16384u + dB[i], Bp + gB[i] + (size_t)k0 * ldb);
        }
    };

    #pragma unroll
    for (int s = 0; s < STAGES - 1; ++s) {
        if (s < T) issue(s);
        asm volatile("cp.async.commit_group;");
    }

    for (int t = 0; t < T; ++t) {
        asm volatile("cp.async.wait_group 1;");
        __syncthreads();
        if (t + STAGES - 1 < T) issue(t + STAGES - 1);
        asm volatile("cp.async.commit_group;");

        const uint32_t sA = sbase + (uint32_t)(t % STAGES) * STAGE;
        const uint32_t sB = sA + 16384u;
        #pragma unroll
        for (int kk = 0; kk < 4; ++kk) {
            uint32_t a[2][4];
            #pragma unroll
            for (int mi = 0; mi < 2; ++mi)
                ldsm4(a[mi][0], a[mi][1], a[mi][2], a[mi][3],
                      sA + aoff[mi] + ((((uint32_t)(2 * kk) + kcoA) ^ asw[mi]) << 4));
            uint32_t b[4][4];
            #pragma unroll
            for (int p = 0; p < 4; ++p) {
                if (!BNN)
                    ldsm4(b[p][0], b[p][1], b[p][2], b[p][3],
                          sB + boff[p] + ((((uint32_t)(2 * kk) + kcoB) ^ bsw[p]) << 4));
                else
                    ldsm4t(b[p][0], b[p][1], b[p][2], b[p][3],
                           sB + (uint32_t)kk * 4096u + bkoff + bco[p]);
            }
            #pragma unroll
            for (int mi = 0; mi < 2; ++mi)
                #pragma unroll
                for (int p = 0; p < 4; ++p) {
                    mma16816(acc[mi][2 * p],     a[mi], b[p][0], b[p][1]);
                    mma16816(acc[mi][2 * p + 1], a[mi], b[p][2], b[p][3]);
                }
        }
    }

    const int gid = lane >> 2, qid = lane & 3;
    #pragma unroll
    for (int mi = 0; mi < 2; ++mi) {
        #pragma unroll
        for (int ni = 0; ni < 8; ++ni) {
            const int r = tm0 + wm * 32 + mi * 16 + gid;
            const int c = tn0 + wn * 64 + ni * 8 + qid * 2;
            float v0 = acc[mi][ni][0], v1 = acc[mi][ni][1];
            float v2 = acc[mi][ni][2], v3 = acc[mi][ni][3];
            if (EPI == 1 || EPI == 2) {
                const float2 bb = *reinterpret_cast<const float2*>(bias + c);
                v0 += bb.x; v1 += bb.y; v2 += bb.x; v3 += bb.y;
            }
            if (EPI == 0) {
                *reinterpret_cast<float2*>(Cf + (size_t)r * ldc + c) =
                    make_float2(v0, v1);
                *reinterpret_cast<float2*>(Cf + (size_t)(r + 8) * ldc + c) =
                    make_float2(v2, v3);
            } else if (EPI == 2) {
                *reinterpret_cast<__half2*>(Ch + (size_t)r * ldc + c) =
                    __halves2half2(__float2half_rn(v0), __float2half_rn(v1));
                *reinterpret_cast<__half2*>(Ch + (size_t)(r + 8) * ldc + c) =
                    __halves2half2(__float2half_rn(v2), __float2half_rn(v3));
            } else {
                const __half h0 = __float2half_rn(v0), h1 = __float2half_rn(v1);
                const __half h2 = __float2half_rn(v2), h3 = __float2half_rn(v3);
                *reinterpret_cast<__half2*>(Ch + (size_t)r * ldc + c) =
                    __halves2half2(h0, h1);
                *reinterpret_cast<__half2*>(Ch + (size_t)(r + 8) * ldc + c) =
                    __halves2half2(h2, h3);
                *reinterpret_cast<__half2*>(Cl + (size_t)r * ldc + c) =
                    __halves2half2(__float2half_rn(v0 - __half2float(h0)),
                                   __float2half_rn(v1 - __half2float(h1)));
                *reinterpret_cast<__half2*>(Cl + (size_t)(r + 8) * ldc + c) =
                    __halves2half2(__float2half_rn(v2 - __half2float(h2)),
                                   __float2half_rn(v3 - __half2float(h3)));
                if (EPI == 4) {
                    char2 q01; q01.x = quant8(v0); q01.y = quant8(v1);
                    char2 q23; q23.x = quant8(v2); q23.y = quant8(v3);
                    *reinterpret_cast<char2*>(g_yq + (size_t)r * ldc + c) = q01;
                    *reinterpret_cast<char2*>(g_yq + (size_t)(r + 8) * ldc + c) = q23;
                }
            }
        }
    }
}

// ============================================================================
// INT8 GEMM core (TN): s8 in, s32 accum, fp16 store with SSCALE.
// ============================================================================
template<int KVAL>
__device__ __forceinline__ void gemm_s8(
    const int8_t* __restrict__ A, const int8_t* __restrict__ B,
    int lda, int ldb, __half* __restrict__ C, int ldc,
    int tm0, int tn0)
{
    constexpr int T = KVAL / 128;
    constexpr int STAGES = 3;
    constexpr uint32_t STAGE = 32768u;

    extern __shared__ __align__(16) char smem[];
    const uint32_t sbase = smem_u32(smem);

    const int tid  = threadIdx.x;
    const int lane = tid & 31;
    const int warp = tid >> 5;
    const int wm = warp & 3;
    const int wn = warp >> 2;

    uint32_t dA[4], gA[4], gB[4];
    #pragma unroll
    for (int i = 0; i < 4; ++i) {
        const int slot = tid + i * 256;
        const int r = slot >> 3, c = slot & 7;
        dA[i] = (uint32_t)(r * 128 + ((c ^ (r & 7)) << 4));
        gA[i] = (uint32_t)((tm0 + r) * lda + c * 16);
        gB[i] = (uint32_t)((tn0 + r) * ldb + c * 16);
    }

    const uint32_t kcoA = (lane >> 4) & 1;
    uint32_t aoff[2], asw[2];
    {
        const int roff = (lane & 7) + (((lane >> 3) & 1) << 3);
        #pragma unroll
        for (int mi = 0; mi < 2; ++mi) {
            const int r = wm * 32 + mi * 16 + roff;
            aoff[mi] = (uint32_t)(r * 128);
            asw[mi]  = (uint32_t)(r & 7);
        }
    }
    const uint32_t kcoB = (lane >> 3) & 1;
    uint32_t boff[4], bsw[4];
    {
        const int noff = (lane & 7) + (((lane >> 4) & 1) << 3);
        #pragma unroll
        for (int p = 0; p < 4; ++p) {
            const int r = wn * 64 + p * 16 + noff;
            boff[p] = (uint32_t)(r * 128);
            bsw[p]  = (uint32_t)(r & 7);
        }
    }

    int acc[2][8][4];
    #pragma unroll
    for (int mi = 0; mi < 2; ++mi)
        #pragma unroll
        for (int ni = 0; ni < 8; ++ni)
            #pragma unroll
            for (int j = 0; j < 4; ++j) acc[mi][ni][j] = 0;

    auto issue = [&](int t) {
        const int k0 = t * 128;
        const uint32_t s = sbase + (uint32_t)(t % STAGES) * STAGE;
        #pragma unroll
        for (int i = 0; i < 4; ++i) {
            cpa16(s + dA[i], A + gA[i] + k0);
            cpa16(s + 16384u + dA[i], B + gB[i] + k0);
        }
    };

    #pragma unroll
    for (int s = 0; s < STAGES - 1; ++s) {
        if (s < T) issue(s);
        asm volatile("cp.async.commit_group;");
    }

    for (int t = 0; t < T; ++t) {
        asm volatile("cp.async.wait_group 1;");
        __syncthreads();
        if (t + STAGES - 1 < T) issue(t + STAGES - 1);
        asm volatile("cp.async.commit_group;");

        const uint32_t sA = sbase + (uint32_t)(t % STAGES) * STAGE;
        const uint32_t sB = sA + 16384u;
        #pragma unroll
        for (int kk = 0; kk < 4; ++kk) {
            uint32_t a[2][4];
            #pragma unroll
            for (int mi = 0; mi < 2; ++mi)
                ldsm4(a[mi][0], a[mi][1], a[mi][2], a[mi][3],
                      sA + aoff[mi] + ((((uint32_t)(2 * kk) + kcoA) ^ asw[mi]) << 4));
            uint32_t b[4][4];
            #pragma unroll
            for (int p = 0; p < 4; ++p)
                ldsm4(b[p][0], b[p][1], b[p][2], b[p][3],
                      sB + boff[p] + ((((uint32_t)(2 * kk) + kcoB) ^ bsw[p]) << 4));
            #pragma unroll
            for (int mi = 0; mi < 2; ++mi)
                #pragma unroll
                for (int p = 0; p < 4; ++p) {
                    mma_s8(acc[mi][2 * p],     a[mi], b[p][0], b[p][1]);
                    mma_s8(acc[mi][2 * p + 1], a[mi], b[p][2], b[p][3]);
                }
        }
    }

    const int gid = lane >> 2, qid = lane & 3;
    #pragma unroll
    for (int mi = 0; mi < 2; ++mi) {
        #pragma unroll
        for (int ni = 0; ni < 8; ++ni) {
            const int r = tm0 + wm * 32 + mi * 16 + gid;
            const int c = tn0 + wn * 64 + ni * 8 + qid * 2;
            const float v0 = (float)acc[mi][ni][0] * SSCALE;
            const float v1 = (float)acc[mi][ni][1] * SSCALE;
            const float v2 = (float)acc[mi][ni][2] * SSCALE;
            const float v3 = (float)acc[mi][ni][3] * SSCALE;
            *reinterpret_cast<__half2*>(C + (size_t)r * ldc + c) =
                __halves2half2(__float2half_rn(v0), __float2half_rn(v1));
            *reinterpret_cast<__half2*>(C + (size_t)(r + 8) * ldc + c) =
                __halves2half2(__float2half_rn(v2), __float2half_rn(v3));
        }
    }
}

// ----------------------------------------------------------------------------
// prep kernels
// ----------------------------------------------------------------------------
__device__ __forceinline__ void split4(const float4 v, __half2* dh, __half2* dl) {
    const __half h0 = __float2half_rn(v.x), h1 = __float2half_rn(v.y);
    const __half h2 = __float2half_rn(v.z), h3 = __float2half_rn(v.w);
    dh[0] = __halves2half2(h0, h1);
    dh[1] = __halves2half2(h2, h3);
    dl[0] = __halves2half2(__float2half_rn(v.x - __half2float(h0)),
                           __float2half_rn(v.y - __half2float(h1)));
    dl[1] = __halves2half2(__float2half_rn(v.z - __half2float(h2)),
                           __float2half_rn(v.w - __half2float(h3)));
}

__global__ __launch_bounds__(256)
void split_x_kernel(const float* __restrict__ src)
{
    const int i = blockIdx.x * blockDim.x + threadIdx.x;
    const float4 v = reinterpret_cast<const float4*>(src)[i];
    split4(v, reinterpret_cast<__half2*>(g_xh) + 2 * i,
              reinterpret_cast<__half2*>(g_xl) + 2 * i);
    char4 q;
    q.x = quant8(v.x); q.y = quant8(v.y);
    q.z = quant8(v.z); q.w = quant8(v.w);
    reinterpret_cast<char4*>(g_xq)[i] = q;
}

__global__ __launch_bounds__(256)
void wkv_prep_kernel(const float* __restrict__ Wk, const float* __restrict__ Wv)
{
    const int i = blockIdx.x * blockDim.x + threadIdx.x;
    if (blockIdx.z == 0) {
        const float4 v = reinterpret_cast<const float4*>(Wk)[i];
        split4(v, reinterpret_cast<__half2*>(g_wk_h) + 2 * i,
                  reinterpret_cast<__half2*>(g_wk_l) + 2 * i);
    } else {
        const float4 v = reinterpret_cast<const float4*>(Wv)[i];
        reinterpret_cast<__half2*>(g_wv_h)[2 * i] =
            __halves2half2(__float2half_rn(v.x), __float2half_rn(v.y));
        reinterpret_cast<__half2*>(g_wv_h)[2 * i + 1] =
            __halves2half2(__float2half_rn(v.z), __float2half_rn(v.w));
    }
}

__global__ __launch_bounds__(256)
void wq_transpose_kernel(const float* __restrict__ Wq)
{
    __shared__ float s[32][33];
    const int a0 = blockIdx.x * 32, d0 = blockIdx.y * 32;
    const int tx = threadIdx.x & 31, ty = threadIdx.x >> 5;
    #pragma unroll
    for (int i = 0; i < 4; ++i) {
        const int d = d0 + ty + 8 * i;
        s[ty + 8 * i][tx] = Wq[(size_t)d * HID + a0 + tx];
    }
    __syncthreads();
    #pragma unroll
    for (int i = 0; i < 4; ++i) {
        const int a = a0 + ty + 8 * i;
        const float v = s[tx][ty + 8 * i];
        const __half h = __float2half_rn(v);
        g_wqt_h[(size_t)a * HID + d0 + tx] = h;
        g_wqt_l[(size_t)a * HID + d0 + tx] =
            __float2half_rn(v - __half2float(h));
    }
}

// t2 = Wk^T bq : stage 1 — 128 CTAs, each reduces a 32-row d-slice
__global__ __launch_bounds__(256)
void t2_part_kernel(const float* __restrict__ Wk, const float* __restrict__ bq)
{
    const int a  = blockIdx.x * 256 + threadIdx.x;
    const int d0 = blockIdx.y * 32;
    float acc = 0.f;
    #pragma unroll
    for (int i = 0; i < 32; ++i)
        acc += Wk[(size_t)(d0 + i) * HID + a] * bq[d0 + i];
    g_t2p[blockIdx.y][a] = acc;
}

// t2 stage 2 — fixed-order sum of the 32 partials (deterministic)
__global__ __launch_bounds__(256)
void t2_reduce_kernel()
{
    const int a = blockIdx.x * 256 + threadIdx.x;
    float acc = 0.f;
    #pragma unroll
    for (int z = 0; z < 32; ++z)
        acc += g_t2p[z][a];
    g_t2[a] = acc;
}

__global__ __launch_bounds__(128)
void w_kernel(const float* __restrict__ x)
{
    const int warp = threadIdx.x >> 5, lane = threadIdx.x & 31;
    const int row = blockIdx.x * 4 + warp;
    const float* xr = x + (size_t)row * HID;
    float s = 0.f;
    for (int a = lane; a < HID; a += 32) s += xr[a] * g_t2[a];
    #pragma unroll
    for (int off = 16; off; off >>= 1)
        s += __shfl_xor_sync(0xffffffffu, s, off);
    if (lane == 0) g_w[row] = s;
}

// ----------------------------------------------------------------------------
// GEMM kernels
// ----------------------------------------------------------------------------
__global__ __launch_bounds__(256, 2)
void mv_kernel(const float* __restrict__ bv)
{
    if (blockIdx.y < 8)
        gemm_main<1024, 3, true, 1>(g_wqt_h, g_wqt_l, g_wk_h, g_wk_l, HID, HID,
                                    nullptr, g_mh, g_ml, g_zero, HID,
                                    blockIdx.y * 128, blockIdx.x * 128);
    else
        gemm_main<1024, 1, false, 2>(g_xh, nullptr, g_wv_h, nullptr, HID, HID,
                                     nullptr, g_vh, nullptr, bv, HID,
                                     (blockIdx.y - 8) * 128, blockIdx.x * 128);
}

__global__ __launch_bounds__(256, 2)
void y_kernel()
{
    gemm_main<1024, 3, true, 4>(g_xh, g_xl, g_mh, g_ml, HID, HID,
                                nullptr, g_yh, g_yl, g_zero, HID,
                                blockIdx.y * 128, blockIdx.x * 128);
}

__global__ __launch_bounds__(256, 2)
void scores_kernel()
{
    const size_t bo = (size_t)blockIdx.z * SEQ * HID;
    gemm_s8<1024>(g_yq + bo, g_xq + bo, HID, HID,
                  g_s + (size_t)blockIdx.z * SEQ * SEQ, SEQ,
                  blockIdx.y * 128, blockIdx.x * 128);
}

// ----------------------------------------------------------------------------
// Fused gate + exact rescore + softmax + P.v gather.
// ----------------------------------------------------------------------------
__global__ __launch_bounds__(256)
void softmax_rescore_pv_kernel(float* __restrict__ out)
{
    const int row = blockIdx.x;
    const int batch = row >> 11;
    const int wbase = batch << 11;
    const __half* srow = g_s + (size_t)row * SEQ;
    const int t = threadIdx.x, lane = t & 31, wid = t >> 5;

    __shared__ float red[8];
    __shared__ int   s_wtot[8];
    __shared__ int   s_wbase[8];
    __shared__ int   s_ncand;
    __shared__ int   s_idx[SEQ];
    __shared__ float s_logit[SEQ];
    __shared__ float s_y[HID];

    {
        const __half2* yh2 = reinterpret_cast<const __half2*>(g_yh + (size_t)row * HID);
        const __half2* yl2 = reinterpret_cast<const __half2*>(g_yl + (size_t)row * HID);
        #pragma unroll
        for (int i = 0; i < 2; ++i) {
            const int k = t + i * 256;
            const float2 h = __half22float2(yh2[k]);
            const float2 l = __half22float2(yl2[k]);
            s_y[2 * k]     = h.x + l.x;
            s_y[2 * k + 1] = h.y + l.y;
        }
    }

    float av[8];
    {
        const float4 w0 = *reinterpret_cast<const float4*>(g_w + wbase + 4 * t);
        const float4 w1 = *reinterpret_cast<const float4*>(g_w + wbase + 1024 + 4 * t);
        const __half2* s2 = reinterpret_cast<const __half2*>(srow);
        const float2 a0 = __half22float2(s2[2 * t]);
        const float2 a1 = __half22float2(s2[2 * t + 1]);
        const float2 a2 = __half22float2(s2[512 + 2 * t]);
        const float2 a3 = __half22float2(s2[512 + 2 * t + 1]);
        av[0] = a0.x + w0.x; av[1] = a0.y + w0.y;
        av[2] = a1.x + w0.z; av[3] = a1.y + w0.w;
        av[4] = a2.x + w1.x; av[5] = a2.y + w1.y;
        av[6] = a3.x + w1.z; av[7] = a3.y + w1.w;
    }
    int cols[8];
    cols[0] = 4 * t;           cols[1] = 4 * t + 1;
    cols[2] = 4 * t + 2;       cols[3] = 4 * t + 3;
    cols[4] = 1024 + 4 * t;    cols[5] = 1024 + 4 * t + 1;
    cols[6] = 1024 + 4 * t + 2; cols[7] = 1024 + 4 * t + 3;

    float m = av[0];
    #pragma unroll
    for (int j = 1; j < 8; ++j) m = fmaxf(m, av[j]);
    #pragma unroll
    for (int off = 16; off; off >>= 1)
        m = fmaxf(m, __shfl_xor_sync(0xffffffffu, m, off));
    if (lane == 0) red[wid] = m;
    __syncthreads();
    if (t < 8) {
        float mm = red[t];
        #pragma unroll
        for (int off = 4; off; off >>= 1)
            mm = fmaxf(mm, __shfl_xor_sync(0xffu, mm, off));
        if (t == 0) red[0] = mm;
    }
    __syncthreads();
    m = red[0];
    __syncthreads();

    const float thr = m - 22.5f;

    int cnt = 0;
    #pragma unroll
    for (int j = 0; j < 8; ++j)
        if (av[j] > thr) cnt++;
    int inc = cnt;
    #pragma unroll
    for (int off = 1; off < 32; off <<= 1) {
        int n = __shfl_up_sync(0xffffffffu, inc, off);
        if (lane >= off) inc += n;
    }
    if (lane == 31) s_wtot[wid] = inc;
    __syncthreads();
    if (t == 0) {
        int run = 0;
        #pragma unroll
        for (int wI = 0; wI < 8; ++wI) {
            s_wbase[wI] = run;
            run += s_wtot[wI];
        }
        s_ncand = run;
    }
    __syncthreads();
    int ofs = s_wbase[wid] + (inc - cnt);
    #pragma unroll
    for (int j = 0; j < 8; ++j) {
        if (av[j] > thr) {
            s_idx[ofs] = cols[j];
            ofs++;
        }
    }
    __syncthreads();
    const int ncand = s_ncand;

    for (int k = wid; k < ncand; k += 8) {
        const int j = s_idx[k];
        const __half2* xh2 = reinterpret_cast<const __half2*>(
            g_xh + (size_t)(wbase + j) * HID);
        const __half2* xl2 = reinterpret_cast<const __half2*>(
            g_xl + (size_t)(wbase + j) * HID);
        float part = 0.f;
        for (int d = lane; d < 512; d += 32) {
            const float2 h = __half22float2(xh2[d]);
            const float2 l = __half22float2(xl2[d]);
            part += s_y[2 * d] * (h.x + l.x) + s_y[2 * d + 1] * (h.y + l.y);
        }
        #pragma unroll
        for (int off = 16; off; off >>= 1)
            part += __shfl_xor_sync(0xffffffffu, part, off);
        if (lane == 0) s_logit[k] = part + g_w[wbase + j];
    }
    __syncthreads();

    float m2 = -3.4e38f;
    for (int k = t; k < ncand; k += 256) m2 = fmaxf(m2, s_logit[k]);
    #pragma unroll
    for (int off = 16; off; off >>= 1)
        m2 = fmaxf(m2, __shfl_xor_sync(0xffffffffu, m2, off));
    if (lane == 0) red[wid] = m2;
    __syncthreads();
    if (t < 8) {
        float mm = red[t];
        #pragma unroll
        for (int off = 4; off; off >>= 1)
            mm = fmaxf(mm, __shfl_xor_sync(0xffu, mm, off));
        if (t == 0) red[0] = mm;
    }
    __syncthreads();
    m2 = red[0];
    __syncthreads();

    const float thr2 = m2 - 17.0f;
    float ssum = 0.f;
    for (int k = t; k < ncand; k += 256) {
        const float l = s_logit[k];
        const float e = (l > thr2) ? __expf(l - m2) : 0.f;
        s_logit[k] = e;
        ssum += e;
    }
    #pragma unroll
    for (int off = 16; off; off >>= 1)
        ssum += __shfl_xor_sync(0xffffffffu, ssum, off);
    if (lane == 0) red[wid] = ssum;
    __syncthreads();
    if (t < 8) {
        float ss = red[t];
        #pragma unroll
        for (int off = 4; off; off >>= 1)
            ss += __shfl_xor_sync(0xffu, ss, off);
        if (t == 0) red[0] = ss;
    }
    __syncthreads();
    const float inv = 1.0f / red[0];
    __syncthreads();

    const __half* vbase = g_vh + (size_t)batch * SEQ * HID;
    float acc0 = 0.f, acc1 = 0.f, acc2 = 0.f, acc3 = 0.f;
    for (int k = 0; k < ncand; ++k) {
        const float pv = s_logit[k] * inv;
        if (pv != 0.f) {
            const __half2* vr = reinterpret_cast<const __half2*>(
                vbase + (size_t)s_idx[k] * HID) + 2 * t;
            const float2 f0 = __half22float2(vr[0]);
            const float2 f1 = __half22float2(vr[1]);
            acc0 += pv * f0.x; acc1 += pv * f0.y;
            acc2 += pv * f1.x; acc3 += pv * f1.y;
        }
    }
    float4 o;
    o.x = acc0; o.y = acc1; o.z = acc2; o.w = acc3;
    *reinterpret_cast<float4*>(out + (size_t)row * HID + 4 * t) = o;
}

// ----------------------------------------------------------------------------
// launch
// ----------------------------------------------------------------------------
#define GEMM_SMEM 98304

extern "C" void kernel_launch(void* const* d_in, const int* in_sizes, int n_in,
                              void* d_out, int out_size)
{
    (void)in_sizes; (void)n_in; (void)out_size;
    const float* x  = (const float*)d_in[0];
    const float* Wq = (const float*)d_in[1];
    const float* bq = (const float*)d_in[2];
    const float* Wk = (const float*)d_in[3];
    const float* Wv = (const float*)d_in[5];
    const float* bv = (const float*)d_in[6];
    float* out = (float*)d_out;

    cudaFuncSetAttribute(mv_kernel,
        cudaFuncAttributeMaxDynamicSharedMemorySize, GEMM_SMEM);
    cudaFuncSetAttribute(y_kernel,
        cudaFuncAttributeMaxDynamicSharedMemorySize, GEMM_SMEM);
    cudaFuncSetAttribute(scores_kernel,
        cudaFuncAttributeMaxDynamicSharedMemorySize, GEMM_SMEM);

    // 0) prep
    split_x_kernel<<<MTOT * HID / 4 / 256, 256>>>(x);
    wq_transpose_kernel<<<dim3(HID / 32, HID / 32), 256>>>(Wq);
    wkv_prep_kernel<<<dim3(HID * HID / 4 / 256, 1, 2), 256>>>(Wk, Wv);
    t2_part_kernel<<<dim3(HID / 256, 32), 256>>>(Wk, bq);
    t2_reduce_kernel<<<HID / 256, 256>>>();
    w_kernel<<<MTOT / 4, 128>>>(x);

    // 1) merged: M = Wq^T Wk (split3) + v = x Wv^T + bv (1x)
    mv_kernel<<<dim3(HID / 128, 8 + MTOT / 128), 256, GEMM_SMEM>>>(bv);
    // 2) y = x M (split3) -> yh/yl + yq
    y_kernel<<<dim3(HID / 128, MTOT / 128), 256, GEMM_SMEM>>>();
    // 3) approx scores = yq xq^T (int8) -> fp16
    scores_kernel<<<dim3(SEQ / 128, SEQ / 128, BATCH), 256, GEMM_SMEM>>>();
    // 4) fused gate + exact rescore + softmax + sparse P.v gather -> out
    softmax_rescore_pv_kernel<<<BATCH * SEQ, 256>>>(out);
}